// round 4
// baseline (speedup 1.0000x reference)
#include <cuda_runtime.h>

#define Bb 4
#define Nn 1280
#define NM 256
#define NSd 1024
#define Cc 768
#define Hh 12
#define Dd 64
#define MEMN 1280
#define LFULL 2560
#define KSEL_S 640
#define KSEL_M 128
#define NT 256
#define KTP 257

__device__ float g_q[Bb*Hh*Nn*Dd];
__device__ float g_k[Bb*Hh*Nn*Dd];
__device__ float g_v[Bb*Hh*Nn*Dd];
__device__ float g_qkvlow[Bb*Nn*24];
__device__ float g_idvlow[Bb*NM*8];
__device__ float g_act[Bb*NM*Hh];
__device__ float g_idv[Bb*NM*Cc];
__device__ float g_xo[Bb*Nn*Cc];
__device__ float g_wplow[Bb*Nn*32];

__device__ __forceinline__ unsigned fkey(float f){
    unsigned b = __float_as_uint(f);
    return (b & 0x80000000u) ? ~b : (b | 0x80000000u);
}

// Warp-synchronous exact top-K select + softmax weights. ATOMIC-FREE histogram
// via __match_any_sync: lanes with equal bin merge; leader lane adds popc to the
// warp-private bin. Identical semantics to previous version.
template<int L, int KS>
__device__ __forceinline__ float warp_topk(float* sp, unsigned* hb,
                                           unsigned short* idxl, float vmax, int lane){
    const unsigned FULL = 0xffffffffu;
    unsigned prefix = 0; int need = KS;
    #pragma unroll
    for (int p = 3; p >= 0; p--){
        const int shift = p * 8;
        const unsigned maskhi = (p == 3) ? 0u : (0xffffffffu << (shift + 8));
        #pragma unroll
        for (int i = 0; i < 8; i++) hb[lane + i*32] = 0;
        __syncwarp();
        for (int g = 0; g < L/32; g++){
            unsigned key = fkey(sp[g*32 + lane]);
            bool act = ((key & maskhi) == prefix);
            unsigned bin = (key >> shift) & 255u;
            unsigned tag = act ? bin : (256u + (unsigned)lane);
            unsigned mm = __match_any_sync(FULL, tag);
            if (act && ((mm & ((1u << lane) - 1u)) == 0u))
                hb[bin] += (unsigned)__popc(mm);
        }
        __syncwarp();
        unsigned c[8]; unsigned tot = 0;
        #pragma unroll
        for (int i = 0; i < 8; i++){ c[i] = hb[lane*8 + i]; tot += c[i]; }
        unsigned run = tot;
        #pragma unroll
        for (int off = 1; off < 32; off <<= 1){
            unsigned v = __shfl_down_sync(FULL, run, off);
            if (lane + off < 32) run += v;
        }
        unsigned above = run - tot;
        unsigned gtv = above, pack = 0;
        #pragma unroll
        for (int i = 7; i >= 0; i--){
            unsigned ge = gtv + c[i];
            if ((int)ge >= need && (int)gtv < need)
                pack = 0x80000000u | ((unsigned)(lane*8 + i) << 12) | gtv;
            gtv = ge;
        }
        #pragma unroll
        for (int off = 16; off; off >>= 1)
            pack = max(pack, __shfl_xor_sync(FULL, pack, off));
        need -= (int)(pack & 0xFFFu);
        prefix |= ((pack >> 12) & 255u) << shift;
        __syncwarp();
    }
    const unsigned thr = prefix;
    int tieacc = 0, nsel = 0; float lsum = 0.f;
    for (int g = 0; g < L/32; g++){
        int j = g*32 + lane;
        float v = sp[j];
        unsigned key = fkey(v);
        bool eq = (key == thr);
        unsigned eqm = __ballot_sync(FULL, eq);
        bool sel = (key > thr) || (eq && (tieacc + __popc(eqm & ((1u<<lane) - 1u))) < need);
        tieacc += __popc(eqm);
        float e = sel ? __expf(v - vmax) : 0.f;
        sp[j] = e; lsum += e;
        unsigned sm = __ballot_sync(FULL, sel);
        if (sel) idxl[nsel + __popc(sm & ((1u<<lane) - 1u))] = (unsigned short)j;
        nsel += __popc(sm);
    }
    #pragma unroll
    for (int off = 16; off; off >>= 1) lsum += __shfl_xor_sync(FULL, lsum, off);
    return lsum;
}

__global__ void k_qkv_low(const float* __restrict__ x, const float* __restrict__ qkvA){
    const int row = blockIdx.x;
    const int tid = threadIdx.x;
    __shared__ float xs[Cc];
    for (int i = tid; i < Cc; i += NT) xs[i] = x[row*Cc + i];
    __syncthreads();
    const int warp = tid >> 5, lane = tid & 31;
    for (int o = warp; o < 24; o += 8){
        const float* a = &qkvA[o*Cc];
        float p = 0.f;
        for (int i = lane; i < Cc; i += 32) p += xs[i] * a[i];
        #pragma unroll
        for (int off = 16; off; off >>= 1) p += __shfl_xor_sync(0xffffffffu, p, off);
        if (lane == 0) g_qkvlow[row*24 + o] = p;
    }
}

#define SGEMM_MAIN(Aptr, Wptr, KDIM)                                              \
    __shared__ __align__(16) float As[16*64];                                      \
    __shared__ __align__(16) float Ws[16*64];                                      \
    float acc[4][4];                                                               \
    _Pragma("unroll") for (int i_ = 0; i_ < 4; i_++)                               \
    _Pragma("unroll") for (int j_ = 0; j_ < 4; j_++) acc[i_][j_] = 0.f;            \
    const int tid = threadIdx.x;                                                   \
    const int ty = tid >> 4, tx = tid & 15;                                        \
    const int lr = tid >> 2, lk = (tid & 3) * 4;                                   \
    const int row0 = blockIdx.y * 64, col0 = blockIdx.x * 64;                      \
    for (int kt = 0; kt < KDIM; kt += 16){                                         \
        float4 a4 = *(const float4*)&Aptr[(row0 + lr)*KDIM + kt + lk];             \
        float4 w4 = *(const float4*)&Wptr[(col0 + lr)*KDIM + kt + lk];             \
        __syncthreads();                                                           \
        As[(lk+0)*64 + lr] = a4.x; As[(lk+1)*64 + lr] = a4.y;                      \
        As[(lk+2)*64 + lr] = a4.z; As[(lk+3)*64 + lr] = a4.w;                      \
        Ws[(lk+0)*64 + lr] = w4.x; Ws[(lk+1)*64 + lr] = w4.y;                      \
        Ws[(lk+2)*64 + lr] = w4.z; Ws[(lk+3)*64 + lr] = w4.w;                      \
        __syncthreads();                                                           \
        _Pragma("unroll")                                                          \
        for (int kk = 0; kk < 16; kk++){                                           \
            float4 ra = *(const float4*)&As[kk*64 + ty*4];                         \
            float4 rb = *(const float4*)&Ws[kk*64 + tx*4];                         \
            acc[0][0] += ra.x*rb.x; acc[0][1] += ra.x*rb.y;                        \
            acc[0][2] += ra.x*rb.z; acc[0][3] += ra.x*rb.w;                        \
            acc[1][0] += ra.y*rb.x; acc[1][1] += ra.y*rb.y;                        \
            acc[1][2] += ra.y*rb.z; acc[1][3] += ra.y*rb.w;                        \
            acc[2][0] += ra.z*rb.x; acc[2][1] += ra.z*rb.y;                        \
            acc[2][2] += ra.z*rb.z; acc[2][3] += ra.z*rb.w;                        \
            acc[3][0] += ra.w*rb.x; acc[3][1] += ra.w*rb.y;                        \
            acc[3][2] += ra.w*rb.z; acc[3][3] += ra.w*rb.w;                        \
        }                                                                          \
    }

__global__ void k_sgemm_qkv(const float* __restrict__ x, const float* __restrict__ W,
                            const float* __restrict__ bq, const float* __restrict__ qkvB){
    SGEMM_MAIN(x, W, Cc)
    const int g = col0 / Cc;
    #pragma unroll
    for (int ii = 0; ii < 4; ii++){
        const int m = row0 + ty*4 + ii;
        const int b = m / Nn, n = m % Nn;
        float lw[8];
        #pragma unroll
        for (int r = 0; r < 8; r++) lw[r] = g_qkvlow[m*24 + g*8 + r];
        #pragma unroll
        for (int jj = 0; jj < 4; jj++){
            const int j = col0 + tx*4 + jj;
            const int c = j - g*Cc;
            const float* bv = &qkvB[(g*Cc + c)*8];
            float lora = 0.f;
            #pragma unroll
            for (int r = 0; r < 8; r++) lora += lw[r] * bv[r];
            float val = acc[ii][jj] + bq[j] + 0.125f * lora;
            const int h = c >> 6, d = c & 63;
            const int dst = ((b*Hh + h)*Nn + n)*Dd + d;
            if (g == 0)      g_q[dst] = val * 0.125f;
            else if (g == 1) g_k[dst] = val;
            else             g_v[dst] = val;
        }
    }
}

__global__ void k_id_small(const float* __restrict__ idt, const float* __restrict__ idkA,
                           const float* __restrict__ idvA, const float* __restrict__ Widk,
                           const float* __restrict__ bidk, const float* __restrict__ idkB){
    const int row = blockIdx.x;
    const int tid = threadIdx.x;
    __shared__ float xs[Cc];
    __shared__ float lk[8], dk[12];
    for (int i = tid; i < Cc; i += NT) xs[i] = idt[row*Cc + i];
    __syncthreads();
    const int warp = tid >> 5, lane = tid & 31;
    for (int o = warp; o < 28; o += 8){
        const float* a;
        if (o < 8)       a = &idkA[o*Cc];
        else if (o < 16) a = &idvA[(o - 8)*Cc];
        else             a = &Widk[(o - 16)*Cc];
        float p = 0.f;
        for (int i = lane; i < Cc; i += 32) p += xs[i] * a[i];
        #pragma unroll
        for (int off = 16; off; off >>= 1) p += __shfl_xor_sync(0xffffffffu, p, off);
        if (lane == 0){
            if (o < 8)       lk[o] = p;
            else if (o < 16) g_idvlow[row*8 + (o - 8)] = p;
            else             dk[o - 16] = p;
        }
    }
    __syncthreads();
    if (tid < 12){
        float lo = 0.f;
        #pragma unroll
        for (int r = 0; r < 8; r++) lo += lk[r] * idkB[tid*8 + r];
        float f = dk[tid] + bidk[tid] + 0.125f * lo;
        g_act[row*Hh + tid] = 1.f + tanhf(f);
    }
}

__global__ void k_sgemm_idv(const float* __restrict__ idt, const float* __restrict__ W,
                            const float* __restrict__ bidv, const float* __restrict__ idvB){
    SGEMM_MAIN(idt, W, Cc)
    #pragma unroll
    for (int ii = 0; ii < 4; ii++){
        const int m = row0 + ty*4 + ii;
        float lw[8];
        #pragma unroll
        for (int r = 0; r < 8; r++) lw[r] = g_idvlow[m*8 + r];
        #pragma unroll
        for (int jj = 0; jj < 4; jj++){
            const int c = col0 + tx*4 + jj;
            const float* bv = &idvB[c*8];
            float lora = 0.f;
            #pragma unroll
            for (int r = 0; r < 8; r++) lora += lw[r] * bv[r];
            g_idv[m*Cc + c] = acc[ii][jj] + bidv[c] + 0.125f * lora;
        }
    }
}

__global__ void k_apply_id(float* __restrict__ kmid, float* __restrict__ vmid){
    const int idx = blockIdx.x * NT + threadIdx.x;
    const int d = idx & 63;
    int t = idx >> 6;
    const int m = t % NM; t /= NM;
    const int h = t % Hh; const int b = t / Hh;
    const int src = ((b*Hh + h)*Nn + m)*Dd + d;
    kmid[idx] = g_k[src] * g_act[(b*NM + m)*Hh + h];
    vmid[idx] = g_v[src] + g_idv[(b*NM + m)*Cc + h*Dd + d];
}

#define SM_M_S    0
#define SM_M_KT   8192
#define SM_M_QS   74048
#define SM_M_HIST 76096
#define SM_M_IDX  84288
#define SMEM_M_TOT 86336

__global__ void k_attn_m(const float* __restrict__ kmid, const float* __restrict__ vmid){
    extern __shared__ __align__(16) char smb[];
    float* s  = (float*)(smb + SM_M_S);
    float* kt = (float*)(smb + SM_M_KT);
    float* qs = (float*)(smb + SM_M_QS);
    unsigned* hist = (unsigned*)(smb + SM_M_HIST);
    unsigned short* idxl = (unsigned short*)(smb + SM_M_IDX);
    const int tid = threadIdx.x, lane = tid & 31, w = tid >> 5;
    const int qt = blockIdx.x & 31;
    const int bh = blockIdx.x >> 5;
    const int b = bh / Hh, h = bh % Hh;
    const int m0 = qt * 8;
    for (int i = tid; i < 512; i += NT){
        int r = i >> 6, d = i & 63;
        qs[i] = g_q[((size_t)bh*Nn + m0 + r)*Dd + d];
    }
    for (int idx = tid; idx < 256*16; idx += NT){
        int r = idx >> 4, c4 = idx & 15;
        float4 kv = *(const float4*)&kmid[((size_t)bh*NM + r)*Dd + c4*4];
        kt[(c4*4+0)*KTP + r] = kv.x;
        kt[(c4*4+1)*KTP + r] = kv.y;
        kt[(c4*4+2)*KTP + r] = kv.z;
        kt[(c4*4+3)*KTP + r] = kv.w;
    }
    __syncthreads();
    {
        float acc8[8];
        #pragma unroll
        for (int r = 0; r < 8; r++) acc8[r] = 0.f;
        const float4* qs4 = (const float4*)qs;
        #pragma unroll 4
        for (int i4 = 0; i4 < 16; i4++){
            float k0 = kt[(i4*4+0)*KTP + tid];
            float k1 = kt[(i4*4+1)*KTP + tid];
            float k2 = kt[(i4*4+2)*KTP + tid];
            float k3 = kt[(i4*4+3)*KTP + tid];
            #pragma unroll
            for (int r = 0; r < 8; r++){
                float4 q4 = qs4[r*16 + i4];
                acc8[r] += k0*q4.x + k1*q4.y + k2*q4.z + k3*q4.w;
            }
        }
        #pragma unroll
        for (int r = 0; r < 8; r++) s[r*NM + tid] = acc8[r];
    }
    __syncthreads();
    float* sp = s + w*NM;
    float lmax = -1e30f;
    for (int g = 0; g < NM/32; g++) lmax = fmaxf(lmax, sp[g*32 + lane]);
    #pragma unroll
    for (int off = 16; off; off >>= 1) lmax = fmaxf(lmax, __shfl_xor_sync(0xffffffffu, lmax, off));
    float Z = warp_topk<NM, KSEL_M>(sp, hist + w*256, idxl + w*KSEL_M, lmax, lane);
    float invZ = 1.f / Z;
    __syncthreads();
    float* vsh = kt;
    for (int idx = tid; idx < 256*16; idx += NT){
        int r = idx >> 4, c4 = idx & 15;
        *(float4*)&vsh[r*Dd + c4*4] = *(const float4*)&vmid[((size_t)bh*NM + r)*Dd + c4*4];
    }
    __syncthreads();
    float2 acc = {0.f, 0.f};
    const unsigned short* il = idxl + w*KSEL_M;
    for (int n = 0; n < KSEL_M; n++){
        int j = il[n];
        float wgt = sp[j];
        float2 v2 = ((const float2*)&vsh[j*Dd])[lane];
        acc.x += wgt*v2.x; acc.y += wgt*v2.y;
    }
    float2 o = {acc.x*invZ, acc.y*invZ};
    ((float2*)&g_xo[((size_t)b*Nn + m0 + w)*Cc + h*Dd])[lane] = o;
}

#define SM_S_S    0
#define SM_S_KT   81920
#define SM_S_QS   147712
#define SM_S_HIST 149760
#define SM_S_IDX  157952
#define SMEM_S_TOT 168192

__global__ void k_attn_s(const float* __restrict__ memk, const float* __restrict__ memv,
                         const float* __restrict__ vmid){
    extern __shared__ __align__(16) char smb[];
    float* s  = (float*)(smb + SM_S_S);
    float* kt = (float*)(smb + SM_S_KT);
    float* qs = (float*)(smb + SM_S_QS);
    unsigned* hist = (unsigned*)(smb + SM_S_HIST);
    unsigned short* idxl = (unsigned short*)(smb + SM_S_IDX);
    const int tid = threadIdx.x, lane = tid & 31, w = tid >> 5;
    const int qt = blockIdx.x & 127;
    const int bh = blockIdx.x >> 7;
    const int b = bh / Hh, h = bh % Hh;
    const int nq0 = NM + qt*8;
    for (int i = tid; i < 512; i += NT){
        int r = i >> 6, d = i & 63;
        qs[i] = g_q[((size_t)bh*Nn + nq0 + r)*Dd + d];
    }
    const float4* qs4 = (const float4*)qs;
    for (int ck = 0; ck < 10; ck++){
        __syncthreads();
        for (int idx = tid; idx < 256*16; idx += NT){
            int r = idx >> 4, c4 = idx & 15;
            int j = ck*256 + r;
            const float* kr = (j < MEMN) ? &memk[((size_t)bh*MEMN + j)*Dd]
                                         : &g_k[((size_t)bh*Nn + (j - MEMN))*Dd];
            float4 kv = *(const float4*)(kr + c4*4);
            kt[(c4*4+0)*KTP + r] = kv.x;
            kt[(c4*4+1)*KTP + r] = kv.y;
            kt[(c4*4+2)*KTP + r] = kv.z;
            kt[(c4*4+3)*KTP + r] = kv.w;
        }
        __syncthreads();
        float acc8[8];
        #pragma unroll
        for (int r = 0; r < 8; r++) acc8[r] = 0.f;
        #pragma unroll 4
        for (int i4 = 0; i4 < 16; i4++){
            float k0 = kt[(i4*4+0)*KTP + tid];
            float k1 = kt[(i4*4+1)*KTP + tid];
            float k2 = kt[(i4*4+2)*KTP + tid];
            float k3 = kt[(i4*4+3)*KTP + tid];
            #pragma unroll
            for (int r = 0; r < 8; r++){
                float4 q4 = qs4[r*16 + i4];
                acc8[r] += k0*q4.x + k1*q4.y + k2*q4.z + k3*q4.w;
            }
        }
        #pragma unroll
        for (int r = 0; r < 8; r++) s[r*LFULL + ck*256 + tid] = acc8[r];
    }
    __syncthreads();
    float* sp = s + w*LFULL;
    float lmax = -1e30f;
    for (int g = 0; g < LFULL/32; g++) lmax = fmaxf(lmax, sp[g*32 + lane]);
    #pragma unroll
    for (int off = 16; off; off >>= 1) lmax = fmaxf(lmax, __shfl_xor_sync(0xffffffffu, lmax, off));
    float Z = warp_topk<LFULL, KSEL_S>(sp, hist + w*256, idxl + w*KSEL_S, lmax, lane);
    float invZ = 1.f / Z;
    float* vsh = kt;
    const unsigned short* il = idxl + w*KSEL_S;
    int n = 0;
    float2 acc = {0.f, 0.f};
    for (int ck = 0; ck < 10; ck++){
        __syncthreads();
        for (int idx = tid; idx < 256*16; idx += NT){
            int r = idx >> 4, c4 = idx & 15;
            int j = ck*256 + r;
            const float* vr;
            if (j < MEMN)            vr = &memv[((size_t)bh*MEMN + j)*Dd];
            else if (j < MEMN + NM)  vr = &vmid[((size_t)bh*NM + (j - MEMN))*Dd];
            else                     vr = &g_v[((size_t)bh*Nn + (j - MEMN))*Dd];
            *(float4*)&vsh[r*Dd + c4*4] = *(const float4*)(vr + c4*4);
        }
        __syncthreads();
        const int jend = (ck + 1)*256, jbase = ck*256;
        while (n < KSEL_S){
            int j = il[n];
            if (j >= jend) break;
            float wgt = sp[j];
            float2 v2 = ((const float2*)&vsh[(j - jbase)*Dd])[lane];
            acc.x += wgt*v2.x; acc.y += wgt*v2.y;
            n++;
        }
    }
    float2 o = {acc.x*invZ, acc.y*invZ};
    ((float2*)&g_xo[((size_t)b*Nn + nq0 + w)*Cc + h*Dd])[lane] = o;
}

__global__ void k_route(const float* __restrict__ routeW, const float* __restrict__ projA){
    const int row = blockIdx.x;
    const int tid = threadIdx.x;
    __shared__ float xs[Cc];
    __shared__ float lg[4], pl[32], sm[4];
    for (int i = tid; i < Cc; i += NT) xs[i] = g_xo[row*Cc + i];
    __syncthreads();
    const int warp = tid >> 5, lane = tid & 31;
    for (int o = warp; o < 36; o += 8){
        const float* a = (o < 4) ? &routeW[o*Cc] : &projA[(o - 4)*Cc];
        float p = 0.f;
        for (int i = lane; i < Cc; i += 32) p += xs[i] * a[i];
        #pragma unroll
        for (int off = 16; off; off >>= 1) p += __shfl_xor_sync(0xffffffffu, p, off);
        if (lane == 0){
            if (o < 4) lg[o] = p;
            else       pl[o - 4] = p;
        }
    }
    __syncthreads();
    if (tid == 0){
        float mx = fmaxf(fmaxf(lg[0], lg[1]), fmaxf(lg[2], lg[3]));
        float e0 = __expf(lg[0]-mx), e1 = __expf(lg[1]-mx);
        float e2 = __expf(lg[2]-mx), e3 = __expf(lg[3]-mx);
        float si = 1.f / (e0 + e1 + e2 + e3);
        sm[0] = e0*si; sm[1] = e1*si; sm[2] = e2*si; sm[3] = e3*si;
    }
    __syncthreads();
    if (tid < 32) g_wplow[row*32 + tid] = sm[tid >> 3] * pl[tid] * 0.125f;
}

__global__ void k_sgemm_proj(const float* __restrict__ W, const float* __restrict__ bp,
                             const float* __restrict__ projB, float* __restrict__ out){
    SGEMM_MAIN(g_xo, W, Cc)
    #pragma unroll
    for (int ii = 0; ii < 4; ii++){
        const int m = row0 + ty*4 + ii;
        float wl[32];
        #pragma unroll
        for (int t = 0; t < 32; t++) wl[t] = g_wplow[m*32 + t];
        #pragma unroll
        for (int jj = 0; jj < 4; jj++){
            const int c = col0 + tx*4 + jj;
            float lora = 0.f;
            #pragma unroll
            for (int e = 0; e < 4; e++){
                const float* bv = &projB[(e*Cc + c)*8];
                #pragma unroll
                for (int r = 0; r < 8; r++) lora += wl[e*8 + r] * bv[r];
            }
            out[m*Cc + c] = acc[ii][jj] + bp[c] + lora;
        }
    }
}

extern "C" void kernel_launch(void* const* d_in, const int* in_sizes, int n_in,
                              void* d_out, int out_size){
    const float* x      = (const float*)d_in[0];
    const float* idt    = (const float*)d_in[1];
    const float* memk   = (const float*)d_in[2];
    const float* memv   = (const float*)d_in[3];
    const float* Wqkv   = (const float*)d_in[4];
    const float* bqkv   = (const float*)d_in[5];
    const float* qkvA   = (const float*)d_in[6];
    const float* qkvB   = (const float*)d_in[7];
    const float* Wproj  = (const float*)d_in[8];
    const float* bproj  = (const float*)d_in[9];
    const float* routeW = (const float*)d_in[10];
    const float* projA  = (const float*)d_in[11];
    const float* projB  = (const float*)d_in[12];
    const float* Widk   = (const float*)d_in[13];
    const float* bidk   = (const float*)d_in[14];
    const float* idkA   = (const float*)d_in[15];
    const float* idkB   = (const float*)d_in[16];
    const float* Widv   = (const float*)d_in[17];
    const float* bidv   = (const float*)d_in[18];
    const float* idvA   = (const float*)d_in[19];
    const float* idvB   = (const float*)d_in[20];

    float* out  = (float*)d_out;
    float* kmid = out + Bb*Nn*Cc;
    float* vmid = kmid + Bb*Hh*NM*Dd;

    static int init = 0;
    if (!init){
        cudaFuncSetAttribute(k_attn_m, cudaFuncAttributeMaxDynamicSharedMemorySize, SMEM_M_TOT);
        cudaFuncSetAttribute(k_attn_s, cudaFuncAttributeMaxDynamicSharedMemorySize, SMEM_S_TOT);
        init = 1;
    }

    k_qkv_low<<<Bb*Nn, NT>>>(x, qkvA);
    k_sgemm_qkv<<<dim3(36, 80), NT>>>(x, Wqkv, bqkv, qkvB);
    k_id_small<<<Bb*NM, NT>>>(idt, idkA, idvA, Widk, bidk, idkB);
    k_sgemm_idv<<<dim3(12, 16), NT>>>(idt, Widv, bidv, idvB);
    k_apply_id<<<(Bb*Hh*NM*Dd)/NT, NT>>>(kmid, vmid);
    k_attn_m<<<Bb*Hh*NM/8, NT, SMEM_M_TOT>>>(kmid, vmid);
    k_attn_s<<<Bb*Hh*NSd/8, NT, SMEM_S_TOT>>>(memk, memv, vmid);
    k_route<<<Bb*Nn, NT>>>(routeW, projA);
    k_sgemm_proj<<<dim3(12, 80), NT>>>(Wproj, bproj, projB, out);
}

// round 5
// speedup vs baseline: 1.4041x; 1.4041x over previous
#include <cuda_runtime.h>

#define Bb 4
#define Nn 1280
#define NM 256
#define NSd 1024
#define Cc 768
#define Hh 12
#define Dd 64
#define MEMN 1280
#define LFULL 2560
#define KSEL_S 640
#define KSEL_M 128
#define NT 256
#define KTP 257
#define KT2 129
#define CKS 128
#define NCH 20

__device__ float g_q[Bb*Hh*Nn*Dd];
__device__ float g_k[Bb*Hh*Nn*Dd];
__device__ float g_v[Bb*Hh*Nn*Dd];
__device__ float g_qkvlow[Bb*Nn*24];
__device__ float g_idvlow[Bb*NM*8];
__device__ float g_act[Bb*NM*Hh];
__device__ float g_idv[Bb*NM*Cc];
__device__ float g_xo[Bb*Nn*Cc];
__device__ float g_wplow[Bb*Nn*32];

__device__ __forceinline__ unsigned fkey(float f){
    unsigned b = __float_as_uint(f);
    return (b & 0x80000000u) ? ~b : (b | 0x80000000u);
}

// Warp-synchronous exact top-K + softmax weights. Histogram via ballots into
// REGISTERS (one bin per lane, <=32 bins/pass, 7 passes cover 32 bits).
// cs[g/GPC] records the selection-count boundary at each chunk of GPC groups.
template<int L, int KS, int GPC>
__device__ float warp_topk(float* sp, unsigned short* idxl, int* cs,
                           float vmax, int lane){
    const unsigned FULL = 0xffffffffu;
    const int G = L/32;
    const int SH[7] = {27,22,17,12,7,2,0};
    const int NB[7] = {5,5,5,5,5,5,2};
    unsigned prefix = 0; int need = KS;
    #pragma unroll
    for (int p = 0; p < 7; p++){
        const int shift = SH[p], nb = NB[p];
        const unsigned Bm = (1u << nb) - 1u;
        const unsigned maskhi = (p == 0) ? 0u : ~((1u << (shift + nb)) - 1u);
        unsigned cnt = 0;
        for (int g = 0; g < G; g++){
            unsigned key = fkey(sp[g*32 + lane]);
            bool act = ((key & maskhi) == prefix);
            unsigned wv = (key >> shift) & Bm;
            unsigned mact = __ballot_sync(FULL, act);
            unsigned m0 = __ballot_sync(FULL, wv & 1);
            unsigned m1 = __ballot_sync(FULL, wv & 2);
            unsigned sel = mact & ((lane & 1) ? m0 : ~m0)
                                & ((lane & 2) ? m1 : ~m1);
            if (nb == 5){
                unsigned m2 = __ballot_sync(FULL, wv & 4);
                unsigned m3 = __ballot_sync(FULL, wv & 8);
                unsigned m4 = __ballot_sync(FULL, wv & 16);
                sel &= (lane & 4) ? m2 : ~m2;
                sel &= (lane & 8) ? m3 : ~m3;
                sel &= (lane & 16) ? m4 : ~m4;
            }
            cnt += __popc(sel);
        }
        if ((unsigned)lane > Bm) cnt = 0;
        unsigned run = cnt;
        #pragma unroll
        for (int off = 1; off < 32; off <<= 1){
            unsigned v = __shfl_down_sync(FULL, run, off);
            if (lane + off < 32) run += v;
        }
        unsigned gt = run - cnt;
        bool isthr = ((int)run >= need) && ((int)gt < need);
        unsigned mthr = __ballot_sync(FULL, isthr);
        int tl = __ffs(mthr) - 1;
        unsigned gtt = __shfl_sync(FULL, gt, tl);
        need -= (int)gtt;
        prefix |= ((unsigned)tl) << shift;
    }
    const unsigned thr = prefix;
    int tieacc = 0, nsel = 0; float lsum = 0.f;
    for (int g = 0; g < G; g++){
        if ((g % GPC) == 0 && lane == 0) cs[g / GPC] = nsel;
        int j = g*32 + lane;
        float v = sp[j];
        unsigned key = fkey(v);
        bool eq = (key == thr);
        unsigned eqm = __ballot_sync(FULL, eq);
        bool selb = (key > thr) || (eq && (tieacc + __popc(eqm & ((1u<<lane)-1u))) < need);
        tieacc += __popc(eqm);
        float e = selb ? __expf(v - vmax) : 0.f;
        sp[j] = e; lsum += e;
        unsigned sm = __ballot_sync(FULL, selb);
        if (selb) idxl[nsel + __popc(sm & ((1u<<lane)-1u))] = (unsigned short)j;
        nsel += __popc(sm);
    }
    if (lane == 0) cs[G / GPC] = KS;
    #pragma unroll
    for (int off = 16; off; off >>= 1) lsum += __shfl_xor_sync(FULL, lsum, off);
    return lsum;
}

__global__ void k_qkv_low(const float* __restrict__ x, const float* __restrict__ qkvA){
    const int row = blockIdx.x;
    const int tid = threadIdx.x;
    __shared__ float xs[Cc];
    for (int i = tid; i < Cc; i += NT) xs[i] = x[row*Cc + i];
    __syncthreads();
    const int warp = tid >> 5, lane = tid & 31;
    for (int o = warp; o < 24; o += 8){
        const float* a = &qkvA[o*Cc];
        float p = 0.f;
        for (int i = lane; i < Cc; i += 32) p += xs[i] * a[i];
        #pragma unroll
        for (int off = 16; off; off >>= 1) p += __shfl_xor_sync(0xffffffffu, p, off);
        if (lane == 0) g_qkvlow[row*24 + o] = p;
    }
}

#define SGEMM_MAIN(Aptr, Wptr, KDIM)                                              \
    __shared__ __align__(16) float As[16*64];                                      \
    __shared__ __align__(16) float Ws[16*64];                                      \
    float acc[4][4];                                                               \
    _Pragma("unroll") for (int i_ = 0; i_ < 4; i_++)                               \
    _Pragma("unroll") for (int j_ = 0; j_ < 4; j_++) acc[i_][j_] = 0.f;            \
    const int tid = threadIdx.x;                                                   \
    const int ty = tid >> 4, tx = tid & 15;                                        \
    const int lr = tid >> 2, lk = (tid & 3) * 4;                                   \
    const int row0 = blockIdx.y * 64, col0 = blockIdx.x * 64;                      \
    for (int kt = 0; kt < KDIM; kt += 16){                                         \
        float4 a4 = *(const float4*)&Aptr[(row0 + lr)*KDIM + kt + lk];             \
        float4 w4 = *(const float4*)&Wptr[(col0 + lr)*KDIM + kt + lk];             \
        __syncthreads();                                                           \
        As[(lk+0)*64 + lr] = a4.x; As[(lk+1)*64 + lr] = a4.y;                      \
        As[(lk+2)*64 + lr] = a4.z; As[(lk+3)*64 + lr] = a4.w;                      \
        Ws[(lk+0)*64 + lr] = w4.x; Ws[(lk+1)*64 + lr] = w4.y;                      \
        Ws[(lk+2)*64 + lr] = w4.z; Ws[(lk+3)*64 + lr] = w4.w;                      \
        __syncthreads();                                                           \
        _Pragma("unroll")                                                          \
        for (int kk = 0; kk < 16; kk++){                                           \
            float4 ra = *(const float4*)&As[kk*64 + ty*4];                         \
            float4 rb = *(const float4*)&Ws[kk*64 + tx*4];                         \
            acc[0][0] += ra.x*rb.x; acc[0][1] += ra.x*rb.y;                        \
            acc[0][2] += ra.x*rb.z; acc[0][3] += ra.x*rb.w;                        \
            acc[1][0] += ra.y*rb.x; acc[1][1] += ra.y*rb.y;                        \
            acc[1][2] += ra.y*rb.z; acc[1][3] += ra.y*rb.w;                        \
            acc[2][0] += ra.z*rb.x; acc[2][1] += ra.z*rb.y;                        \
            acc[2][2] += ra.z*rb.z; acc[2][3] += ra.z*rb.w;                        \
            acc[3][0] += ra.w*rb.x; acc[3][1] += ra.w*rb.y;                        \
            acc[3][2] += ra.w*rb.z; acc[3][3] += ra.w*rb.w;                        \
        }                                                                          \
    }

__global__ void k_sgemm_qkv(const float* __restrict__ x, const float* __restrict__ W,
                            const float* __restrict__ bq, const float* __restrict__ qkvB){
    SGEMM_MAIN(x, W, Cc)
    const int g = col0 / Cc;
    #pragma unroll
    for (int ii = 0; ii < 4; ii++){
        const int m = row0 + ty*4 + ii;
        const int b = m / Nn, n = m % Nn;
        float lw[8];
        #pragma unroll
        for (int r = 0; r < 8; r++) lw[r] = g_qkvlow[m*24 + g*8 + r];
        #pragma unroll
        for (int jj = 0; jj < 4; jj++){
            const int j = col0 + tx*4 + jj;
            const int c = j - g*Cc;
            const float* bv = &qkvB[(g*Cc + c)*8];
            float lora = 0.f;
            #pragma unroll
            for (int r = 0; r < 8; r++) lora += lw[r] * bv[r];
            float val = acc[ii][jj] + bq[j] + 0.125f * lora;
            const int h = c >> 6, d = c & 63;
            const int dst = ((b*Hh + h)*Nn + n)*Dd + d;
            if (g == 0)      g_q[dst] = val * 0.125f;
            else if (g == 1) g_k[dst] = val;
            else             g_v[dst] = val;
        }
    }
}

__global__ void k_id_small(const float* __restrict__ idt, const float* __restrict__ idkA,
                           const float* __restrict__ idvA, const float* __restrict__ Widk,
                           const float* __restrict__ bidk, const float* __restrict__ idkB){
    const int row = blockIdx.x;
    const int tid = threadIdx.x;
    __shared__ float xs[Cc];
    __shared__ float lk[8], dk[12];
    for (int i = tid; i < Cc; i += NT) xs[i] = idt[row*Cc + i];
    __syncthreads();
    const int warp = tid >> 5, lane = tid & 31;
    for (int o = warp; o < 28; o += 8){
        const float* a;
        if (o < 8)       a = &idkA[o*Cc];
        else if (o < 16) a = &idvA[(o - 8)*Cc];
        else             a = &Widk[(o - 16)*Cc];
        float p = 0.f;
        for (int i = lane; i < Cc; i += 32) p += xs[i] * a[i];
        #pragma unroll
        for (int off = 16; off; off >>= 1) p += __shfl_xor_sync(0xffffffffu, p, off);
        if (lane == 0){
            if (o < 8)       lk[o] = p;
            else if (o < 16) g_idvlow[row*8 + (o - 8)] = p;
            else             dk[o - 16] = p;
        }
    }
    __syncthreads();
    if (tid < 12){
        float lo = 0.f;
        #pragma unroll
        for (int r = 0; r < 8; r++) lo += lk[r] * idkB[tid*8 + r];
        float f = dk[tid] + bidk[tid] + 0.125f * lo;
        g_act[row*Hh + tid] = 1.f + tanhf(f);
    }
}

__global__ void k_sgemm_idv(const float* __restrict__ idt, const float* __restrict__ W,
                            const float* __restrict__ bidv, const float* __restrict__ idvB){
    SGEMM_MAIN(idt, W, Cc)
    #pragma unroll
    for (int ii = 0; ii < 4; ii++){
        const int m = row0 + ty*4 + ii;
        float lw[8];
        #pragma unroll
        for (int r = 0; r < 8; r++) lw[r] = g_idvlow[m*8 + r];
        #pragma unroll
        for (int jj = 0; jj < 4; jj++){
            const int c = col0 + tx*4 + jj;
            const float* bv = &idvB[c*8];
            float lora = 0.f;
            #pragma unroll
            for (int r = 0; r < 8; r++) lora += lw[r] * bv[r];
            g_idv[m*Cc + c] = acc[ii][jj] + bidv[c] + 0.125f * lora;
        }
    }
}

__global__ void k_apply_id(float* __restrict__ kmid, float* __restrict__ vmid){
    const int idx = blockIdx.x * NT + threadIdx.x;
    const int d = idx & 63;
    int t = idx >> 6;
    const int m = t % NM; t /= NM;
    const int h = t % Hh; const int b = t / Hh;
    const int src = ((b*Hh + h)*Nn + m)*Dd + d;
    kmid[idx] = g_k[src] * g_act[(b*NM + m)*Hh + h];
    vmid[idx] = g_v[src] + g_idv[(b*NM + m)*Cc + h*Dd + d];
}

// ---- mem attention: 8 rows/block ----
#define SM_M_S    0
#define SM_M_KT   8192
#define SM_M_QS   73984
#define SM_M_IDX  76032
#define SM_M_CS   78080
#define SMEM_M_TOT 78208

__global__ void k_attn_m(const float* __restrict__ kmid, const float* __restrict__ vmid){
    extern __shared__ __align__(16) char smb[];
    float* s  = (float*)(smb + SM_M_S);
    float* kt = (float*)(smb + SM_M_KT);
    float* qs = (float*)(smb + SM_M_QS);
    unsigned short* idxl = (unsigned short*)(smb + SM_M_IDX);
    int* csb = (int*)(smb + SM_M_CS);
    const int tid = threadIdx.x, lane = tid & 31, w = tid >> 5;
    const int qt = blockIdx.x & 31;
    const int bh = blockIdx.x >> 5;
    const int b = bh / Hh, h = bh % Hh;
    const int m0 = qt * 8;
    for (int i = tid; i < 512; i += NT){
        int r = i >> 6, d = i & 63;
        qs[i] = g_q[((size_t)bh*Nn + m0 + r)*Dd + d];
    }
    for (int idx = tid; idx < 256*16; idx += NT){
        int r = idx >> 4, c4 = idx & 15;
        float4 kv = *(const float4*)&kmid[((size_t)bh*NM + r)*Dd + c4*4];
        kt[(c4*4+0)*KTP + r] = kv.x;
        kt[(c4*4+1)*KTP + r] = kv.y;
        kt[(c4*4+2)*KTP + r] = kv.z;
        kt[(c4*4+3)*KTP + r] = kv.w;
    }
    __syncthreads();
    {
        float acc8[8];
        #pragma unroll
        for (int r = 0; r < 8; r++) acc8[r] = 0.f;
        const float4* qs4 = (const float4*)qs;
        #pragma unroll 4
        for (int i4 = 0; i4 < 16; i4++){
            float k0 = kt[(i4*4+0)*KTP + tid];
            float k1 = kt[(i4*4+1)*KTP + tid];
            float k2 = kt[(i4*4+2)*KTP + tid];
            float k3 = kt[(i4*4+3)*KTP + tid];
            #pragma unroll
            for (int r = 0; r < 8; r++){
                float4 q4 = qs4[r*16 + i4];
                acc8[r] += k0*q4.x + k1*q4.y + k2*q4.z + k3*q4.w;
            }
        }
        #pragma unroll
        for (int r = 0; r < 8; r++) s[r*NM + tid] = acc8[r];
    }
    __syncthreads();
    float* sp = s + w*NM;
    float lmax = -1e30f;
    #pragma unroll
    for (int g = 0; g < NM/32; g++) lmax = fmaxf(lmax, sp[g*32 + lane]);
    #pragma unroll
    for (int off = 16; off; off >>= 1) lmax = fmaxf(lmax, __shfl_xor_sync(0xffffffffu, lmax, off));
    float Z = warp_topk<NM, KSEL_M, 8>(sp, idxl + w*KSEL_M, csb + w*4, lmax, lane);
    float invZ = 1.f / Z;
    __syncthreads();
    float* vsh = kt;
    for (int idx = tid; idx < 256*16; idx += NT){
        int r = idx >> 4, c4 = idx & 15;
        *(float4*)&vsh[r*Dd + c4*4] = *(const float4*)&vmid[((size_t)bh*NM + r)*Dd + c4*4];
    }
    __syncthreads();
    float2 acc = {0.f, 0.f};
    const unsigned short* il = idxl + w*KSEL_M;
    #pragma unroll 4
    for (int n = 0; n < KSEL_M; n++){
        int j = il[n];
        float wgt = sp[j];
        float2 v2 = ((const float2*)&vsh[j*Dd])[lane];
        acc.x += wgt*v2.x; acc.y += wgt*v2.y;
    }
    float2 o = {acc.x*invZ, acc.y*invZ};
    ((float2*)&g_xo[((size_t)b*Nn + m0 + w)*Cc + h*Dd])[lane] = o;
}

// ---- streaming attention: 8 rows/block, 128-key chunks, reg-prefetch ----
#define SM_S_S    0
#define SM_S_KT   81920
#define SM_S_QS   114944
#define SM_S_CS   116992
#define SM_S_IDX  117760
#define SMEM_S_TOT 128000

__global__ __launch_bounds__(NT, 1)
void k_attn_s(const float* __restrict__ memk, const float* __restrict__ memv,
              const float* __restrict__ vmid){
    extern __shared__ __align__(16) char smb[];
    float* s  = (float*)(smb + SM_S_S);
    float* kt = (float*)(smb + SM_S_KT);
    float* qs = (float*)(smb + SM_S_QS);
    int* csall = (int*)(smb + SM_S_CS);
    unsigned short* idxall = (unsigned short*)(smb + SM_S_IDX);
    const int tid = threadIdx.x, lane = tid & 31, w = tid >> 5;
    const int qt = blockIdx.x & 127;
    const int bh = blockIdx.x >> 7;
    const int b = bh / Hh, h = bh % Hh;
    const int nq0 = NM + qt*8;
    for (int i = tid; i < 512; i += NT){
        int r = i >> 6, d = i & 63;
        qs[i] = g_q[((size_t)bh*Nn + nq0 + r)*Dd + d];
    }
    const int pr = tid >> 1;            // key row 0..127
    const int pco = (tid & 1) * 8;      // float4 offset 0 or 8
    float4 pre[8];
    {
        const float* kr = &memk[((size_t)bh*MEMN + pr)*Dd];
        #pragma unroll
        for (int i = 0; i < 8; i++) pre[i] = ((const float4*)kr)[pco + i];
    }
    const int key = tid & 127, rbase = (tid >> 7) * 4;
    const float4* qs4 = (const float4*)qs;
    for (int ck = 0; ck < NCH; ck++){
        __syncthreads();
        #pragma unroll
        for (int i = 0; i < 8; i++){
            int c = (pco + i)*4;
            kt[(c+0)*KT2 + pr] = pre[i].x; kt[(c+1)*KT2 + pr] = pre[i].y;
            kt[(c+2)*KT2 + pr] = pre[i].z; kt[(c+3)*KT2 + pr] = pre[i].w;
        }
        __syncthreads();
        if (ck + 1 < NCH){
            int j = (ck+1)*CKS + pr;
            const float* kr = (j < MEMN) ? &memk[((size_t)bh*MEMN + j)*Dd]
                                         : &g_k[((size_t)bh*Nn + (j - MEMN))*Dd];
            #pragma unroll
            for (int i = 0; i < 8; i++) pre[i] = ((const float4*)kr)[pco + i];
        }
        float a0 = 0.f, a1 = 0.f, a2 = 0.f, a3 = 0.f;
        #pragma unroll 4
        for (int i4 = 0; i4 < 16; i4++){
            float k0 = kt[(i4*4+0)*KT2 + key];
            float k1 = kt[(i4*4+1)*KT2 + key];
            float k2 = kt[(i4*4+2)*KT2 + key];
            float k3 = kt[(i4*4+3)*KT2 + key];
            float4 qa = qs4[(rbase+0)*16 + i4];
            float4 qb = qs4[(rbase+1)*16 + i4];
            float4 qc = qs4[(rbase+2)*16 + i4];
            float4 qd = qs4[(rbase+3)*16 + i4];
            a0 += k0*qa.x + k1*qa.y + k2*qa.z + k3*qa.w;
            a1 += k0*qb.x + k1*qb.y + k2*qb.z + k3*qb.w;
            a2 += k0*qc.x + k1*qc.y + k2*qc.z + k3*qc.w;
            a3 += k0*qd.x + k1*qd.y + k2*qd.z + k3*qd.w;
        }
        s[(rbase+0)*LFULL + ck*CKS + key] = a0;
        s[(rbase+1)*LFULL + ck*CKS + key] = a1;
        s[(rbase+2)*LFULL + ck*CKS + key] = a2;
        s[(rbase+3)*LFULL + ck*CKS + key] = a3;
    }
    __syncthreads();
    float* sp = s + w*LFULL;
    int* cs = csall + w*24;
    unsigned short* il = idxall + w*KSEL_S;
    float lmax = -1e30f;
    for (int g = 0; g < LFULL/32; g++) lmax = fmaxf(lmax, sp[g*32 + lane]);
    #pragma unroll
    for (int off = 16; off; off >>= 1) lmax = fmaxf(lmax, __shfl_xor_sync(0xffffffffu, lmax, off));
    float Z = warp_topk<LFULL, KSEL_S, 4>(sp, il, cs, lmax, lane);
    float invZ = 1.f / Z;
    // V phase
    float* vsh = kt;
    {
        const float* vr = &memv[((size_t)bh*MEMN + pr)*Dd];
        #pragma unroll
        for (int i = 0; i < 8; i++) pre[i] = ((const float4*)vr)[pco + i];
    }
    float2 acc = {0.f, 0.f};
    for (int ck = 0; ck < NCH; ck++){
        __syncthreads();
        #pragma unroll
        for (int i = 0; i < 8; i++)
            *(float4*)&vsh[pr*Dd + (pco + i)*4] = pre[i];
        __syncthreads();
        if (ck + 1 < NCH){
            int j = (ck+1)*CKS + pr;
            const float* vr;
            if (j < MEMN)            vr = &memv[((size_t)bh*MEMN + j)*Dd];
            else if (j < MEMN + NM)  vr = &vmid[((size_t)bh*NM + (j - MEMN))*Dd];
            else                     vr = &g_v[((size_t)bh*Nn + (j - MEMN))*Dd];
            #pragma unroll
            for (int i = 0; i < 8; i++) pre[i] = ((const float4*)vr)[pco + i];
        }
        const int nb = cs[ck], ne = cs[ck+1], jb = ck*CKS;
        #pragma unroll 4
        for (int n = nb; n < ne; n++){
            int j = il[n];
            float wgt = sp[j];
            float2 v2 = ((const float2*)&vsh[(j - jb)*Dd])[lane];
            acc.x += wgt*v2.x; acc.y += wgt*v2.y;
        }
    }
    float2 o = {acc.x*invZ, acc.y*invZ};
    ((float2*)&g_xo[((size_t)b*Nn + nq0 + w)*Cc + h*Dd])[lane] = o;
}

__global__ void k_route(const float* __restrict__ routeW, const float* __restrict__ projA){
    const int row = blockIdx.x;
    const int tid = threadIdx.x;
    __shared__ float xs[Cc];
    __shared__ float lg[4], pl[32], sm[4];
    for (int i = tid; i < Cc; i += NT) xs[i] = g_xo[row*Cc + i];
    __syncthreads();
    const int warp = tid >> 5, lane = tid & 31;
    for (int o = warp; o < 36; o += 8){
        const float* a = (o < 4) ? &routeW[o*Cc] : &projA[(o - 4)*Cc];
        float p = 0.f;
        for (int i = lane; i < Cc; i += 32) p += xs[i] * a[i];
        #pragma unroll
        for (int off = 16; off; off >>= 1) p += __shfl_xor_sync(0xffffffffu, p, off);
        if (lane == 0){
            if (o < 4) lg[o] = p;
            else       pl[o - 4] = p;
        }
    }
    __syncthreads();
    if (tid == 0){
        float mx = fmaxf(fmaxf(lg[0], lg[1]), fmaxf(lg[2], lg[3]));
        float e0 = __expf(lg[0]-mx), e1 = __expf(lg[1]-mx);
        float e2 = __expf(lg[2]-mx), e3 = __expf(lg[3]-mx);
        float si = 1.f / (e0 + e1 + e2 + e3);
        sm[0] = e0*si; sm[1] = e1*si; sm[2] = e2*si; sm[3] = e3*si;
    }
    __syncthreads();
    if (tid < 32) g_wplow[row*32 + tid] = sm[tid >> 3] * pl[tid] * 0.125f;
}

__global__ void k_sgemm_proj(const float* __restrict__ W, const float* __restrict__ bp,
                             const float* __restrict__ projB, float* __restrict__ out){
    SGEMM_MAIN(g_xo, W, Cc)
    #pragma unroll
    for (int ii = 0; ii < 4; ii++){
        const int m = row0 + ty*4 + ii;
        float wl[32];
        #pragma unroll
        for (int t = 0; t < 32; t++) wl[t] = g_wplow[m*32 + t];
        #pragma unroll
        for (int jj = 0; jj < 4; jj++){
            const int c = col0 + tx*4 + jj;
            float lora = 0.f;
            #pragma unroll
            for (int e = 0; e < 4; e++){
                const float* bv = &projB[(e*Cc + c)*8];
                #pragma unroll
                for (int r = 0; r < 8; r++) lora += wl[e*8 + r] * bv[r];
            }
            out[m*Cc + c] = acc[ii][jj] + bp[c] + lora;
        }
    }
}

extern "C" void kernel_launch(void* const* d_in, const int* in_sizes, int n_in,
                              void* d_out, int out_size){
    const float* x      = (const float*)d_in[0];
    const float* idt    = (const float*)d_in[1];
    const float* memk   = (const float*)d_in[2];
    const float* memv   = (const float*)d_in[3];
    const float* Wqkv   = (const float*)d_in[4];
    const float* bqkv   = (const float*)d_in[5];
    const float* qkvA   = (const float*)d_in[6];
    const float* qkvB   = (const float*)d_in[7];
    const float* Wproj  = (const float*)d_in[8];
    const float* bproj  = (const float*)d_in[9];
    const float* routeW = (const float*)d_in[10];
    const float* projA  = (const float*)d_in[11];
    const float* projB  = (const float*)d_in[12];
    const float* Widk   = (const float*)d_in[13];
    const float* bidk   = (const float*)d_in[14];
    const float* idkA   = (const float*)d_in[15];
    const float* idkB   = (const float*)d_in[16];
    const float* Widv   = (const float*)d_in[17];
    const float* bidv   = (const float*)d_in[18];
    const float* idvA   = (const float*)d_in[19];
    const float* idvB   = (const float*)d_in[20];

    float* out  = (float*)d_out;
    float* kmid = out + Bb*Nn*Cc;
    float* vmid = kmid + Bb*Hh*NM*Dd;

    static int init = 0;
    if (!init){
        cudaFuncSetAttribute(k_attn_m, cudaFuncAttributeMaxDynamicSharedMemorySize, SMEM_M_TOT);
        cudaFuncSetAttribute(k_attn_s, cudaFuncAttributeMaxDynamicSharedMemorySize, SMEM_S_TOT);
        init = 1;
    }

    k_qkv_low<<<Bb*Nn, NT>>>(x, qkvA);
    k_sgemm_qkv<<<dim3(36, 80), NT>>>(x, Wqkv, bqkv, qkvB);
    k_id_small<<<Bb*NM, NT>>>(idt, idkA, idvA, Widk, bidk, idkB);
    k_sgemm_idv<<<dim3(12, 16), NT>>>(idt, Widv, bidv, idvB);
    k_apply_id<<<(Bb*Hh*NM*Dd)/NT, NT>>>(kmid, vmid);
    k_attn_m<<<Bb*Hh*NM/8, NT, SMEM_M_TOT>>>(kmid, vmid);
    k_attn_s<<<Bb*Hh*NSd/8, NT, SMEM_S_TOT>>>(memk, memv, vmid);
    k_route<<<Bb*Nn, NT>>>(routeW, projA);
    k_sgemm_proj<<<dim3(12, 80), NT>>>(Wproj, bproj, projB, out);
}

// round 6
// speedup vs baseline: 2.0596x; 1.4668x over previous
#include <cuda_runtime.h>

#define Bb 4
#define Nn 1280
#define NM 256
#define NSd 1024
#define Cc 768
#define Hh 12
#define Dd 64
#define MEMN 1280
#define LFULL 2560
#define KSEL_S 640
#define KSEL_M 128
#define NT 256
#define NTS 512
#define TQS 16
#define KTP 257
#define KT2 129
#define CKS 128
#define NCH 20

__device__ float g_q[Bb*Hh*Nn*Dd];
__device__ float g_k[Bb*Hh*Nn*Dd];
__device__ float g_v[Bb*Hh*Nn*Dd];
__device__ float g_qkvlow[Bb*Nn*24];
__device__ float g_idvlow[Bb*NM*8];
__device__ float g_act[Bb*NM*Hh];
__device__ float g_idv[Bb*NM*Cc];
__device__ float g_xo[Bb*Nn*Cc];
__device__ float g_wplow[Bb*Nn*32];

__device__ __forceinline__ unsigned fkey(float f){
    unsigned b = __float_as_uint(f);
    return (b & 0x80000000u) ? ~b : (b | 0x80000000u);
}

// Warp-synchronous exact top-K + softmax via register/ballot radix select.
template<int L, int KS, int GPC>
__device__ float warp_topk(float* sp, unsigned short* idxl, int* cs,
                           float vmax, int lane){
    const unsigned FULL = 0xffffffffu;
    const int G = L/32;
    const int SH[7] = {27,22,17,12,7,2,0};
    const int NB[7] = {5,5,5,5,5,5,2};
    unsigned prefix = 0; int need = KS;
    #pragma unroll
    for (int p = 0; p < 7; p++){
        const int shift = SH[p], nb = NB[p];
        const unsigned Bm = (1u << nb) - 1u;
        const unsigned maskhi = (p == 0) ? 0u : ~((1u << (shift + nb)) - 1u);
        unsigned cnt = 0;
        for (int g = 0; g < G; g++){
            unsigned key = fkey(sp[g*32 + lane]);
            bool act = ((key & maskhi) == prefix);
            unsigned wv = (key >> shift) & Bm;
            unsigned mact = __ballot_sync(FULL, act);
            unsigned m0 = __ballot_sync(FULL, wv & 1);
            unsigned m1 = __ballot_sync(FULL, wv & 2);
            unsigned sel = mact & ((lane & 1) ? m0 : ~m0)
                                & ((lane & 2) ? m1 : ~m1);
            if (nb == 5){
                unsigned m2 = __ballot_sync(FULL, wv & 4);
                unsigned m3 = __ballot_sync(FULL, wv & 8);
                unsigned m4 = __ballot_sync(FULL, wv & 16);
                sel &= (lane & 4) ? m2 : ~m2;
                sel &= (lane & 8) ? m3 : ~m3;
                sel &= (lane & 16) ? m4 : ~m4;
            }
            cnt += __popc(sel);
        }
        if ((unsigned)lane > Bm) cnt = 0;
        unsigned run = cnt;
        #pragma unroll
        for (int off = 1; off < 32; off <<= 1){
            unsigned v = __shfl_down_sync(FULL, run, off);
            if (lane + off < 32) run += v;
        }
        unsigned gt = run - cnt;
        bool isthr = ((int)run >= need) && ((int)gt < need);
        unsigned mthr = __ballot_sync(FULL, isthr);
        int tl = __ffs(mthr) - 1;
        unsigned gtt = __shfl_sync(FULL, gt, tl);
        need -= (int)gtt;
        prefix |= ((unsigned)tl) << shift;
    }
    const unsigned thr = prefix;
    int tieacc = 0, nsel = 0; float lsum = 0.f;
    for (int g = 0; g < G; g++){
        if ((g % GPC) == 0 && lane == 0) cs[g / GPC] = nsel;
        int j = g*32 + lane;
        float v = sp[j];
        unsigned key = fkey(v);
        bool eq = (key == thr);
        unsigned eqm = __ballot_sync(FULL, eq);
        bool selb = (key > thr) || (eq && (tieacc + __popc(eqm & ((1u<<lane)-1u))) < need);
        tieacc += __popc(eqm);
        float e = selb ? __expf(v - vmax) : 0.f;
        sp[j] = e; lsum += e;
        unsigned sm = __ballot_sync(FULL, selb);
        if (selb) idxl[nsel + __popc(sm & ((1u<<lane)-1u))] = (unsigned short)j;
        nsel += __popc(sm);
    }
    if (lane == 0) cs[G / GPC] = KS;
    #pragma unroll
    for (int off = 16; off; off >>= 1) lsum += __shfl_xor_sync(FULL, lsum, off);
    return lsum;
}

__global__ void k_qkv_low(const float* __restrict__ x, const float* __restrict__ qkvA){
    const int row = blockIdx.x;
    const int tid = threadIdx.x;
    __shared__ float xs[Cc];
    for (int i = tid; i < Cc; i += NT) xs[i] = x[row*Cc + i];
    __syncthreads();
    const int warp = tid >> 5, lane = tid & 31;
    for (int o = warp; o < 24; o += 8){
        const float* a = &qkvA[o*Cc];
        float p = 0.f;
        for (int i = lane; i < Cc; i += 32) p += xs[i] * a[i];
        #pragma unroll
        for (int off = 16; off; off >>= 1) p += __shfl_xor_sync(0xffffffffu, p, off);
        if (lane == 0) g_qkvlow[row*24 + o] = p;
    }
}

#define SGEMM_MAIN(Aptr, Wptr, KDIM)                                              \
    __shared__ __align__(16) float As[16*64];                                      \
    __shared__ __align__(16) float Ws[16*64];                                      \
    float acc[4][4];                                                               \
    _Pragma("unroll") for (int i_ = 0; i_ < 4; i_++)                               \
    _Pragma("unroll") for (int j_ = 0; j_ < 4; j_++) acc[i_][j_] = 0.f;            \
    const int tid = threadIdx.x;                                                   \
    const int ty = tid >> 4, tx = tid & 15;                                        \
    const int lr = tid >> 2, lk = (tid & 3) * 4;                                   \
    const int row0 = blockIdx.y * 64, col0 = blockIdx.x * 64;                      \
    for (int kt = 0; kt < KDIM; kt += 16){                                         \
        float4 a4 = *(const float4*)&Aptr[(row0 + lr)*KDIM + kt + lk];             \
        float4 w4 = *(const float4*)&Wptr[(col0 + lr)*KDIM + kt + lk];             \
        __syncthreads();                                                           \
        As[(lk+0)*64 + lr] = a4.x; As[(lk+1)*64 + lr] = a4.y;                      \
        As[(lk+2)*64 + lr] = a4.z; As[(lk+3)*64 + lr] = a4.w;                      \
        Ws[(lk+0)*64 + lr] = w4.x; Ws[(lk+1)*64 + lr] = w4.y;                      \
        Ws[(lk+2)*64 + lr] = w4.z; Ws[(lk+3)*64 + lr] = w4.w;                      \
        __syncthreads();                                                           \
        _Pragma("unroll")                                                          \
        for (int kk = 0; kk < 16; kk++){                                           \
            float4 ra = *(const float4*)&As[kk*64 + ty*4];                         \
            float4 rb = *(const float4*)&Ws[kk*64 + tx*4];                         \
            acc[0][0] += ra.x*rb.x; acc[0][1] += ra.x*rb.y;                        \
            acc[0][2] += ra.x*rb.z; acc[0][3] += ra.x*rb.w;                        \
            acc[1][0] += ra.y*rb.x; acc[1][1] += ra.y*rb.y;                        \
            acc[1][2] += ra.y*rb.z; acc[1][3] += ra.y*rb.w;                        \
            acc[2][0] += ra.z*rb.x; acc[2][1] += ra.z*rb.y;                        \
            acc[2][2] += ra.z*rb.z; acc[2][3] += ra.z*rb.w;                        \
            acc[3][0] += ra.w*rb.x; acc[3][1] += ra.w*rb.y;                        \
            acc[3][2] += ra.w*rb.z; acc[3][3] += ra.w*rb.w;                        \
        }                                                                          \
    }

__global__ void k_sgemm_qkv(const float* __restrict__ x, const float* __restrict__ W,
                            const float* __restrict__ bq, const float* __restrict__ qkvB){
    SGEMM_MAIN(x, W, Cc)
    const int g = col0 / Cc;
    #pragma unroll
    for (int ii = 0; ii < 4; ii++){
        const int m = row0 + ty*4 + ii;
        const int b = m / Nn, n = m % Nn;
        float lw[8];
        #pragma unroll
        for (int r = 0; r < 8; r++) lw[r] = g_qkvlow[m*24 + g*8 + r];
        #pragma unroll
        for (int jj = 0; jj < 4; jj++){
            const int j = col0 + tx*4 + jj;
            const int c = j - g*Cc;
            const float* bv = &qkvB[(g*Cc + c)*8];
            float lora = 0.f;
            #pragma unroll
            for (int r = 0; r < 8; r++) lora += lw[r] * bv[r];
            float val = acc[ii][jj] + bq[j] + 0.125f * lora;
            const int h = c >> 6, d = c & 63;
            const int dst = ((b*Hh + h)*Nn + n)*Dd + d;
            if (g == 0)      g_q[dst] = val * 0.125f;
            else if (g == 1) g_k[dst] = val;
            else             g_v[dst] = val;
        }
    }
}

__global__ void k_id_small(const float* __restrict__ idt, const float* __restrict__ idkA,
                           const float* __restrict__ idvA, const float* __restrict__ Widk,
                           const float* __restrict__ bidk, const float* __restrict__ idkB){
    const int row = blockIdx.x;
    const int tid = threadIdx.x;
    __shared__ float xs[Cc];
    __shared__ float lk[8], dk[12];
    for (int i = tid; i < Cc; i += NT) xs[i] = idt[row*Cc + i];
    __syncthreads();
    const int warp = tid >> 5, lane = tid & 31;
    for (int o = warp; o < 28; o += 8){
        const float* a;
        if (o < 8)       a = &idkA[o*Cc];
        else if (o < 16) a = &idvA[(o - 8)*Cc];
        else             a = &Widk[(o - 16)*Cc];
        float p = 0.f;
        for (int i = lane; i < Cc; i += 32) p += xs[i] * a[i];
        #pragma unroll
        for (int off = 16; off; off >>= 1) p += __shfl_xor_sync(0xffffffffu, p, off);
        if (lane == 0){
            if (o < 8)       lk[o] = p;
            else if (o < 16) g_idvlow[row*8 + (o - 8)] = p;
            else             dk[o - 16] = p;
        }
    }
    __syncthreads();
    if (tid < 12){
        float lo = 0.f;
        #pragma unroll
        for (int r = 0; r < 8; r++) lo += lk[r] * idkB[tid*8 + r];
        float f = dk[tid] + bidk[tid] + 0.125f * lo;
        g_act[row*Hh + tid] = 1.f + tanhf(f);
    }
}

__global__ void k_sgemm_idv(const float* __restrict__ idt, const float* __restrict__ W,
                            const float* __restrict__ bidv, const float* __restrict__ idvB){
    SGEMM_MAIN(idt, W, Cc)
    #pragma unroll
    for (int ii = 0; ii < 4; ii++){
        const int m = row0 + ty*4 + ii;
        float lw[8];
        #pragma unroll
        for (int r = 0; r < 8; r++) lw[r] = g_idvlow[m*8 + r];
        #pragma unroll
        for (int jj = 0; jj < 4; jj++){
            const int c = col0 + tx*4 + jj;
            const float* bv = &idvB[c*8];
            float lora = 0.f;
            #pragma unroll
            for (int r = 0; r < 8; r++) lora += lw[r] * bv[r];
            g_idv[m*Cc + c] = acc[ii][jj] + bidv[c] + 0.125f * lora;
        }
    }
}

__global__ void k_apply_id(float* __restrict__ kmid, float* __restrict__ vmid){
    const int idx = blockIdx.x * NT + threadIdx.x;
    const int d = idx & 63;
    int t = idx >> 6;
    const int m = t % NM; t /= NM;
    const int h = t % Hh; const int b = t / Hh;
    const int src = ((b*Hh + h)*Nn + m)*Dd + d;
    kmid[idx] = g_k[src] * g_act[(b*NM + m)*Hh + h];
    vmid[idx] = g_v[src] + g_idv[(b*NM + m)*Cc + h*Dd + d];
}

// ---- mem attention: 16 rows/block, 512 threads, 1 warp per row ----
#define SMM_S    0
#define SMM_KT   16384
#define SMM_QS   82176
#define SMM_IDX  86272
#define SMM_CS   90368
#define SMEM_M_TOT 90496

__global__ __launch_bounds__(NTS, 2)
void k_attn_m(const float* __restrict__ kmid, const float* __restrict__ vmid){
    extern __shared__ __align__(16) char smb[];
    float* s  = (float*)(smb + SMM_S);
    float* kt = (float*)(smb + SMM_KT);
    float* qs = (float*)(smb + SMM_QS);
    unsigned short* idxall = (unsigned short*)(smb + SMM_IDX);
    int* csall = (int*)(smb + SMM_CS);
    const int tid = threadIdx.x, lane = tid & 31, w = tid >> 5;
    const int qt = blockIdx.x & 15;
    const int bh = blockIdx.x >> 4;
    const int b = bh / Hh, h = bh % Hh;
    const int m0 = qt * TQS;
    #pragma unroll
    for (int i = tid; i < TQS*Dd; i += NTS){
        int r = i >> 6, d = i & 63;
        qs[i] = g_q[((size_t)bh*Nn + m0 + r)*Dd + d];
    }
    #pragma unroll
    for (int ph = 0; ph < 8; ph++){
        int idx = tid + ph*NTS;
        int r = idx >> 4, c4 = idx & 15;
        float4 kv = *(const float4*)&kmid[((size_t)bh*NM + r)*Dd + c4*4];
        kt[(c4*4+0)*KTP + r] = kv.x;
        kt[(c4*4+1)*KTP + r] = kv.y;
        kt[(c4*4+2)*KTP + r] = kv.z;
        kt[(c4*4+3)*KTP + r] = kv.w;
    }
    __syncthreads();
    {
        const int key = tid & 255, rg = (tid >> 8) * 8;
        float acc8[8];
        #pragma unroll
        for (int r = 0; r < 8; r++) acc8[r] = 0.f;
        const float4* qs4 = (const float4*)qs;
        #pragma unroll 2
        for (int i4 = 0; i4 < 16; i4++){
            float k0 = kt[(i4*4+0)*KTP + key];
            float k1 = kt[(i4*4+1)*KTP + key];
            float k2 = kt[(i4*4+2)*KTP + key];
            float k3 = kt[(i4*4+3)*KTP + key];
            #pragma unroll
            for (int r = 0; r < 8; r++){
                float4 q4 = qs4[(rg+r)*16 + i4];
                acc8[r] += k0*q4.x + k1*q4.y + k2*q4.z + k3*q4.w;
            }
        }
        #pragma unroll
        for (int r = 0; r < 8; r++) s[(rg+r)*NM + key] = acc8[r];
    }
    __syncthreads();
    float* sp = s + w*NM;
    float lmax = -1e30f;
    #pragma unroll
    for (int g = 0; g < NM/32; g++) lmax = fmaxf(lmax, sp[g*32 + lane]);
    #pragma unroll
    for (int off = 16; off; off >>= 1) lmax = fmaxf(lmax, __shfl_xor_sync(0xffffffffu, lmax, off));
    float Z = warp_topk<NM, KSEL_M, 8>(sp, idxall + w*KSEL_M, csall + w*2, lmax, lane);
    float invZ = 1.f / Z;
    __syncthreads();
    float* vsh = kt;
    #pragma unroll
    for (int ph = 0; ph < 8; ph++){
        int idx = tid + ph*NTS;
        int r = idx >> 4, c4 = idx & 15;
        *(float4*)&vsh[r*Dd + c4*4] = *(const float4*)&vmid[((size_t)bh*NM + r)*Dd + c4*4];
    }
    __syncthreads();
    float2 acc = {0.f, 0.f};
    const unsigned short* il = idxall + w*KSEL_M;
    #pragma unroll 4
    for (int n = 0; n < KSEL_M; n++){
        int j = il[n];
        float wgt = sp[j];
        float2 v2 = ((const float2*)&vsh[j*Dd])[lane];
        acc.x += wgt*v2.x; acc.y += wgt*v2.y;
    }
    float2 o = {acc.x*invZ, acc.y*invZ};
    ((float2*)&g_xo[((size_t)b*Nn + m0 + w)*Cc + h*Dd])[lane] = o;
}

// ---- streaming attention: 16 rows/block, 512 threads, reg-prefetch ----
#define SMS_S    0
#define SMS_KT   163840
#define SMS_QS   196864
#define SMS_CS   200960
#define SMS_IDX  202496
#define SMEM_S_TOT 222976

__global__ __launch_bounds__(NTS, 1)
void k_attn_s(const float* __restrict__ memk, const float* __restrict__ memv,
              const float* __restrict__ vmid){
    extern __shared__ __align__(16) char smb[];
    float* s  = (float*)(smb + SMS_S);
    float* kt = (float*)(smb + SMS_KT);
    float* qs = (float*)(smb + SMS_QS);
    int* csall = (int*)(smb + SMS_CS);
    unsigned short* idxall = (unsigned short*)(smb + SMS_IDX);
    const int tid = threadIdx.x, lane = tid & 31, w = tid >> 5;
    const int qt = blockIdx.x & 63;
    const int bh = blockIdx.x >> 6;
    const int b = bh / Hh, h = bh % Hh;
    const int nq0 = NM + qt*TQS;
    #pragma unroll
    for (int i = tid; i < TQS*Dd; i += NTS){
        int r = i >> 6, d = i & 63;
        qs[i] = g_q[((size_t)bh*Nn + nq0 + r)*Dd + d];
    }
    const int pr = tid >> 2;            // key row 0..127
    const int pco = (tid & 3) * 4;      // float4 base 0,4,8,12
    float4 pre[4];
    {
        const float* kr = &memk[((size_t)bh*MEMN + pr)*Dd];
        #pragma unroll
        for (int i = 0; i < 4; i++) pre[i] = ((const float4*)kr)[pco + i];
    }
    const int key = tid & 127, rbase = (tid >> 7) * 4;
    const float4* qs4 = (const float4*)qs;
    for (int ck = 0; ck < NCH; ck++){
        __syncthreads();
        #pragma unroll
        for (int i = 0; i < 4; i++){
            int c = (pco + i)*4;
            kt[(c+0)*KT2 + pr] = pre[i].x; kt[(c+1)*KT2 + pr] = pre[i].y;
            kt[(c+2)*KT2 + pr] = pre[i].z; kt[(c+3)*KT2 + pr] = pre[i].w;
        }
        __syncthreads();
        if (ck + 1 < NCH){
            int j = (ck+1)*CKS + pr;
            const float* kr = (j < MEMN) ? &memk[((size_t)bh*MEMN + j)*Dd]
                                         : &g_k[((size_t)bh*Nn + (j - MEMN))*Dd];
            #pragma unroll
            for (int i = 0; i < 4; i++) pre[i] = ((const float4*)kr)[pco + i];
        }
        float a0 = 0.f, a1 = 0.f, a2 = 0.f, a3 = 0.f;
        #pragma unroll 4
        for (int i4 = 0; i4 < 16; i4++){
            float k0 = kt[(i4*4+0)*KT2 + key];
            float k1 = kt[(i4*4+1)*KT2 + key];
            float k2 = kt[(i4*4+2)*KT2 + key];
            float k3 = kt[(i4*4+3)*KT2 + key];
            float4 qa = qs4[(rbase+0)*16 + i4];
            float4 qb = qs4[(rbase+1)*16 + i4];
            float4 qc = qs4[(rbase+2)*16 + i4];
            float4 qd = qs4[(rbase+3)*16 + i4];
            a0 += k0*qa.x + k1*qa.y + k2*qa.z + k3*qa.w;
            a1 += k0*qb.x + k1*qb.y + k2*qb.z + k3*qb.w;
            a2 += k0*qc.x + k1*qc.y + k2*qc.z + k3*qc.w;
            a3 += k0*qd.x + k1*qd.y + k2*qd.z + k3*qd.w;
        }
        s[(rbase+0)*LFULL + ck*CKS + key] = a0;
        s[(rbase+1)*LFULL + ck*CKS + key] = a1;
        s[(rbase+2)*LFULL + ck*CKS + key] = a2;
        s[(rbase+3)*LFULL + ck*CKS + key] = a3;
    }
    __syncthreads();
    float* sp = s + w*LFULL;
    int* cs = csall + w*24;
    unsigned short* il = idxall + w*KSEL_S;
    float lmax = -1e30f;
    for (int g = 0; g < LFULL/32; g++) lmax = fmaxf(lmax, sp[g*32 + lane]);
    #pragma unroll
    for (int off = 16; off; off >>= 1) lmax = fmaxf(lmax, __shfl_xor_sync(0xffffffffu, lmax, off));
    float Z = warp_topk<LFULL, KSEL_S, 4>(sp, il, cs, lmax, lane);
    float invZ = 1.f / Z;
    // V phase
    float* vsh = kt;
    {
        const float* vr = &memv[((size_t)bh*MEMN + pr)*Dd];
        #pragma unroll
        for (int i = 0; i < 4; i++) pre[i] = ((const float4*)vr)[pco + i];
    }
    float2 acc = {0.f, 0.f};
    for (int ck = 0; ck < NCH; ck++){
        __syncthreads();
        #pragma unroll
        for (int i = 0; i < 4; i++)
            *(float4*)&vsh[pr*Dd + (pco + i)*4] = pre[i];
        __syncthreads();
        if (ck + 1 < NCH){
            int j = (ck+1)*CKS + pr;
            const float* vr;
            if (j < MEMN)            vr = &memv[((size_t)bh*MEMN + j)*Dd];
            else if (j < MEMN + NM)  vr = &vmid[((size_t)bh*NM + (j - MEMN))*Dd];
            else                     vr = &g_v[((size_t)bh*Nn + (j - MEMN))*Dd];
            #pragma unroll
            for (int i = 0; i < 4; i++) pre[i] = ((const float4*)vr)[pco + i];
        }
        const int nb = cs[ck], ne = cs[ck+1], jb = ck*CKS;
        #pragma unroll 4
        for (int n = nb; n < ne; n++){
            int j = il[n];
            float wgt = sp[j];
            float2 v2 = ((const float2*)&vsh[(j - jb)*Dd])[lane];
            acc.x += wgt*v2.x; acc.y += wgt*v2.y;
        }
    }
    float2 o = {acc.x*invZ, acc.y*invZ};
    ((float2*)&g_xo[((size_t)b*Nn + nq0 + w)*Cc + h*Dd])[lane] = o;
}

__global__ void k_route(const float* __restrict__ routeW, const float* __restrict__ projA){
    const int row = blockIdx.x;
    const int tid = threadIdx.x;
    __shared__ float xs[Cc];
    __shared__ float lg[4], pl[32], sm[4];
    for (int i = tid; i < Cc; i += NT) xs[i] = g_xo[row*Cc + i];
    __syncthreads();
    const int warp = tid >> 5, lane = tid & 31;
    for (int o = warp; o < 36; o += 8){
        const float* a = (o < 4) ? &routeW[o*Cc] : &projA[(o - 4)*Cc];
        float p = 0.f;
        for (int i = lane; i < Cc; i += 32) p += xs[i] * a[i];
        #pragma unroll
        for (int off = 16; off; off >>= 1) p += __shfl_xor_sync(0xffffffffu, p, off);
        if (lane == 0){
            if (o < 4) lg[o] = p;
            else       pl[o - 4] = p;
        }
    }
    __syncthreads();
    if (tid == 0){
        float mx = fmaxf(fmaxf(lg[0], lg[1]), fmaxf(lg[2], lg[3]));
        float e0 = __expf(lg[0]-mx), e1 = __expf(lg[1]-mx);
        float e2 = __expf(lg[2]-mx), e3 = __expf(lg[3]-mx);
        float si = 1.f / (e0 + e1 + e2 + e3);
        sm[0] = e0*si; sm[1] = e1*si; sm[2] = e2*si; sm[3] = e3*si;
    }
    __syncthreads();
    if (tid < 32) g_wplow[row*32 + tid] = sm[tid >> 3] * pl[tid] * 0.125f;
}

__global__ void k_sgemm_proj(const float* __restrict__ W, const float* __restrict__ bp,
                             const float* __restrict__ projB, float* __restrict__ out){
    SGEMM_MAIN(g_xo, W, Cc)
    #pragma unroll
    for (int ii = 0; ii < 4; ii++){
        const int m = row0 + ty*4 + ii;
        float wl[32];
        #pragma unroll
        for (int t = 0; t < 32; t++) wl[t] = g_wplow[m*32 + t];
        #pragma unroll
        for (int jj = 0; jj < 4; jj++){
            const int c = col0 + tx*4 + jj;
            float lora = 0.f;
            #pragma unroll
            for (int e = 0; e < 4; e++){
                const float* bv = &projB[(e*Cc + c)*8];
                #pragma unroll
                for (int r = 0; r < 8; r++) lora += wl[e*8 + r] * bv[r];
            }
            out[m*Cc + c] = acc[ii][jj] + bp[c] + lora;
        }
    }
}

extern "C" void kernel_launch(void* const* d_in, const int* in_sizes, int n_in,
                              void* d_out, int out_size){
    const float* x      = (const float*)d_in[0];
    const float* idt    = (const float*)d_in[1];
    const float* memk   = (const float*)d_in[2];
    const float* memv   = (const float*)d_in[3];
    const float* Wqkv   = (const float*)d_in[4];
    const float* bqkv   = (const float*)d_in[5];
    const float* qkvA   = (const float*)d_in[6];
    const float* qkvB   = (const float*)d_in[7];
    const float* Wproj  = (const float*)d_in[8];
    const float* bproj  = (const float*)d_in[9];
    const float* routeW = (const float*)d_in[10];
    const float* projA  = (const float*)d_in[11];
    const float* projB  = (const float*)d_in[12];
    const float* Widk   = (const float*)d_in[13];
    const float* bidk   = (const float*)d_in[14];
    const float* idkA   = (const float*)d_in[15];
    const float* idkB   = (const float*)d_in[16];
    const float* Widv   = (const float*)d_in[17];
    const float* bidv   = (const float*)d_in[18];
    const float* idvA   = (const float*)d_in[19];
    const float* idvB   = (const float*)d_in[20];

    float* out  = (float*)d_out;
    float* kmid = out + Bb*Nn*Cc;
    float* vmid = kmid + Bb*Hh*NM*Dd;

    static int init = 0;
    if (!init){
        cudaFuncSetAttribute(k_attn_m, cudaFuncAttributeMaxDynamicSharedMemorySize, SMEM_M_TOT);
        cudaFuncSetAttribute(k_attn_s, cudaFuncAttributeMaxDynamicSharedMemorySize, SMEM_S_TOT);
        init = 1;
    }

    k_qkv_low<<<Bb*Nn, NT>>>(x, qkvA);
    k_sgemm_qkv<<<dim3(36, 80), NT>>>(x, Wqkv, bqkv, qkvB);
    k_id_small<<<Bb*NM, NT>>>(idt, idkA, idvA, Widk, bidk, idkB);
    k_sgemm_idv<<<dim3(12, 16), NT>>>(idt, Widv, bidv, idvB);
    k_apply_id<<<(Bb*Hh*NM*Dd)/NT, NT>>>(kmid, vmid);
    k_attn_m<<<Bb*Hh*NM/TQS, NTS, SMEM_M_TOT>>>(kmid, vmid);
    k_attn_s<<<Bb*Hh*NSd/TQS, NTS, SMEM_S_TOT>>>(memk, memv, vmid);
    k_route<<<Bb*Nn, NT>>>(routeW, projA);
    k_sgemm_proj<<<dim3(12, 80), NT>>>(Wproj, bproj, projB, out);
}

// round 7
// speedup vs baseline: 2.3275x; 1.1301x over previous
#include <cuda_runtime.h>

#define Bb 4
#define Nn 1280
#define NM 256
#define NSd 1024
#define Cc 768
#define Hh 12
#define Dd 64
#define MEMN 1280
#define LFULL 2560
#define KSEL_S 640
#define KSEL_M 128
#define NT 256
#define NTS 512
#define TQS 16
#define KTP 257
#define KT2 129
#define CKS 128
#define NCH 20

__device__ float g_q[Bb*Hh*Nn*Dd];
__device__ float g_k[Bb*Hh*Nn*Dd];
__device__ float g_v[Bb*Hh*Nn*Dd];
__device__ float g_qkvlow[Bb*Nn*24];
__device__ float g_idvlow[Bb*NM*8];
__device__ float g_act[Bb*NM*Hh];
__device__ float g_idv[Bb*NM*Cc];
__device__ float g_xo[Bb*Nn*Cc];
__device__ float g_wplow[Bb*Nn*32];

__device__ __forceinline__ unsigned fkey(float f){
    unsigned b = __float_as_uint(f);
    return (b & 0x80000000u) ? ~b : (b | 0x80000000u);
}
__device__ __forceinline__ float inv_fkey(unsigned k){
    return (k & 0x80000000u) ? __uint_as_float(k ^ 0x80000000u)
                             : __uint_as_float(~k);
}

// Warp-synchronous exact top-K + softmax. Scores arrive PRE-CONVERTED to
// order-preserving keys (unsigned) in sp. Radix select via register/ballot
// histogram, with early exit when the threshold bin count equals the
// remaining need. On exit sp holds float softmax weights (0 for unselected).
template<int L, int KS, int GPC>
__device__ float warp_topk(float* sp, unsigned short* idxl, int* cs,
                           unsigned maxkey, int lane){
    const unsigned FULL = 0xffffffffu;
    unsigned* spk = (unsigned*)sp;
    const int G = L/32;
    const float vmax = inv_fkey(maxkey);
    unsigned prefix = 0; int need = KS;
    const int SH[7] = {27,22,17,12,7,2,0};
    const int NB[7] = {5,5,5,5,5,5,2};
    #pragma unroll
    for (int p = 0; p < 7; p++){
        const int shift = SH[p], nb = NB[p];
        const unsigned Bm = (1u << nb) - 1u;
        const unsigned maskhi = (p == 0) ? 0u : ~((1u << (shift + nb)) - 1u);
        unsigned cnt = 0;
        for (int g = 0; g < G; g++){
            unsigned key = spk[g*32 + lane];
            bool act = ((key & maskhi) == prefix);
            unsigned wv = (key >> shift) & Bm;
            unsigned mact = __ballot_sync(FULL, act);
            unsigned m0 = __ballot_sync(FULL, wv & 1);
            unsigned m1 = __ballot_sync(FULL, wv & 2);
            unsigned sel = mact & ((lane & 1) ? m0 : ~m0)
                                & ((lane & 2) ? m1 : ~m1);
            if (nb == 5){
                unsigned m2 = __ballot_sync(FULL, wv & 4);
                unsigned m3 = __ballot_sync(FULL, wv & 8);
                unsigned m4 = __ballot_sync(FULL, wv & 16);
                sel &= (lane & 4) ? m2 : ~m2;
                sel &= (lane & 8) ? m3 : ~m3;
                sel &= (lane & 16) ? m4 : ~m4;
            }
            cnt += __popc(sel);
        }
        if ((unsigned)lane > Bm) cnt = 0;
        unsigned run = cnt;
        #pragma unroll
        for (int off = 1; off < 32; off <<= 1){
            unsigned v = __shfl_down_sync(FULL, run, off);
            if (lane + off < 32) run += v;
        }
        unsigned gt = run - cnt;
        bool isthr = ((int)run >= need) && ((int)gt < need);
        unsigned mthr = __ballot_sync(FULL, isthr);
        int tl = __ffs(mthr) - 1;
        unsigned gtt = __shfl_sync(FULL, gt, tl);
        need -= (int)gtt;
        prefix |= ((unsigned)tl) << shift;
        unsigned cb = __shfl_sync(FULL, cnt, tl);
        if ((int)cb == need) break;   // whole bin selected; low bits irrelevant
    }
    const unsigned thr = prefix;
    int tieacc = 0, nsel = 0; float lsum = 0.f;
    for (int g = 0; g < G; g++){
        if ((g % GPC) == 0 && lane == 0) cs[g / GPC] = nsel;
        int j = g*32 + lane;
        unsigned key = spk[j];
        bool eq = (key == thr);
        unsigned eqm = __ballot_sync(FULL, eq);
        bool selb = (key > thr) || (eq && (tieacc + __popc(eqm & ((1u<<lane)-1u))) < need);
        tieacc += __popc(eqm);
        float v = inv_fkey(key);
        float e = selb ? __expf(v - vmax) : 0.f;
        sp[j] = e; lsum += e;
        unsigned sm = __ballot_sync(FULL, selb);
        if (selb) idxl[nsel + __popc(sm & ((1u<<lane)-1u))] = (unsigned short)j;
        nsel += __popc(sm);
    }
    if (lane == 0) cs[G / GPC] = KS;
    #pragma unroll
    for (int off = 16; off; off >>= 1) lsum += __shfl_xor_sync(FULL, lsum, off);
    return lsum;
}

// ---- qkv lora low, 8 rows per block ----
__global__ void k_qkv_low(const float* __restrict__ x, const float* __restrict__ qkvA){
    __shared__ float xs[8*Cc];
    const int tid = threadIdx.x;
    const int m0 = blockIdx.x * 8;
    for (int i = tid; i < 8*Cc; i += NT) xs[i] = x[(size_t)m0*Cc + i];
    __syncthreads();
    const int warp = tid >> 5, lane = tid & 31;
    for (int o = warp; o < 24; o += 8){
        const float* a = &qkvA[o*Cc];
        float acc[8];
        #pragma unroll
        for (int r = 0; r < 8; r++) acc[r] = 0.f;
        for (int i = lane; i < Cc; i += 32){
            float av = a[i];
            #pragma unroll
            for (int r = 0; r < 8; r++) acc[r] += xs[r*Cc + i] * av;
        }
        #pragma unroll
        for (int r = 0; r < 8; r++){
            float p = acc[r];
            #pragma unroll
            for (int off = 16; off; off >>= 1) p += __shfl_xor_sync(0xffffffffu, p, off);
            if (lane == 0) g_qkvlow[(m0 + r)*24 + o] = p;
        }
    }
}

#define SGEMM_MAIN(Aptr, Wptr, KDIM)                                              \
    __shared__ __align__(16) float As[16*64];                                      \
    __shared__ __align__(16) float Ws[16*64];                                      \
    float acc[4][4];                                                               \
    _Pragma("unroll") for (int i_ = 0; i_ < 4; i_++)                               \
    _Pragma("unroll") for (int j_ = 0; j_ < 4; j_++) acc[i_][j_] = 0.f;            \
    const int tid = threadIdx.x;                                                   \
    const int ty = tid >> 4, tx = tid & 15;                                        \
    const int lr = tid >> 2, lk = (tid & 3) * 4;                                   \
    const int row0 = blockIdx.y * 64, col0 = blockIdx.x * 64;                      \
    for (int kt = 0; kt < KDIM; kt += 16){                                         \
        float4 a4 = *(const float4*)&Aptr[(row0 + lr)*KDIM + kt + lk];             \
        float4 w4 = *(const float4*)&Wptr[(col0 + lr)*KDIM + kt + lk];             \
        __syncthreads();                                                           \
        As[(lk+0)*64 + lr] = a4.x; As[(lk+1)*64 + lr] = a4.y;                      \
        As[(lk+2)*64 + lr] = a4.z; As[(lk+3)*64 + lr] = a4.w;                      \
        Ws[(lk+0)*64 + lr] = w4.x; Ws[(lk+1)*64 + lr] = w4.y;                      \
        Ws[(lk+2)*64 + lr] = w4.z; Ws[(lk+3)*64 + lr] = w4.w;                      \
        __syncthreads();                                                           \
        _Pragma("unroll")                                                          \
        for (int kk = 0; kk < 16; kk++){                                           \
            float4 ra = *(const float4*)&As[kk*64 + ty*4];                         \
            float4 rb = *(const float4*)&Ws[kk*64 + tx*4];                         \
            acc[0][0] += ra.x*rb.x; acc[0][1] += ra.x*rb.y;                        \
            acc[0][2] += ra.x*rb.z; acc[0][3] += ra.x*rb.w;                        \
            acc[1][0] += ra.y*rb.x; acc[1][1] += ra.y*rb.y;                        \
            acc[1][2] += ra.y*rb.z; acc[1][3] += ra.y*rb.w;                        \
            acc[2][0] += ra.z*rb.x; acc[2][1] += ra.z*rb.y;                        \
            acc[2][2] += ra.z*rb.z; acc[2][3] += ra.z*rb.w;                        \
            acc[3][0] += ra.w*rb.x; acc[3][1] += ra.w*rb.y;                        \
            acc[3][2] += ra.w*rb.z; acc[3][3] += ra.w*rb.w;                        \
        }                                                                          \
    }

__global__ void k_sgemm_qkv(const float* __restrict__ x, const float* __restrict__ W,
                            const float* __restrict__ bq, const float* __restrict__ qkvB){
    SGEMM_MAIN(x, W, Cc)
    const int g = col0 / Cc;
    #pragma unroll
    for (int ii = 0; ii < 4; ii++){
        const int m = row0 + ty*4 + ii;
        const int b = m / Nn, n = m % Nn;
        float lw[8];
        #pragma unroll
        for (int r = 0; r < 8; r++) lw[r] = g_qkvlow[m*24 + g*8 + r];
        #pragma unroll
        for (int jj = 0; jj < 4; jj++){
            const int j = col0 + tx*4 + jj;
            const int c = j - g*Cc;
            const float* bv = &qkvB[(g*Cc + c)*8];
            float lora = 0.f;
            #pragma unroll
            for (int r = 0; r < 8; r++) lora += lw[r] * bv[r];
            float val = acc[ii][jj] + bq[j] + 0.125f * lora;
            const int h = c >> 6, d = c & 63;
            const int dst = ((b*Hh + h)*Nn + n)*Dd + d;
            if (g == 0)      g_q[dst] = val * 0.125f;
            else if (g == 1) g_k[dst] = val;
            else             g_v[dst] = val;
        }
    }
}

__global__ void k_id_small(const float* __restrict__ idt, const float* __restrict__ idkA,
                           const float* __restrict__ idvA, const float* __restrict__ Widk,
                           const float* __restrict__ bidk, const float* __restrict__ idkB){
    const int row = blockIdx.x;
    const int tid = threadIdx.x;
    __shared__ float xs[Cc];
    __shared__ float lk[8], dk[12];
    for (int i = tid; i < Cc; i += NT) xs[i] = idt[row*Cc + i];
    __syncthreads();
    const int warp = tid >> 5, lane = tid & 31;
    for (int o = warp; o < 28; o += 8){
        const float* a;
        if (o < 8)       a = &idkA[o*Cc];
        else if (o < 16) a = &idvA[(o - 8)*Cc];
        else             a = &Widk[(o - 16)*Cc];
        float p = 0.f;
        for (int i = lane; i < Cc; i += 32) p += xs[i] * a[i];
        #pragma unroll
        for (int off = 16; off; off >>= 1) p += __shfl_xor_sync(0xffffffffu, p, off);
        if (lane == 0){
            if (o < 8)       lk[o] = p;
            else if (o < 16) g_idvlow[row*8 + (o - 8)] = p;
            else             dk[o - 16] = p;
        }
    }
    __syncthreads();
    if (tid < 12){
        float lo = 0.f;
        #pragma unroll
        for (int r = 0; r < 8; r++) lo += lk[r] * idkB[tid*8 + r];
        float f = dk[tid] + bidk[tid] + 0.125f * lo;
        g_act[row*Hh + tid] = 1.f + tanhf(f);
    }
}

__global__ void k_sgemm_idv(const float* __restrict__ idt, const float* __restrict__ W,
                            const float* __restrict__ bidv, const float* __restrict__ idvB){
    SGEMM_MAIN(idt, W, Cc)
    #pragma unroll
    for (int ii = 0; ii < 4; ii++){
        const int m = row0 + ty*4 + ii;
        float lw[8];
        #pragma unroll
        for (int r = 0; r < 8; r++) lw[r] = g_idvlow[m*8 + r];
        #pragma unroll
        for (int jj = 0; jj < 4; jj++){
            const int c = col0 + tx*4 + jj;
            const float* bv = &idvB[c*8];
            float lora = 0.f;
            #pragma unroll
            for (int r = 0; r < 8; r++) lora += lw[r] * bv[r];
            g_idv[m*Cc + c] = acc[ii][jj] + bidv[c] + 0.125f * lora;
        }
    }
}

__global__ void k_apply_id(float* __restrict__ kmid, float* __restrict__ vmid){
    const int idx = blockIdx.x * NT + threadIdx.x;
    const int d = idx & 63;
    int t = idx >> 6;
    const int m = t % NM; t /= NM;
    const int h = t % Hh; const int b = t / Hh;
    const int src = ((b*Hh + h)*Nn + m)*Dd + d;
    kmid[idx] = g_k[src] * g_act[(b*NM + m)*Hh + h];
    vmid[idx] = g_v[src] + g_idv[(b*NM + m)*Cc + h*Dd + d];
}

// ---- mem attention: 16 rows/block, 512 threads ----
#define SMM_S    0
#define SMM_KT   16384
#define SMM_QS   82176
#define SMM_IDX  86272
#define SMM_CS   90368
#define SMEM_M_TOT 90496

__global__ __launch_bounds__(NTS, 2)
void k_attn_m(const float* __restrict__ kmid, const float* __restrict__ vmid){
    extern __shared__ __align__(16) char smb[];
    float* s  = (float*)(smb + SMM_S);
    float* kt = (float*)(smb + SMM_KT);
    float* qs = (float*)(smb + SMM_QS);
    unsigned short* idxall = (unsigned short*)(smb + SMM_IDX);
    int* csall = (int*)(smb + SMM_CS);
    const int tid = threadIdx.x, lane = tid & 31, w = tid >> 5;
    const int qt = blockIdx.x & 15;
    const int bh = blockIdx.x >> 4;
    const int b = bh / Hh, h = bh % Hh;
    const int m0 = qt * TQS;
    #pragma unroll
    for (int i = tid; i < TQS*Dd; i += NTS){
        int r = i >> 6, d = i & 63;
        qs[i] = g_q[((size_t)bh*Nn + m0 + r)*Dd + d];
    }
    #pragma unroll
    for (int ph = 0; ph < 8; ph++){
        int idx = tid + ph*NTS;
        int r = idx >> 4, c4 = idx & 15;
        float4 kv = *(const float4*)&kmid[((size_t)bh*NM + r)*Dd + c4*4];
        kt[(c4*4+0)*KTP + r] = kv.x;
        kt[(c4*4+1)*KTP + r] = kv.y;
        kt[(c4*4+2)*KTP + r] = kv.z;
        kt[(c4*4+3)*KTP + r] = kv.w;
    }
    __syncthreads();
    {
        const int key = tid & 255, rg = (tid >> 8) * 8;
        float acc8[8];
        #pragma unroll
        for (int r = 0; r < 8; r++) acc8[r] = 0.f;
        const float4* qs4 = (const float4*)qs;
        #pragma unroll 2
        for (int i4 = 0; i4 < 16; i4++){
            float k0 = kt[(i4*4+0)*KTP + key];
            float k1 = kt[(i4*4+1)*KTP + key];
            float k2 = kt[(i4*4+2)*KTP + key];
            float k3 = kt[(i4*4+3)*KTP + key];
            #pragma unroll
            for (int r = 0; r < 8; r++){
                float4 q4 = qs4[(rg+r)*16 + i4];
                acc8[r] += k0*q4.x + k1*q4.y + k2*q4.z + k3*q4.w;
            }
        }
        #pragma unroll
        for (int r = 0; r < 8; r++)
            ((unsigned*)s)[(rg+r)*NM + key] = fkey(acc8[r]);
    }
    __syncthreads();
    float* sp = s + w*NM;
    unsigned* spk = (unsigned*)sp;
    unsigned kmax = 0;
    #pragma unroll
    for (int g = 0; g < NM/32; g++) kmax = max(kmax, spk[g*32 + lane]);
    #pragma unroll
    for (int off = 16; off; off >>= 1) kmax = max(kmax, __shfl_xor_sync(0xffffffffu, kmax, off));
    float Z = warp_topk<NM, KSEL_M, 8>(sp, idxall + w*KSEL_M, csall + w*2, kmax, lane);
    float invZ = 1.f / Z;
    __syncthreads();
    float* vsh = kt;
    #pragma unroll
    for (int ph = 0; ph < 8; ph++){
        int idx = tid + ph*NTS;
        int r = idx >> 4, c4 = idx & 15;
        *(float4*)&vsh[r*Dd + c4*4] = *(const float4*)&vmid[((size_t)bh*NM + r)*Dd + c4*4];
    }
    __syncthreads();
    float2 acc = {0.f, 0.f};
    const unsigned short* il = idxall + w*KSEL_M;
    #pragma unroll 4
    for (int n = 0; n < KSEL_M; n++){
        int j = il[n];
        float wgt = sp[j];
        float2 v2 = ((const float2*)&vsh[j*Dd])[lane];
        acc.x += wgt*v2.x; acc.y += wgt*v2.y;
    }
    float2 o = {acc.x*invZ, acc.y*invZ};
    ((float2*)&g_xo[((size_t)b*Nn + m0 + w)*Cc + h*Dd])[lane] = o;
}

// ---- streaming attention: 16 rows/block, 512 threads, reg-prefetch ----
#define SMS_S    0
#define SMS_KT   163840
#define SMS_QS   196864
#define SMS_CS   200960
#define SMS_IDX  202496
#define SMEM_S_TOT 222976

__global__ __launch_bounds__(NTS, 1)
void k_attn_s(const float* __restrict__ memk, const float* __restrict__ memv,
              const float* __restrict__ vmid){
    extern __shared__ __align__(16) char smb[];
    float* s  = (float*)(smb + SMS_S);
    float* kt = (float*)(smb + SMS_KT);
    float* qs = (float*)(smb + SMS_QS);
    int* csall = (int*)(smb + SMS_CS);
    unsigned short* idxall = (unsigned short*)(smb + SMS_IDX);
    const int tid = threadIdx.x, lane = tid & 31, w = tid >> 5;
    const int qt = blockIdx.x & 63;
    const int bh = blockIdx.x >> 6;
    const int b = bh / Hh, h = bh % Hh;
    const int nq0 = NM + qt*TQS;
    #pragma unroll
    for (int i = tid; i < TQS*Dd; i += NTS){
        int r = i >> 6, d = i & 63;
        qs[i] = g_q[((size_t)bh*Nn + nq0 + r)*Dd + d];
    }
    const int pr = tid >> 2;
    const int pco = (tid & 3) * 4;
    float4 pre[4];
    {
        const float* kr = &memk[((size_t)bh*MEMN + pr)*Dd];
        #pragma unroll
        for (int i = 0; i < 4; i++) pre[i] = ((const float4*)kr)[pco + i];
    }
    const int key = tid & 127, rbase = (tid >> 7) * 4;
    const float4* qs4 = (const float4*)qs;
    for (int ck = 0; ck < NCH; ck++){
        __syncthreads();
        #pragma unroll
        for (int i = 0; i < 4; i++){
            int c = (pco + i)*4;
            kt[(c+0)*KT2 + pr] = pre[i].x; kt[(c+1)*KT2 + pr] = pre[i].y;
            kt[(c+2)*KT2 + pr] = pre[i].z; kt[(c+3)*KT2 + pr] = pre[i].w;
        }
        __syncthreads();
        if (ck + 1 < NCH){
            int j = (ck+1)*CKS + pr;
            const float* kr = (j < MEMN) ? &memk[((size_t)bh*MEMN + j)*Dd]
                                         : &g_k[((size_t)bh*Nn + (j - MEMN))*Dd];
            #pragma unroll
            for (int i = 0; i < 4; i++) pre[i] = ((const float4*)kr)[pco + i];
        }
        float a0 = 0.f, a1 = 0.f, a2 = 0.f, a3 = 0.f;
        #pragma unroll 4
        for (int i4 = 0; i4 < 16; i4++){
            float k0 = kt[(i4*4+0)*KT2 + key];
            float k1 = kt[(i4*4+1)*KT2 + key];
            float k2 = kt[(i4*4+2)*KT2 + key];
            float k3 = kt[(i4*4+3)*KT2 + key];
            float4 qa = qs4[(rbase+0)*16 + i4];
            float4 qb = qs4[(rbase+1)*16 + i4];
            float4 qc = qs4[(rbase+2)*16 + i4];
            float4 qd = qs4[(rbase+3)*16 + i4];
            a0 += k0*qa.x + k1*qa.y + k2*qa.z + k3*qa.w;
            a1 += k0*qb.x + k1*qb.y + k2*qb.z + k3*qb.w;
            a2 += k0*qc.x + k1*qc.y + k2*qc.z + k3*qc.w;
            a3 += k0*qd.x + k1*qd.y + k2*qd.z + k3*qd.w;
        }
        unsigned* su = (unsigned*)s;
        su[(rbase+0)*LFULL + ck*CKS + key] = fkey(a0);
        su[(rbase+1)*LFULL + ck*CKS + key] = fkey(a1);
        su[(rbase+2)*LFULL + ck*CKS + key] = fkey(a2);
        su[(rbase+3)*LFULL + ck*CKS + key] = fkey(a3);
    }
    __syncthreads();
    float* sp = s + w*LFULL;
    unsigned* spk = (unsigned*)sp;
    int* cs = csall + w*24;
    unsigned short* il = idxall + w*KSEL_S;
    unsigned kmax = 0;
    for (int g = 0; g < LFULL/32; g++) kmax = max(kmax, spk[g*32 + lane]);
    #pragma unroll
    for (int off = 16; off; off >>= 1) kmax = max(kmax, __shfl_xor_sync(0xffffffffu, kmax, off));
    float Z = warp_topk<LFULL, KSEL_S, 4>(sp, il, cs, kmax, lane);
    float invZ = 1.f / Z;
    float* vsh = kt;
    {
        const float* vr = &memv[((size_t)bh*MEMN + pr)*Dd];
        #pragma unroll
        for (int i = 0; i < 4; i++) pre[i] = ((const float4*)vr)[pco + i];
    }
    float2 acc = {0.f, 0.f};
    for (int ck = 0; ck < NCH; ck++){
        __syncthreads();
        #pragma unroll
        for (int i = 0; i < 4; i++)
            *(float4*)&vsh[pr*Dd + (pco + i)*4] = pre[i];
        __syncthreads();
        if (ck + 1 < NCH){
            int j = (ck+1)*CKS + pr;
            const float* vr;
            if (j < MEMN)            vr = &memv[((size_t)bh*MEMN + j)*Dd];
            else if (j < MEMN + NM)  vr = &vmid[((size_t)bh*NM + (j - MEMN))*Dd];
            else                     vr = &g_v[((size_t)bh*Nn + (j - MEMN))*Dd];
            #pragma unroll
            for (int i = 0; i < 4; i++) pre[i] = ((const float4*)vr)[pco + i];
        }
        const int nb = cs[ck], ne = cs[ck+1], jb = ck*CKS;
        #pragma unroll 4
        for (int n = nb; n < ne; n++){
            int j = il[n];
            float wgt = sp[j];
            float2 v2 = ((const float2*)&vsh[(j - jb)*Dd])[lane];
            acc.x += wgt*v2.x; acc.y += wgt*v2.y;
        }
    }
    float2 o = {acc.x*invZ, acc.y*invZ};
    ((float2*)&g_xo[((size_t)b*Nn + nq0 + w)*Cc + h*Dd])[lane] = o;
}

// ---- route softmax + proj lows, 8 rows per block ----
__global__ void k_route(const float* __restrict__ routeW, const float* __restrict__ projA){
    __shared__ float xs[8*Cc];
    __shared__ float lg[8][4], pl[8][32], sm[8][4];
    const int tid = threadIdx.x;
    const int m0 = blockIdx.x * 8;
    for (int i = tid; i < 8*Cc; i += NT) xs[i] = g_xo[(size_t)m0*Cc + i];
    __syncthreads();
    const int warp = tid >> 5, lane = tid & 31;
    for (int o = warp; o < 36; o += 8){
        const float* a = (o < 4) ? &routeW[o*Cc] : &projA[(o - 4)*Cc];
        float acc[8];
        #pragma unroll
        for (int r = 0; r < 8; r++) acc[r] = 0.f;
        for (int i = lane; i < Cc; i += 32){
            float av = a[i];
            #pragma unroll
            for (int r = 0; r < 8; r++) acc[r] += xs[r*Cc + i] * av;
        }
        #pragma unroll
        for (int r = 0; r < 8; r++){
            float p = acc[r];
            #pragma unroll
            for (int off = 16; off; off >>= 1) p += __shfl_xor_sync(0xffffffffu, p, off);
            if (lane == 0){
                if (o < 4) lg[r][o] = p;
                else       pl[r][o - 4] = p;
            }
        }
    }
    __syncthreads();
    if (tid < 8){
        int r = tid;
        float mx = fmaxf(fmaxf(lg[r][0], lg[r][1]), fmaxf(lg[r][2], lg[r][3]));
        float e0 = __expf(lg[r][0]-mx), e1 = __expf(lg[r][1]-mx);
        float e2 = __expf(lg[r][2]-mx), e3 = __expf(lg[r][3]-mx);
        float si = 1.f / (e0 + e1 + e2 + e3);
        sm[r][0] = e0*si; sm[r][1] = e1*si; sm[r][2] = e2*si; sm[r][3] = e3*si;
    }
    __syncthreads();
    {
        int r = tid >> 5, t = tid & 31;
        g_wplow[(m0 + r)*32 + t] = sm[r][t >> 3] * pl[r][t] * 0.125f;
    }
}

__global__ void k_sgemm_proj(const float* __restrict__ W, const float* __restrict__ bp,
                             const float* __restrict__ projB, float* __restrict__ out){
    SGEMM_MAIN(g_xo, W, Cc)
    #pragma unroll
    for (int ii = 0; ii < 4; ii++){
        const int m = row0 + ty*4 + ii;
        float wl[32];
        #pragma unroll
        for (int t = 0; t < 32; t++) wl[t] = g_wplow[m*32 + t];
        #pragma unroll
        for (int jj = 0; jj < 4; jj++){
            const int c = col0 + tx*4 + jj;
            float lora = 0.f;
            #pragma unroll
            for (int e = 0; e < 4; e++){
                const float* bv = &projB[(e*Cc + c)*8];
                #pragma unroll
                for (int r = 0; r < 8; r++) lora += wl[e*8 + r] * bv[r];
            }
            out[m*Cc + c] = acc[ii][jj] + bp[c] + lora;
        }
    }
}

extern "C" void kernel_launch(void* const* d_in, const int* in_sizes, int n_in,
                              void* d_out, int out_size){
    const float* x      = (const float*)d_in[0];
    const float* idt    = (const float*)d_in[1];
    const float* memk   = (const float*)d_in[2];
    const float* memv   = (const float*)d_in[3];
    const float* Wqkv   = (const float*)d_in[4];
    const float* bqkv   = (const float*)d_in[5];
    const float* qkvA   = (const float*)d_in[6];
    const float* qkvB   = (const float*)d_in[7];
    const float* Wproj  = (const float*)d_in[8];
    const float* bproj  = (const float*)d_in[9];
    const float* routeW = (const float*)d_in[10];
    const float* projA  = (const float*)d_in[11];
    const float* projB  = (const float*)d_in[12];
    const float* Widk   = (const float*)d_in[13];
    const float* bidk   = (const float*)d_in[14];
    const float* idkA   = (const float*)d_in[15];
    const float* idkB   = (const float*)d_in[16];
    const float* Widv   = (const float*)d_in[17];
    const float* bidv   = (const float*)d_in[18];
    const float* idvA   = (const float*)d_in[19];
    const float* idvB   = (const float*)d_in[20];

    float* out  = (float*)d_out;
    float* kmid = out + Bb*Nn*Cc;
    float* vmid = kmid + Bb*Hh*NM*Dd;

    static int init = 0;
    if (!init){
        cudaFuncSetAttribute(k_attn_m, cudaFuncAttributeMaxDynamicSharedMemorySize, SMEM_M_TOT);
        cudaFuncSetAttribute(k_attn_s, cudaFuncAttributeMaxDynamicSharedMemorySize, SMEM_S_TOT);
        init = 1;
    }

    k_qkv_low<<<Bb*Nn/8, NT>>>(x, qkvA);
    k_sgemm_qkv<<<dim3(36, 80), NT>>>(x, Wqkv, bqkv, qkvB);
    k_id_small<<<Bb*NM, NT>>>(idt, idkA, idvA, Widk, bidk, idkB);
    k_sgemm_idv<<<dim3(12, 16), NT>>>(idt, Widv, bidv, idvB);
    k_apply_id<<<(Bb*Hh*NM*Dd)/NT, NT>>>(kmid, vmid);
    k_attn_m<<<Bb*Hh*NM/TQS, NTS, SMEM_M_TOT>>>(kmid, vmid);
    k_attn_s<<<Bb*Hh*NSd/TQS, NTS, SMEM_S_TOT>>>(memk, memv, vmid);
    k_route<<<Bb*Nn/8, NT>>>(routeW, projA);
    k_sgemm_proj<<<dim3(12, 80), NT>>>(Wproj, bproj, projB, out);
}

// round 8
// speedup vs baseline: 2.5437x; 1.0929x over previous
#include <cuda_runtime.h>

#define Bb 4
#define Nn 1280
#define NM 256
#define NSd 1024
#define Cc 768
#define Hh 12
#define Dd 64
#define MEMN 1280
#define LFULL 2560
#define KSEL_S 640
#define KSEL_M 128
#define NT 256
#define NTS 512
#define TQS 16
#define KTP 257
#define KT2 129
#define CKS 128
#define NCH 20

__device__ float g_q[Bb*Hh*Nn*Dd];
__device__ float g_k[Bb*Hh*Nn*Dd];
__device__ float g_v[Bb*Hh*Nn*Dd];
__device__ float g_qkvlow[Bb*Nn*24];
__device__ float g_idvlow[Bb*NM*8];
__device__ float g_act[Bb*NM*Hh];
__device__ float g_idv[Bb*NM*Cc];
__device__ float g_xo[Bb*Nn*Cc];
__device__ float g_wplow[Bb*Nn*32];

__device__ __forceinline__ unsigned fkey(float f){
    unsigned b = __float_as_uint(f);
    return (b & 0x80000000u) ? ~b : (b | 0x80000000u);
}
__device__ __forceinline__ float inv_fkey(unsigned k){
    return (k & 0x80000000u) ? __uint_as_float(k ^ 0x80000000u)
                             : __uint_as_float(~k);
}

// Warp-synchronous exact top-K + softmax (keys pre-converted; early-exit radix).
template<int L, int KS, int GPC>
__device__ float warp_topk(float* sp, unsigned short* idxl, int* cs,
                           unsigned maxkey, int lane){
    const unsigned FULL = 0xffffffffu;
    unsigned* spk = (unsigned*)sp;
    const int G = L/32;
    const float vmax = inv_fkey(maxkey);
    unsigned prefix = 0; int need = KS;
    const int SH[7] = {27,22,17,12,7,2,0};
    const int NB[7] = {5,5,5,5,5,5,2};
    #pragma unroll
    for (int p = 0; p < 7; p++){
        const int shift = SH[p], nb = NB[p];
        const unsigned Bm = (1u << nb) - 1u;
        const unsigned maskhi = (p == 0) ? 0u : ~((1u << (shift + nb)) - 1u);
        unsigned cnt = 0;
        for (int g = 0; g < G; g++){
            unsigned key = spk[g*32 + lane];
            bool act = ((key & maskhi) == prefix);
            unsigned wv = (key >> shift) & Bm;
            unsigned mact = __ballot_sync(FULL, act);
            unsigned m0 = __ballot_sync(FULL, wv & 1);
            unsigned m1 = __ballot_sync(FULL, wv & 2);
            unsigned sel = mact & ((lane & 1) ? m0 : ~m0)
                                & ((lane & 2) ? m1 : ~m1);
            if (nb == 5){
                unsigned m2 = __ballot_sync(FULL, wv & 4);
                unsigned m3 = __ballot_sync(FULL, wv & 8);
                unsigned m4 = __ballot_sync(FULL, wv & 16);
                sel &= (lane & 4) ? m2 : ~m2;
                sel &= (lane & 8) ? m3 : ~m3;
                sel &= (lane & 16) ? m4 : ~m4;
            }
            cnt += __popc(sel);
        }
        if ((unsigned)lane > Bm) cnt = 0;
        unsigned run = cnt;
        #pragma unroll
        for (int off = 1; off < 32; off <<= 1){
            unsigned v = __shfl_down_sync(FULL, run, off);
            if (lane + off < 32) run += v;
        }
        unsigned gt = run - cnt;
        bool isthr = ((int)run >= need) && ((int)gt < need);
        unsigned mthr = __ballot_sync(FULL, isthr);
        int tl = __ffs(mthr) - 1;
        unsigned gtt = __shfl_sync(FULL, gt, tl);
        need -= (int)gtt;
        prefix |= ((unsigned)tl) << shift;
        unsigned cb = __shfl_sync(FULL, cnt, tl);
        if ((int)cb == need) break;
    }
    const unsigned thr = prefix;
    int tieacc = 0, nsel = 0; float lsum = 0.f;
    for (int g = 0; g < G; g++){
        if ((g % GPC) == 0 && lane == 0) cs[g / GPC] = nsel;
        int j = g*32 + lane;
        unsigned key = spk[j];
        bool eq = (key == thr);
        unsigned eqm = __ballot_sync(FULL, eq);
        bool selb = (key > thr) || (eq && (tieacc + __popc(eqm & ((1u<<lane)-1u))) < need);
        tieacc += __popc(eqm);
        float v = inv_fkey(key);
        float e = selb ? __expf(v - vmax) : 0.f;
        sp[j] = e; lsum += e;
        unsigned sm = __ballot_sync(FULL, selb);
        if (selb) idxl[nsel + __popc(sm & ((1u<<lane)-1u))] = (unsigned short)j;
        nsel += __popc(sm);
    }
    if (lane == 0) cs[G / GPC] = KS;
    #pragma unroll
    for (int off = 16; off; off >>= 1) lsum += __shfl_xor_sync(FULL, lsum, off);
    return lsum;
}

// ---- qkv lora low, 8 rows per block ----
__global__ void k_qkv_low(const float* __restrict__ x, const float* __restrict__ qkvA){
    __shared__ float xs[8*Cc];
    const int tid = threadIdx.x;
    const int m0 = blockIdx.x * 8;
    for (int i = tid; i < 8*Cc; i += NT) xs[i] = x[(size_t)m0*Cc + i];
    __syncthreads();
    const int warp = tid >> 5, lane = tid & 31;
    for (int o = warp; o < 24; o += 8){
        const float* a = &qkvA[o*Cc];
        float acc[8];
        #pragma unroll
        for (int r = 0; r < 8; r++) acc[r] = 0.f;
        for (int i = lane; i < Cc; i += 32){
            float av = a[i];
            #pragma unroll
            for (int r = 0; r < 8; r++) acc[r] += xs[r*Cc + i] * av;
        }
        #pragma unroll
        for (int r = 0; r < 8; r++){
            float p = acc[r];
            #pragma unroll
            for (int off = 16; off; off >>= 1) p += __shfl_xor_sync(0xffffffffu, p, off);
            if (lane == 0) g_qkvlow[(m0 + r)*24 + o] = p;
        }
    }
}

// ---- 128x128x8 double-buffered SGEMM mainloop ----
#define SG128_COMP(STG)                                                           \
    _Pragma("unroll")                                                             \
    for (int kk = 0; kk < 8; kk++){                                               \
        float4 ra0 = *(const float4*)&As[STG][kk*128 + ty*4];                     \
        float4 ra1 = *(const float4*)&As[STG][kk*128 + 64 + ty*4];                \
        float4 rb0 = *(const float4*)&Ws[STG][kk*128 + tx*4];                     \
        float4 rb1 = *(const float4*)&Ws[STG][kk*128 + 64 + tx*4];                \
        float av_[8] = {ra0.x,ra0.y,ra0.z,ra0.w,ra1.x,ra1.y,ra1.z,ra1.w};         \
        float bw_[8] = {rb0.x,rb0.y,rb0.z,rb0.w,rb1.x,rb1.y,rb1.z,rb1.w};         \
        _Pragma("unroll") for (int i_ = 0; i_ < 8; i_++)                          \
        _Pragma("unroll") for (int j_ = 0; j_ < 8; j_++)                          \
            acc[i_][j_] += av_[i_] * bw_[j_];                                     \
    }

#define SG128_STORE(STG)                                                          \
    As[STG][(lc+0)*128 + lr] = pa.x; As[STG][(lc+1)*128 + lr] = pa.y;             \
    As[STG][(lc+2)*128 + lr] = pa.z; As[STG][(lc+3)*128 + lr] = pa.w;             \
    Ws[STG][(lc+0)*128 + lr] = pw.x; Ws[STG][(lc+1)*128 + lr] = pw.y;             \
    Ws[STG][(lc+2)*128 + lr] = pw.z; Ws[STG][(lc+3)*128 + lr] = pw.w;

#define SG128_MAIN(Aptr, Wptr, KDIM)                                              \
    __shared__ __align__(16) float As[2][8*128];                                  \
    __shared__ __align__(16) float Ws[2][8*128];                                  \
    float acc[8][8];                                                              \
    _Pragma("unroll") for (int i_ = 0; i_ < 8; i_++)                              \
    _Pragma("unroll") for (int j_ = 0; j_ < 8; j_++) acc[i_][j_] = 0.f;           \
    const int tid = threadIdx.x;                                                  \
    const int ty = tid >> 4, tx = tid & 15;                                       \
    const int lr = tid >> 1, lc = (tid & 1)*4;                                    \
    const int row0 = blockIdx.y*128, col0 = blockIdx.x*128;                       \
    const float* Ag = &Aptr[(size_t)(row0 + lr)*KDIM + lc];                       \
    const float* Wg = &Wptr[(size_t)(col0 + lr)*KDIM + lc];                       \
    float4 pa = *(const float4*)Ag;                                               \
    float4 pw = *(const float4*)Wg;                                               \
    int stg = 0;                                                                  \
    SG128_STORE(0)                                                                \
    __syncthreads();                                                              \
    for (int kt = 8; kt < KDIM; kt += 8){                                         \
        float4 na = *(const float4*)(Ag + kt);                                    \
        float4 nw = *(const float4*)(Wg + kt);                                    \
        SG128_COMP(stg)                                                           \
        pa = na; pw = nw;                                                         \
        { const int so = stg ^ 1; SG128_STORE(so) }                               \
        __syncthreads();                                                          \
        stg ^= 1;                                                                 \
    }                                                                             \
    SG128_COMP(stg)

__global__ __launch_bounds__(NT, 2)
void k_sgemm_qkv(const float* __restrict__ x, const float* __restrict__ W,
                 const float* __restrict__ bq, const float* __restrict__ qkvB){
    SG128_MAIN(x, W, Cc)
    const int g = col0 / Cc;
    #pragma unroll
    for (int ii = 0; ii < 8; ii++){
        const int m = row0 + ty*4 + (ii & 3) + (ii >> 2)*64;
        const int b = m / Nn, n = m % Nn;
        float lw[8];
        #pragma unroll
        for (int r = 0; r < 8; r++) lw[r] = g_qkvlow[m*24 + g*8 + r];
        #pragma unroll
        for (int jh = 0; jh < 2; jh++){
            float vv[4];
            #pragma unroll
            for (int q = 0; q < 4; q++){
                const int j = col0 + jh*64 + tx*4 + q;
                const int c = j - g*Cc;
                const float* bv = &qkvB[(g*Cc + c)*8];
                float lora = 0.f;
                #pragma unroll
                for (int r = 0; r < 8; r++) lora += lw[r] * bv[r];
                vv[q] = acc[ii][jh*4 + q] + bq[j] + 0.125f * lora;
            }
            const int c0 = col0 + jh*64 + tx*4 - g*Cc;
            const int h = c0 >> 6, d = c0 & 63;
            const size_t dst = ((size_t)(b*Hh + h)*Nn + n)*Dd + d;
            if (g == 0){
                float4 o = {vv[0]*0.125f, vv[1]*0.125f, vv[2]*0.125f, vv[3]*0.125f};
                *(float4*)&g_q[dst] = o;
            } else if (g == 1){
                float4 o = {vv[0], vv[1], vv[2], vv[3]};
                *(float4*)&g_k[dst] = o;
            } else {
                float4 o = {vv[0], vv[1], vv[2], vv[3]};
                *(float4*)&g_v[dst] = o;
            }
        }
    }
}

__global__ void k_id_small(const float* __restrict__ idt, const float* __restrict__ idkA,
                           const float* __restrict__ idvA, const float* __restrict__ Widk,
                           const float* __restrict__ bidk, const float* __restrict__ idkB){
    const int row = blockIdx.x;
    const int tid = threadIdx.x;
    __shared__ float xs[Cc];
    __shared__ float lk[8], dk[12];
    for (int i = tid; i < Cc; i += NT) xs[i] = idt[row*Cc + i];
    __syncthreads();
    const int warp = tid >> 5, lane = tid & 31;
    for (int o = warp; o < 28; o += 8){
        const float* a;
        if (o < 8)       a = &idkA[o*Cc];
        else if (o < 16) a = &idvA[(o - 8)*Cc];
        else             a = &Widk[(o - 16)*Cc];
        float p = 0.f;
        for (int i = lane; i < Cc; i += 32) p += xs[i] * a[i];
        #pragma unroll
        for (int off = 16; off; off >>= 1) p += __shfl_xor_sync(0xffffffffu, p, off);
        if (lane == 0){
            if (o < 8)       lk[o] = p;
            else if (o < 16) g_idvlow[row*8 + (o - 8)] = p;
            else             dk[o - 16] = p;
        }
    }
    __syncthreads();
    if (tid < 12){
        float lo = 0.f;
        #pragma unroll
        for (int r = 0; r < 8; r++) lo += lk[r] * idkB[tid*8 + r];
        float f = dk[tid] + bidk[tid] + 0.125f * lo;
        g_act[row*Hh + tid] = 1.f + tanhf(f);
    }
}

__global__ __launch_bounds__(NT, 2)
void k_sgemm_idv(const float* __restrict__ idt, const float* __restrict__ W,
                 const float* __restrict__ bidv, const float* __restrict__ idvB){
    SG128_MAIN(idt, W, Cc)
    #pragma unroll
    for (int ii = 0; ii < 8; ii++){
        const int m = row0 + ty*4 + (ii & 3) + (ii >> 2)*64;
        float lw[8];
        #pragma unroll
        for (int r = 0; r < 8; r++) lw[r] = g_idvlow[m*8 + r];
        #pragma unroll
        for (int jh = 0; jh < 2; jh++){
            float vv[4];
            #pragma unroll
            for (int q = 0; q < 4; q++){
                const int c = col0 + jh*64 + tx*4 + q;
                const float* bv = &idvB[c*8];
                float lora = 0.f;
                #pragma unroll
                for (int r = 0; r < 8; r++) lora += lw[r] * bv[r];
                vv[q] = acc[ii][jh*4 + q] + bidv[c] + 0.125f * lora;
            }
            const int c0 = col0 + jh*64 + tx*4;
            float4 o = {vv[0], vv[1], vv[2], vv[3]};
            *(float4*)&g_idv[(size_t)m*Cc + c0] = o;
        }
    }
}

__global__ void k_apply_id(float* __restrict__ kmid, float* __restrict__ vmid){
    const int idx = blockIdx.x * NT + threadIdx.x;
    const int d = idx & 63;
    int t = idx >> 6;
    const int m = t % NM; t /= NM;
    const int h = t % Hh; const int b = t / Hh;
    const int src = ((b*Hh + h)*Nn + m)*Dd + d;
    kmid[idx] = g_k[src] * g_act[(b*NM + m)*Hh + h];
    vmid[idx] = g_v[src] + g_idv[(b*NM + m)*Cc + h*Dd + d];
}

// ---- mem attention: 16 rows/block, 512 threads ----
#define SMM_S    0
#define SMM_KT   16384
#define SMM_QS   82176
#define SMM_IDX  86272
#define SMM_CS   90368
#define SMEM_M_TOT 90496

__global__ __launch_bounds__(NTS, 2)
void k_attn_m(const float* __restrict__ kmid, const float* __restrict__ vmid){
    extern __shared__ __align__(16) char smb[];
    float* s  = (float*)(smb + SMM_S);
    float* kt = (float*)(smb + SMM_KT);
    float* qs = (float*)(smb + SMM_QS);
    unsigned short* idxall = (unsigned short*)(smb + SMM_IDX);
    int* csall = (int*)(smb + SMM_CS);
    const int tid = threadIdx.x, lane = tid & 31, w = tid >> 5;
    const int qt = blockIdx.x & 15;
    const int bh = blockIdx.x >> 4;
    const int b = bh / Hh, h = bh % Hh;
    const int m0 = qt * TQS;
    #pragma unroll
    for (int i = tid; i < TQS*Dd; i += NTS){
        int r = i >> 6, d = i & 63;
        qs[i] = g_q[((size_t)bh*Nn + m0 + r)*Dd + d];
    }
    #pragma unroll
    for (int ph = 0; ph < 8; ph++){
        int idx = tid + ph*NTS;
        int r = idx >> 4, c4 = idx & 15;
        float4 kv = *(const float4*)&kmid[((size_t)bh*NM + r)*Dd + c4*4];
        kt[(c4*4+0)*KTP + r] = kv.x;
        kt[(c4*4+1)*KTP + r] = kv.y;
        kt[(c4*4+2)*KTP + r] = kv.z;
        kt[(c4*4+3)*KTP + r] = kv.w;
    }
    __syncthreads();
    {
        const int key = tid & 255, rg = (tid >> 8) * 8;
        float acc8[8];
        #pragma unroll
        for (int r = 0; r < 8; r++) acc8[r] = 0.f;
        const float4* qs4 = (const float4*)qs;
        #pragma unroll 2
        for (int i4 = 0; i4 < 16; i4++){
            float k0 = kt[(i4*4+0)*KTP + key];
            float k1 = kt[(i4*4+1)*KTP + key];
            float k2 = kt[(i4*4+2)*KTP + key];
            float k3 = kt[(i4*4+3)*KTP + key];
            #pragma unroll
            for (int r = 0; r < 8; r++){
                float4 q4 = qs4[(rg+r)*16 + i4];
                acc8[r] += k0*q4.x + k1*q4.y + k2*q4.z + k3*q4.w;
            }
        }
        #pragma unroll
        for (int r = 0; r < 8; r++)
            ((unsigned*)s)[(rg+r)*NM + key] = fkey(acc8[r]);
    }
    __syncthreads();
    float* sp = s + w*NM;
    unsigned* spk = (unsigned*)sp;
    unsigned kmax = 0;
    #pragma unroll
    for (int g = 0; g < NM/32; g++) kmax = max(kmax, spk[g*32 + lane]);
    #pragma unroll
    for (int off = 16; off; off >>= 1) kmax = max(kmax, __shfl_xor_sync(0xffffffffu, kmax, off));
    float Z = warp_topk<NM, KSEL_M, 8>(sp, idxall + w*KSEL_M, csall + w*2, kmax, lane);
    float invZ = 1.f / Z;
    __syncthreads();
    float* vsh = kt;
    #pragma unroll
    for (int ph = 0; ph < 8; ph++){
        int idx = tid + ph*NTS;
        int r = idx >> 4, c4 = idx & 15;
        *(float4*)&vsh[r*Dd + c4*4] = *(const float4*)&vmid[((size_t)bh*NM + r)*Dd + c4*4];
    }
    __syncthreads();
    float2 acc = {0.f, 0.f};
    const unsigned short* il = idxall + w*KSEL_M;
    #pragma unroll 4
    for (int n = 0; n < KSEL_M; n++){
        int j = il[n];
        float wgt = sp[j];
        float2 v2 = ((const float2*)&vsh[j*Dd])[lane];
        acc.x += wgt*v2.x; acc.y += wgt*v2.y;
    }
    float2 o = {acc.x*invZ, acc.y*invZ};
    ((float2*)&g_xo[((size_t)b*Nn + m0 + w)*Cc + h*Dd])[lane] = o;
}

// ---- streaming attention: 16 rows/block, 512 threads, reg-prefetch ----
#define SMS_S    0
#define SMS_KT   163840
#define SMS_QS   196864
#define SMS_CS   200960
#define SMS_IDX  202496
#define SMEM_S_TOT 222976

__global__ __launch_bounds__(NTS, 1)
void k_attn_s(const float* __restrict__ memk, const float* __restrict__ memv,
              const float* __restrict__ vmid){
    extern __shared__ __align__(16) char smb[];
    float* s  = (float*)(smb + SMS_S);
    float* kt = (float*)(smb + SMS_KT);
    float* qs = (float*)(smb + SMS_QS);
    int* csall = (int*)(smb + SMS_CS);
    unsigned short* idxall = (unsigned short*)(smb + SMS_IDX);
    const int tid = threadIdx.x, lane = tid & 31, w = tid >> 5;
    const int qt = blockIdx.x & 63;
    const int bh = blockIdx.x >> 6;
    const int b = bh / Hh, h = bh % Hh;
    const int nq0 = NM + qt*TQS;
    #pragma unroll
    for (int i = tid; i < TQS*Dd; i += NTS){
        int r = i >> 6, d = i & 63;
        qs[i] = g_q[((size_t)bh*Nn + nq0 + r)*Dd + d];
    }
    const int pr = tid >> 2;
    const int pco = (tid & 3) * 4;
    float4 pre[4];
    {
        const float* kr = &memk[((size_t)bh*MEMN + pr)*Dd];
        #pragma unroll
        for (int i = 0; i < 4; i++) pre[i] = ((const float4*)kr)[pco + i];
    }
    const int key = tid & 127, rbase = (tid >> 7) * 4;
    const float4* qs4 = (const float4*)qs;
    for (int ck = 0; ck < NCH; ck++){
        __syncthreads();
        #pragma unroll
        for (int i = 0; i < 4; i++){
            int c = (pco + i)*4;
            kt[(c+0)*KT2 + pr] = pre[i].x; kt[(c+1)*KT2 + pr] = pre[i].y;
            kt[(c+2)*KT2 + pr] = pre[i].z; kt[(c+3)*KT2 + pr] = pre[i].w;
        }
        __syncthreads();
        if (ck + 1 < NCH){
            int j = (ck+1)*CKS + pr;
            const float* kr = (j < MEMN) ? &memk[((size_t)bh*MEMN + j)*Dd]
                                         : &g_k[((size_t)bh*Nn + (j - MEMN))*Dd];
            #pragma unroll
            for (int i = 0; i < 4; i++) pre[i] = ((const float4*)kr)[pco + i];
        }
        float a0 = 0.f, a1 = 0.f, a2 = 0.f, a3 = 0.f;
        #pragma unroll 4
        for (int i4 = 0; i4 < 16; i4++){
            float k0 = kt[(i4*4+0)*KT2 + key];
            float k1 = kt[(i4*4+1)*KT2 + key];
            float k2 = kt[(i4*4+2)*KT2 + key];
            float k3 = kt[(i4*4+3)*KT2 + key];
            float4 qa = qs4[(rbase+0)*16 + i4];
            float4 qb = qs4[(rbase+1)*16 + i4];
            float4 qc = qs4[(rbase+2)*16 + i4];
            float4 qd = qs4[(rbase+3)*16 + i4];
            a0 += k0*qa.x + k1*qa.y + k2*qa.z + k3*qa.w;
            a1 += k0*qb.x + k1*qb.y + k2*qb.z + k3*qb.w;
            a2 += k0*qc.x + k1*qc.y + k2*qc.z + k3*qc.w;
            a3 += k0*qd.x + k1*qd.y + k2*qd.z + k3*qd.w;
        }
        unsigned* su = (unsigned*)s;
        su[(rbase+0)*LFULL + ck*CKS + key] = fkey(a0);
        su[(rbase+1)*LFULL + ck*CKS + key] = fkey(a1);
        su[(rbase+2)*LFULL + ck*CKS + key] = fkey(a2);
        su[(rbase+3)*LFULL + ck*CKS + key] = fkey(a3);
    }
    __syncthreads();
    float* sp = s + w*LFULL;
    unsigned* spk = (unsigned*)sp;
    int* cs = csall + w*24;
    unsigned short* il = idxall + w*KSEL_S;
    unsigned kmax = 0;
    for (int g = 0; g < LFULL/32; g++) kmax = max(kmax, spk[g*32 + lane]);
    #pragma unroll
    for (int off = 16; off; off >>= 1) kmax = max(kmax, __shfl_xor_sync(0xffffffffu, kmax, off));
    float Z = warp_topk<LFULL, KSEL_S, 4>(sp, il, cs, kmax, lane);
    float invZ = 1.f / Z;
    // V phase: 2 selected keys per iteration (half-warps), float4 lanes
    float* vsh = kt;
    {
        const float* vr = &memv[((size_t)bh*MEMN + pr)*Dd];
        #pragma unroll
        for (int i = 0; i < 4; i++) pre[i] = ((const float4*)vr)[pco + i];
    }
    const int hl = lane >> 4, ll = lane & 15;
    float4 acc4 = {0.f, 0.f, 0.f, 0.f};
    for (int ck = 0; ck < NCH; ck++){
        __syncthreads();
        #pragma unroll
        for (int i = 0; i < 4; i++)
            *(float4*)&vsh[pr*Dd + (pco + i)*4] = pre[i];
        __syncthreads();
        if (ck + 1 < NCH){
            int j = (ck+1)*CKS + pr;
            const float* vr;
            if (j < MEMN)            vr = &memv[((size_t)bh*MEMN + j)*Dd];
            else if (j < MEMN + NM)  vr = &vmid[((size_t)bh*NM + (j - MEMN))*Dd];
            else                     vr = &g_v[((size_t)bh*Nn + (j - MEMN))*Dd];
            #pragma unroll
            for (int i = 0; i < 4; i++) pre[i] = ((const float4*)vr)[pco + i];
        }
        const int nb = cs[ck], ne = cs[ck+1], jb = ck*CKS;
        for (int n = nb; n < ne; n += 2){
            int j0 = il[n];
            int j1 = (n + 1 < ne) ? il[n+1] : j0;
            int jj = hl ? j1 : j0;
            float wgt = sp[jj];
            if (hl && (n + 1 >= ne)) wgt = 0.f;
            float4 v4 = *(const float4*)&vsh[(jj - jb)*Dd + ll*4];
            acc4.x += wgt*v4.x; acc4.y += wgt*v4.y;
            acc4.z += wgt*v4.z; acc4.w += wgt*v4.w;
        }
    }
    acc4.x += __shfl_xor_sync(0xffffffffu, acc4.x, 16);
    acc4.y += __shfl_xor_sync(0xffffffffu, acc4.y, 16);
    acc4.z += __shfl_xor_sync(0xffffffffu, acc4.z, 16);
    acc4.w += __shfl_xor_sync(0xffffffffu, acc4.w, 16);
    if (lane < 16){
        float4 o = {acc4.x*invZ, acc4.y*invZ, acc4.z*invZ, acc4.w*invZ};
        *(float4*)&g_xo[((size_t)b*Nn + nq0 + w)*Cc + h*Dd + ll*4] = o;
    }
}

// ---- route softmax + proj lows, 8 rows per block ----
__global__ void k_route(const float* __restrict__ routeW, const float* __restrict__ projA){
    __shared__ float xs[8*Cc];
    __shared__ float lg[8][4], pl[8][32], sm[8][4];
    const int tid = threadIdx.x;
    const int m0 = blockIdx.x * 8;
    for (int i = tid; i < 8*Cc; i += NT) xs[i] = g_xo[(size_t)m0*Cc + i];
    __syncthreads();
    const int warp = tid >> 5, lane = tid & 31;
    for (int o = warp; o < 36; o += 8){
        const float* a = (o < 4) ? &routeW[o*Cc] : &projA[(o - 4)*Cc];
        float acc[8];
        #pragma unroll
        for (int r = 0; r < 8; r++) acc[r] = 0.f;
        for (int i = lane; i < Cc; i += 32){
            float av = a[i];
            #pragma unroll
            for (int r = 0; r < 8; r++) acc[r] += xs[r*Cc + i] * av;
        }
        #pragma unroll
        for (int r = 0; r < 8; r++){
            float p = acc[r];
            #pragma unroll
            for (int off = 16; off; off >>= 1) p += __shfl_xor_sync(0xffffffffu, p, off);
            if (lane == 0){
                if (o < 4) lg[r][o] = p;
                else       pl[r][o - 4] = p;
            }
        }
    }
    __syncthreads();
    if (tid < 8){
        int r = tid;
        float mx = fmaxf(fmaxf(lg[r][0], lg[r][1]), fmaxf(lg[r][2], lg[r][3]));
        float e0 = __expf(lg[r][0]-mx), e1 = __expf(lg[r][1]-mx);
        float e2 = __expf(lg[r][2]-mx), e3 = __expf(lg[r][3]-mx);
        float si = 1.f / (e0 + e1 + e2 + e3);
        sm[r][0] = e0*si; sm[r][1] = e1*si; sm[r][2] = e2*si; sm[r][3] = e3*si;
    }
    __syncthreads();
    {
        int r = tid >> 5, t = tid & 31;
        g_wplow[(m0 + r)*32 + t] = sm[r][t >> 3] * pl[r][t] * 0.125f;
    }
}

__global__ __launch_bounds__(NT, 2)
void k_sgemm_proj(const float* __restrict__ W, const float* __restrict__ bp,
                  const float* __restrict__ projB, float* __restrict__ out){
    SG128_MAIN(g_xo, W, Cc)
    #pragma unroll
    for (int ii = 0; ii < 8; ii++){
        const int m = row0 + ty*4 + (ii & 3) + (ii >> 2)*64;
        float wl[32];
        #pragma unroll
        for (int t = 0; t < 32; t++) wl[t] = g_wplow[m*32 + t];
        #pragma unroll
        for (int jh = 0; jh < 2; jh++){
            float vv[4];
            #pragma unroll
            for (int q = 0; q < 4; q++){
                const int c = col0 + jh*64 + tx*4 + q;
                float lora = 0.f;
                #pragma unroll
                for (int e = 0; e < 4; e++){
                    const float* bv = &projB[(e*Cc + c)*8];
                    #pragma unroll
                    for (int r = 0; r < 8; r++) lora += wl[e*8 + r] * bv[r];
                }
                vv[q] = acc[ii][jh*4 + q] + bp[c] + lora;
            }
            const int c0 = col0 + jh*64 + tx*4;
            float4 o = {vv[0], vv[1], vv[2], vv[3]};
            *(float4*)&out[(size_t)m*Cc + c0] = o;
        }
    }
}

extern "C" void kernel_launch(void* const* d_in, const int* in_sizes, int n_in,
                              void* d_out, int out_size){
    const float* x      = (const float*)d_in[0];
    const float* idt    = (const float*)d_in[1];
    const float* memk   = (const float*)d_in[2];
    const float* memv   = (const float*)d_in[3];
    const float* Wqkv   = (const float*)d_in[4];
    const float* bqkv   = (const float*)d_in[5];
    const float* qkvA   = (const float*)d_in[6];
    const float* qkvB   = (const float*)d_in[7];
    const float* Wproj  = (const float*)d_in[8];
    const float* bproj  = (const float*)d_in[9];
    const float* routeW = (const float*)d_in[10];
    const float* projA  = (const float*)d_in[11];
    const float* projB  = (const float*)d_in[12];
    const float* Widk   = (const float*)d_in[13];
    const float* bidk   = (const float*)d_in[14];
    const float* idkA   = (const float*)d_in[15];
    const float* idkB   = (const float*)d_in[16];
    const float* Widv   = (const float*)d_in[17];
    const float* bidv   = (const float*)d_in[18];
    const float* idvA   = (const float*)d_in[19];
    const float* idvB   = (const float*)d_in[20];

    float* out  = (float*)d_out;
    float* kmid = out + Bb*Nn*Cc;
    float* vmid = kmid + Bb*Hh*NM*Dd;

    static int init = 0;
    if (!init){
        cudaFuncSetAttribute(k_attn_m, cudaFuncAttributeMaxDynamicSharedMemorySize, SMEM_M_TOT);
        cudaFuncSetAttribute(k_attn_s, cudaFuncAttributeMaxDynamicSharedMemorySize, SMEM_S_TOT);
        init = 1;
    }

    k_qkv_low<<<Bb*Nn/8, NT>>>(x, qkvA);
    k_sgemm_qkv<<<dim3(18, 40), NT>>>(x, Wqkv, bqkv, qkvB);
    k_id_small<<<Bb*NM, NT>>>(idt, idkA, idvA, Widk, bidk, idkB);
    k_sgemm_idv<<<dim3(6, 8), NT>>>(idt, Widv, bidv, idvB);
    k_apply_id<<<(Bb*Hh*NM*Dd)/NT, NT>>>(kmid, vmid);
    k_attn_m<<<Bb*Hh*NM/TQS, NTS, SMEM_M_TOT>>>(kmid, vmid);
    k_attn_s<<<Bb*Hh*NSd/TQS, NTS, SMEM_S_TOT>>>(memk, memv, vmid);
    k_route<<<Bb*Nn/8, NT>>>(routeW, projA);
    k_sgemm_proj<<<dim3(6, 40), NT>>>(Wproj, bproj, projB, out);
}

// round 9
// speedup vs baseline: 2.5982x; 1.0214x over previous
#include <cuda_runtime.h>
#include <cstring>

#define Bb 4
#define Nn 1280
#define NM 256
#define NSd 1024
#define Cc 768
#define Hh 12
#define Dd 64
#define MEMN 1280
#define LFULL 2560
#define KSEL_S 640
#define KSEL_M 128
#define NT 256
#define NTS 512
#define TQS 16
#define KTP 257
#define KT2 129
#define CKS 128
#define NCH 20

typedef unsigned long long u64t;

__device__ float g_q[Bb*Hh*Nn*Dd];
__device__ float g_k[Bb*Hh*Nn*Dd];
__device__ float g_v[Bb*Hh*Nn*Dd];
__device__ float g_qkvlow[Bb*Nn*24];
__device__ float g_idvlow[Bb*NM*8];
__device__ float g_act[Bb*NM*Hh];
__device__ float g_idv[Bb*NM*Cc];
__device__ float g_xo[Bb*Nn*Cc];
__device__ float g_wplow[Bb*Nn*32];

__device__ __forceinline__ u64t ffma2(u64t a, u64t b, u64t c){
    u64t d;
    asm("fma.rn.f32x2 %0, %1, %2, %3;" : "=l"(d) : "l"(a), "l"(b), "l"(c));
    return d;
}
__device__ __forceinline__ u64t pack2(float x, float y){
    u64t d;
    asm("mov.b64 %0, {%1, %2};" : "=l"(d) : "r"(__float_as_uint(x)), "r"(__float_as_uint(y)));
    return d;
}
__device__ __forceinline__ u64t f2u(float2 v){ u64t u; memcpy(&u, &v, 8); return u; }
__device__ __forceinline__ float2 u2f(u64t u){ float2 v; memcpy(&v, &u, 8); return v; }

__device__ __forceinline__ unsigned fkey(float f){
    unsigned b = __float_as_uint(f);
    return (b & 0x80000000u) ? ~b : (b | 0x80000000u);
}
__device__ __forceinline__ float inv_fkey(unsigned k){
    return (k & 0x80000000u) ? __uint_as_float(k ^ 0x80000000u)
                             : __uint_as_float(~k);
}

// Warp-synchronous exact top-K + softmax (keys pre-converted; early-exit radix).
template<int L, int KS, int GPC>
__device__ float warp_topk(float* sp, unsigned short* idxl, int* cs,
                           unsigned maxkey, int lane){
    const unsigned FULL = 0xffffffffu;
    unsigned* spk = (unsigned*)sp;
    const int G = L/32;
    const float vmax = inv_fkey(maxkey);
    unsigned prefix = 0; int need = KS;
    const int SH[7] = {27,22,17,12,7,2,0};
    const int NB[7] = {5,5,5,5,5,5,2};
    #pragma unroll
    for (int p = 0; p < 7; p++){
        const int shift = SH[p], nb = NB[p];
        const unsigned Bm = (1u << nb) - 1u;
        const unsigned maskhi = (p == 0) ? 0u : ~((1u << (shift + nb)) - 1u);
        unsigned cnt = 0;
        for (int g = 0; g < G; g++){
            unsigned key = spk[g*32 + lane];
            bool act = ((key & maskhi) == prefix);
            unsigned wv = (key >> shift) & Bm;
            unsigned mact = __ballot_sync(FULL, act);
            unsigned m0 = __ballot_sync(FULL, wv & 1);
            unsigned m1 = __ballot_sync(FULL, wv & 2);
            unsigned sel = mact & ((lane & 1) ? m0 : ~m0)
                                & ((lane & 2) ? m1 : ~m1);
            if (nb == 5){
                unsigned m2 = __ballot_sync(FULL, wv & 4);
                unsigned m3 = __ballot_sync(FULL, wv & 8);
                unsigned m4 = __ballot_sync(FULL, wv & 16);
                sel &= (lane & 4) ? m2 : ~m2;
                sel &= (lane & 8) ? m3 : ~m3;
                sel &= (lane & 16) ? m4 : ~m4;
            }
            cnt += __popc(sel);
        }
        if ((unsigned)lane > Bm) cnt = 0;
        unsigned run = cnt;
        #pragma unroll
        for (int off = 1; off < 32; off <<= 1){
            unsigned v = __shfl_down_sync(FULL, run, off);
            if (lane + off < 32) run += v;
        }
        unsigned gt = run - cnt;
        bool isthr = ((int)run >= need) && ((int)gt < need);
        unsigned mthr = __ballot_sync(FULL, isthr);
        int tl = __ffs(mthr) - 1;
        unsigned gtt = __shfl_sync(FULL, gt, tl);
        need -= (int)gtt;
        prefix |= ((unsigned)tl) << shift;
        unsigned cb = __shfl_sync(FULL, cnt, tl);
        if ((int)cb == need) break;
    }
    const unsigned thr = prefix;
    int tieacc = 0, nsel = 0; float lsum = 0.f;
    for (int g = 0; g < G; g++){
        if ((g % GPC) == 0 && lane == 0) cs[g / GPC] = nsel;
        int j = g*32 + lane;
        unsigned key = spk[j];
        bool eq = (key == thr);
        unsigned eqm = __ballot_sync(FULL, eq);
        bool selb = (key > thr) || (eq && (tieacc + __popc(eqm & ((1u<<lane)-1u))) < need);
        tieacc += __popc(eqm);
        float v = inv_fkey(key);
        float e = selb ? __expf(v - vmax) : 0.f;
        sp[j] = e; lsum += e;
        unsigned sm = __ballot_sync(FULL, selb);
        if (selb) idxl[nsel + __popc(sm & ((1u<<lane)-1u))] = (unsigned short)j;
        nsel += __popc(sm);
    }
    if (lane == 0) cs[G / GPC] = KS;
    #pragma unroll
    for (int off = 16; off; off >>= 1) lsum += __shfl_xor_sync(FULL, lsum, off);
    return lsum;
}

// ---- qkv lora low, 8 rows per block ----
__global__ void k_qkv_low(const float* __restrict__ x, const float* __restrict__ qkvA){
    __shared__ float xs[8*Cc];
    const int tid = threadIdx.x;
    const int m0 = blockIdx.x * 8;
    for (int i = tid; i < 8*Cc; i += NT) xs[i] = x[(size_t)m0*Cc + i];
    __syncthreads();
    const int warp = tid >> 5, lane = tid & 31;
    for (int o = warp; o < 24; o += 8){
        const float* a = &qkvA[o*Cc];
        float acc[8];
        #pragma unroll
        for (int r = 0; r < 8; r++) acc[r] = 0.f;
        for (int i = lane; i < Cc; i += 32){
            float av = a[i];
            #pragma unroll
            for (int r = 0; r < 8; r++) acc[r] += xs[r*Cc + i] * av;
        }
        #pragma unroll
        for (int r = 0; r < 8; r++){
            float p = acc[r];
            #pragma unroll
            for (int off = 16; off; off >>= 1) p += __shfl_xor_sync(0xffffffffu, p, off);
            if (lane == 0) g_qkvlow[(m0 + r)*24 + o] = p;
        }
    }
}

// ---- 128x128x8 double-buffered SGEMM mainloop with f32x2 packed FMA ----
#define SG128_COMP(STG)                                                           \
    _Pragma("unroll")                                                             \
    for (int kk = 0; kk < 8; kk++){                                               \
        float4 ra0 = *(const float4*)&As[STG][kk*128 + ty*4];                     \
        float4 ra1 = *(const float4*)&As[STG][kk*128 + 64 + ty*4];                \
        float4 rb0 = *(const float4*)&Ws[STG][kk*128 + tx*4];                     \
        float4 rb1 = *(const float4*)&Ws[STG][kk*128 + 64 + tx*4];                \
        u64t av2[4];                                                              \
        av2[0] = f2u(make_float2(ra0.x, ra0.y));                                  \
        av2[1] = f2u(make_float2(ra0.z, ra0.w));                                  \
        av2[2] = f2u(make_float2(ra1.x, ra1.y));                                  \
        av2[3] = f2u(make_float2(ra1.z, ra1.w));                                  \
        float bw_[8] = {rb0.x,rb0.y,rb0.z,rb0.w,rb1.x,rb1.y,rb1.z,rb1.w};         \
        _Pragma("unroll") for (int j_ = 0; j_ < 8; j_++){                         \
            u64t bd = pack2(bw_[j_], bw_[j_]);                                    \
            _Pragma("unroll") for (int i_ = 0; i_ < 4; i_++)                      \
                acc2[i_][j_] = ffma2(av2[i_], bd, acc2[i_][j_]);                  \
        }                                                                         \
    }

#define SG128_STORE(STG)                                                          \
    As[STG][(lc+0)*128 + lr] = pa.x; As[STG][(lc+1)*128 + lr] = pa.y;             \
    As[STG][(lc+2)*128 + lr] = pa.z; As[STG][(lc+3)*128 + lr] = pa.w;             \
    Ws[STG][(lc+0)*128 + lr] = pw.x; Ws[STG][(lc+1)*128 + lr] = pw.y;             \
    Ws[STG][(lc+2)*128 + lr] = pw.z; Ws[STG][(lc+3)*128 + lr] = pw.w;

#define SG128_MAIN(Aptr, Wptr, KDIM)                                              \
    __shared__ __align__(16) float As[2][8*128];                                  \
    __shared__ __align__(16) float Ws[2][8*128];                                  \
    u64t acc2[4][8];                                                              \
    _Pragma("unroll") for (int i_ = 0; i_ < 4; i_++)                              \
    _Pragma("unroll") for (int j_ = 0; j_ < 8; j_++) acc2[i_][j_] = 0ull;         \
    const int tid = threadIdx.x;                                                  \
    const int ty = tid >> 4, tx = tid & 15;                                       \
    const int lr = tid >> 1, lc = (tid & 1)*4;                                    \
    const int row0 = blockIdx.y*128, col0 = blockIdx.x*128;                       \
    const float* Ag = &Aptr[(size_t)(row0 + lr)*KDIM + lc];                       \
    const float* Wg = &Wptr[(size_t)(col0 + lr)*KDIM + lc];                       \
    float4 pa = *(const float4*)Ag;                                               \
    float4 pw = *(const float4*)Wg;                                               \
    int stg = 0;                                                                  \
    SG128_STORE(0)                                                                \
    __syncthreads();                                                              \
    for (int kt = 8; kt < KDIM; kt += 8){                                         \
        float4 na = *(const float4*)(Ag + kt);                                    \
        float4 nw = *(const float4*)(Wg + kt);                                    \
        SG128_COMP(stg)                                                           \
        pa = na; pw = nw;                                                         \
        { const int so = stg ^ 1; SG128_STORE(so) }                               \
        __syncthreads();                                                          \
        stg ^= 1;                                                                 \
    }                                                                             \
    SG128_COMP(stg)                                                               \
    float acc[8][8];                                                              \
    _Pragma("unroll") for (int p_ = 0; p_ < 4; p_++)                              \
    _Pragma("unroll") for (int j_ = 0; j_ < 8; j_++){                             \
        float2 t_ = u2f(acc2[p_][j_]);                                            \
        acc[2*p_][j_] = t_.x; acc[2*p_+1][j_] = t_.y;                             \
    }

__global__ __launch_bounds__(NT, 2)
void k_sgemm_qkv(const float* __restrict__ x, const float* __restrict__ W,
                 const float* __restrict__ bq, const float* __restrict__ qkvB){
    SG128_MAIN(x, W, Cc)
    const int g = col0 / Cc;
    #pragma unroll
    for (int ii = 0; ii < 8; ii++){
        const int m = row0 + ty*4 + (ii & 3) + (ii >> 2)*64;
        const int b = m / Nn, n = m % Nn;
        float lw[8];
        #pragma unroll
        for (int r = 0; r < 8; r++) lw[r] = g_qkvlow[m*24 + g*8 + r];
        #pragma unroll
        for (int jh = 0; jh < 2; jh++){
            float vv[4];
            #pragma unroll
            for (int q = 0; q < 4; q++){
                const int j = col0 + jh*64 + tx*4 + q;
                const int c = j - g*Cc;
                const float* bv = &qkvB[(g*Cc + c)*8];
                float lora = 0.f;
                #pragma unroll
                for (int r = 0; r < 8; r++) lora += lw[r] * bv[r];
                vv[q] = acc[ii][jh*4 + q] + bq[j] + 0.125f * lora;
            }
            const int c0 = col0 + jh*64 + tx*4 - g*Cc;
            const int h = c0 >> 6, d = c0 & 63;
            const size_t dst = ((size_t)(b*Hh + h)*Nn + n)*Dd + d;
            if (g == 0){
                float4 o = {vv[0]*0.125f, vv[1]*0.125f, vv[2]*0.125f, vv[3]*0.125f};
                *(float4*)&g_q[dst] = o;
            } else if (g == 1){
                float4 o = {vv[0], vv[1], vv[2], vv[3]};
                *(float4*)&g_k[dst] = o;
            } else {
                float4 o = {vv[0], vv[1], vv[2], vv[3]};
                *(float4*)&g_v[dst] = o;
            }
        }
    }
}

__global__ void k_id_small(const float* __restrict__ idt, const float* __restrict__ idkA,
                           const float* __restrict__ idvA, const float* __restrict__ Widk,
                           const float* __restrict__ bidk, const float* __restrict__ idkB){
    const int row = blockIdx.x;
    const int tid = threadIdx.x;
    __shared__ float xs[Cc];
    __shared__ float lk[8], dk[12];
    for (int i = tid; i < Cc; i += NT) xs[i] = idt[row*Cc + i];
    __syncthreads();
    const int warp = tid >> 5, lane = tid & 31;
    for (int o = warp; o < 28; o += 8){
        const float* a;
        if (o < 8)       a = &idkA[o*Cc];
        else if (o < 16) a = &idvA[(o - 8)*Cc];
        else             a = &Widk[(o - 16)*Cc];
        float p = 0.f;
        for (int i = lane; i < Cc; i += 32) p += xs[i] * a[i];
        #pragma unroll
        for (int off = 16; off; off >>= 1) p += __shfl_xor_sync(0xffffffffu, p, off);
        if (lane == 0){
            if (o < 8)       lk[o] = p;
            else if (o < 16) g_idvlow[row*8 + (o - 8)] = p;
            else             dk[o - 16] = p;
        }
    }
    __syncthreads();
    if (tid < 12){
        float lo = 0.f;
        #pragma unroll
        for (int r = 0; r < 8; r++) lo += lk[r] * idkB[tid*8 + r];
        float f = dk[tid] + bidk[tid] + 0.125f * lo;
        g_act[row*Hh + tid] = 1.f + tanhf(f);
    }
}

// ---- idv GEMM: 64x64 tiles (full-chip grid for the small GEMM) ----
__global__ void k_sgemm_idv(const float* __restrict__ idt, const float* __restrict__ W,
                            const float* __restrict__ bidv, const float* __restrict__ idvB){
    __shared__ __align__(16) float As[16*64];
    __shared__ __align__(16) float Ws[16*64];
    float acc[4][4];
    #pragma unroll
    for (int i = 0; i < 4; i++)
    #pragma unroll
    for (int j = 0; j < 4; j++) acc[i][j] = 0.f;
    const int tid = threadIdx.x;
    const int ty = tid >> 4, tx = tid & 15;
    const int lr = tid >> 2, lk = (tid & 3) * 4;
    const int row0 = blockIdx.y * 64, col0 = blockIdx.x * 64;
    for (int kt = 0; kt < Cc; kt += 16){
        float4 a4 = *(const float4*)&idt[(row0 + lr)*Cc + kt + lk];
        float4 w4 = *(const float4*)&W[(col0 + lr)*Cc + kt + lk];
        __syncthreads();
        As[(lk+0)*64 + lr] = a4.x; As[(lk+1)*64 + lr] = a4.y;
        As[(lk+2)*64 + lr] = a4.z; As[(lk+3)*64 + lr] = a4.w;
        Ws[(lk+0)*64 + lr] = w4.x; Ws[(lk+1)*64 + lr] = w4.y;
        Ws[(lk+2)*64 + lr] = w4.z; Ws[(lk+3)*64 + lr] = w4.w;
        __syncthreads();
        #pragma unroll
        for (int kk = 0; kk < 16; kk++){
            float4 ra = *(const float4*)&As[kk*64 + ty*4];
            float4 rb = *(const float4*)&Ws[kk*64 + tx*4];
            acc[0][0] += ra.x*rb.x; acc[0][1] += ra.x*rb.y;
            acc[0][2] += ra.x*rb.z; acc[0][3] += ra.x*rb.w;
            acc[1][0] += ra.y*rb.x; acc[1][1] += ra.y*rb.y;
            acc[1][2] += ra.y*rb.z; acc[1][3] += ra.y*rb.w;
            acc[2][0] += ra.z*rb.x; acc[2][1] += ra.z*rb.y;
            acc[2][2] += ra.z*rb.z; acc[2][3] += ra.z*rb.w;
            acc[3][0] += ra.w*rb.x; acc[3][1] += ra.w*rb.y;
            acc[3][2] += ra.w*rb.z; acc[3][3] += ra.w*rb.w;
        }
    }
    #pragma unroll
    for (int ii = 0; ii < 4; ii++){
        const int m = row0 + ty*4 + ii;
        float lw[8];
        #pragma unroll
        for (int r = 0; r < 8; r++) lw[r] = g_idvlow[m*8 + r];
        #pragma unroll
        for (int jj = 0; jj < 4; jj++){
            const int c = col0 + tx*4 + jj;
            const float* bv = &idvB[c*8];
            float lora = 0.f;
            #pragma unroll
            for (int r = 0; r < 8; r++) lora += lw[r] * bv[r];
            g_idv[m*Cc + c] = acc[ii][jj] + bidv[c] + 0.125f * lora;
        }
    }
}

__global__ void k_apply_id(float* __restrict__ kmid, float* __restrict__ vmid){
    const int idx = blockIdx.x * NT + threadIdx.x;
    const int d = idx & 63;
    int t = idx >> 6;
    const int m = t % NM; t /= NM;
    const int h = t % Hh; const int b = t / Hh;
    const int src = ((b*Hh + h)*Nn + m)*Dd + d;
    kmid[idx] = g_k[src] * g_act[(b*NM + m)*Hh + h];
    vmid[idx] = g_v[src] + g_idv[(b*NM + m)*Cc + h*Dd + d];
}

// ---- mem attention: 16 rows/block, 512 threads, packed-f32x2 scores ----
#define SMM_S    0
#define SMM_KT   16384
#define SMM_QS   82176
#define SMM_IDX  86272
#define SMM_CS   90368
#define SMEM_M_TOT 90496

__global__ __launch_bounds__(NTS, 2)
void k_attn_m(const float* __restrict__ kmid, const float* __restrict__ vmid){
    extern __shared__ __align__(16) char smb[];
    float* s  = (float*)(smb + SMM_S);
    float* kt = (float*)(smb + SMM_KT);
    float* qs = (float*)(smb + SMM_QS);
    unsigned short* idxall = (unsigned short*)(smb + SMM_IDX);
    int* csall = (int*)(smb + SMM_CS);
    const int tid = threadIdx.x, lane = tid & 31, w = tid >> 5;
    const int qt = blockIdx.x & 15;
    const int bh = blockIdx.x >> 4;
    const int b = bh / Hh, h = bh % Hh;
    const int m0 = qt * TQS;
    // q packed by row pairs: qs[p*128 + 2*d + (r&1)], p = r>>1
    #pragma unroll
    for (int i = tid; i < TQS*Dd; i += NTS){
        int r = i >> 6, d = i & 63;
        qs[(r >> 1)*128 + (d << 1) + (r & 1)] = g_q[((size_t)bh*Nn + m0 + r)*Dd + d];
    }
    #pragma unroll
    for (int ph = 0; ph < 8; ph++){
        int idx = tid + ph*NTS;
        int r = idx >> 4, c4 = idx & 15;
        float4 kv = *(const float4*)&kmid[((size_t)bh*NM + r)*Dd + c4*4];
        kt[(c4*4+0)*KTP + r] = kv.x;
        kt[(c4*4+1)*KTP + r] = kv.y;
        kt[(c4*4+2)*KTP + r] = kv.z;
        kt[(c4*4+3)*KTP + r] = kv.w;
    }
    __syncthreads();
    {
        const int key = tid & 255, pg = (tid >> 8) * 4;  // 4 row-pairs = 8 rows
        u64t a2[4];
        #pragma unroll
        for (int p = 0; p < 4; p++) a2[p] = 0ull;
        #pragma unroll 8
        for (int d = 0; d < 64; d++){
            float kk = kt[d*KTP + key];
            u64t kd = pack2(kk, kk);
            #pragma unroll
            for (int p = 0; p < 4; p++){
                float2 qv = *(const float2*)&qs[(pg + p)*128 + (d << 1)];
                a2[p] = ffma2(kd, f2u(qv), a2[p]);
            }
        }
        #pragma unroll
        for (int p = 0; p < 4; p++){
            float2 t = u2f(a2[p]);
            ((unsigned*)s)[(pg*2 + 2*p + 0)*NM + key] = fkey(t.x);
            ((unsigned*)s)[(pg*2 + 2*p + 1)*NM + key] = fkey(t.y);
        }
    }
    __syncthreads();
    float* sp = s + w*NM;
    unsigned* spk = (unsigned*)sp;
    unsigned kmax = 0;
    #pragma unroll
    for (int g = 0; g < NM/32; g++) kmax = max(kmax, spk[g*32 + lane]);
    #pragma unroll
    for (int off = 16; off; off >>= 1) kmax = max(kmax, __shfl_xor_sync(0xffffffffu, kmax, off));
    float Z = warp_topk<NM, KSEL_M, 8>(sp, idxall + w*KSEL_M, csall + w*2, kmax, lane);
    float invZ = 1.f / Z;
    __syncthreads();
    float* vsh = kt;
    #pragma unroll
    for (int ph = 0; ph < 8; ph++){
        int idx = tid + ph*NTS;
        int r = idx >> 4, c4 = idx & 15;
        *(float4*)&vsh[r*Dd + c4*4] = *(const float4*)&vmid[((size_t)bh*NM + r)*Dd + c4*4];
    }
    __syncthreads();
    u64t acc2v = 0ull;
    const unsigned short* il = idxall + w*KSEL_M;
    #pragma unroll 4
    for (int n = 0; n < KSEL_M; n++){
        int j = il[n];
        float wgt = sp[j];
        u64t wd = pack2(wgt, wgt);
        float2 v2 = ((const float2*)&vsh[j*Dd])[lane];
        acc2v = ffma2(wd, f2u(v2), acc2v);
    }
    float2 accv = u2f(acc2v);
    float2 o = {accv.x*invZ, accv.y*invZ};
    ((float2*)&g_xo[((size_t)b*Nn + m0 + w)*Cc + h*Dd])[lane] = o;
}

// ---- streaming attention: 16 rows/block, packed-f32x2 scores, reg-prefetch ----
#define SMS_S    0
#define SMS_KT   163840
#define SMS_QS   196864
#define SMS_CS   200960
#define SMS_IDX  202496
#define SMEM_S_TOT 222976

__global__ __launch_bounds__(NTS, 1)
void k_attn_s(const float* __restrict__ memk, const float* __restrict__ memv,
              const float* __restrict__ vmid){
    extern __shared__ __align__(16) char smb[];
    float* s  = (float*)(smb + SMS_S);
    float* kt = (float*)(smb + SMS_KT);
    float* qs = (float*)(smb + SMS_QS);
    int* csall = (int*)(smb + SMS_CS);
    unsigned short* idxall = (unsigned short*)(smb + SMS_IDX);
    const int tid = threadIdx.x, lane = tid & 31, w = tid >> 5;
    const int qt = blockIdx.x & 63;
    const int bh = blockIdx.x >> 6;
    const int b = bh / Hh, h = bh % Hh;
    const int nq0 = NM + qt*TQS;
    // q packed by row pairs
    #pragma unroll
    for (int i = tid; i < TQS*Dd; i += NTS){
        int r = i >> 6, d = i & 63;
        qs[(r >> 1)*128 + (d << 1) + (r & 1)] = g_q[((size_t)bh*Nn + nq0 + r)*Dd + d];
    }
    const int pr = tid >> 2;
    const int pco = (tid & 3) * 4;
    float4 pre[4];
    {
        const float* kr = &memk[((size_t)bh*MEMN + pr)*Dd];
        #pragma unroll
        for (int i = 0; i < 4; i++) pre[i] = ((const float4*)kr)[pco + i];
    }
    const int key = tid & 127, pb = (tid >> 7) * 2;  // 2 row-pairs = 4 rows
    for (int ck = 0; ck < NCH; ck++){
        __syncthreads();
        #pragma unroll
        for (int i = 0; i < 4; i++){
            int c = (pco + i)*4;
            kt[(c+0)*KT2 + pr] = pre[i].x; kt[(c+1)*KT2 + pr] = pre[i].y;
            kt[(c+2)*KT2 + pr] = pre[i].z; kt[(c+3)*KT2 + pr] = pre[i].w;
        }
        __syncthreads();
        if (ck + 1 < NCH){
            int j = (ck+1)*CKS + pr;
            const float* kr = (j < MEMN) ? &memk[((size_t)bh*MEMN + j)*Dd]
                                         : &g_k[((size_t)bh*Nn + (j - MEMN))*Dd];
            #pragma unroll
            for (int i = 0; i < 4; i++) pre[i] = ((const float4*)kr)[pco + i];
        }
        u64t a2A = 0ull, a2B = 0ull;
        #pragma unroll 16
        for (int d = 0; d < 64; d++){
            float kk = kt[d*KT2 + key];
            u64t kd = pack2(kk, kk);
            float2 qA = *(const float2*)&qs[pb*128 + (d << 1)];
            float2 qB = *(const float2*)&qs[(pb + 1)*128 + (d << 1)];
            a2A = ffma2(kd, f2u(qA), a2A);
            a2B = ffma2(kd, f2u(qB), a2B);
        }
        float2 r01 = u2f(a2A), r23 = u2f(a2B);
        unsigned* su = (unsigned*)s;
        su[(pb*2+0)*LFULL + ck*CKS + key] = fkey(r01.x);
        su[(pb*2+1)*LFULL + ck*CKS + key] = fkey(r01.y);
        su[(pb*2+2)*LFULL + ck*CKS + key] = fkey(r23.x);
        su[(pb*2+3)*LFULL + ck*CKS + key] = fkey(r23.y);
    }
    __syncthreads();
    float* sp = s + w*LFULL;
    unsigned* spk = (unsigned*)sp;
    int* cs = csall + w*24;
    unsigned short* il = idxall + w*KSEL_S;
    unsigned kmax = 0;
    for (int g = 0; g < LFULL/32; g++) kmax = max(kmax, spk[g*32 + lane]);
    #pragma unroll
    for (int off = 16; off; off >>= 1) kmax = max(kmax, __shfl_xor_sync(0xffffffffu, kmax, off));
    float Z = warp_topk<LFULL, KSEL_S, 4>(sp, il, cs, kmax, lane);
    float invZ = 1.f / Z;
    // V phase: 2 selected keys per iteration (half-warps), packed FMA
    float* vsh = kt;
    {
        const float* vr = &memv[((size_t)bh*MEMN + pr)*Dd];
        #pragma unroll
        for (int i = 0; i < 4; i++) pre[i] = ((const float4*)vr)[pco + i];
    }
    const int hl = lane >> 4, ll = lane & 15;
    u64t accA = 0ull, accB = 0ull;
    for (int ck = 0; ck < NCH; ck++){
        __syncthreads();
        #pragma unroll
        for (int i = 0; i < 4; i++)
            *(float4*)&vsh[pr*Dd + (pco + i)*4] = pre[i];
        __syncthreads();
        if (ck + 1 < NCH){
            int j = (ck+1)*CKS + pr;
            const float* vr;
            if (j < MEMN)            vr = &memv[((size_t)bh*MEMN + j)*Dd];
            else if (j < MEMN + NM)  vr = &vmid[((size_t)bh*NM + (j - MEMN))*Dd];
            else                     vr = &g_v[((size_t)bh*Nn + (j - MEMN))*Dd];
            #pragma unroll
            for (int i = 0; i < 4; i++) pre[i] = ((const float4*)vr)[pco + i];
        }
        const int nb = cs[ck], ne = cs[ck+1], jb = ck*CKS;
        for (int n = nb; n < ne; n += 2){
            int j0 = il[n];
            int j1 = (n + 1 < ne) ? il[n+1] : j0;
            int jj = hl ? j1 : j0;
            float wgt = sp[jj];
            if (hl && (n + 1 >= ne)) wgt = 0.f;
            u64t wd = pack2(wgt, wgt);
            const float* vb = &vsh[(jj - jb)*Dd + ll*4];
            float2 vA = *(const float2*)vb;
            float2 vB = *(const float2*)(vb + 2);
            accA = ffma2(wd, f2u(vA), accA);
            accB = ffma2(wd, f2u(vB), accB);
        }
    }
    float2 aA = u2f(accA), aB = u2f(accB);
    float4 acc4 = {aA.x, aA.y, aB.x, aB.y};
    acc4.x += __shfl_xor_sync(0xffffffffu, acc4.x, 16);
    acc4.y += __shfl_xor_sync(0xffffffffu, acc4.y, 16);
    acc4.z += __shfl_xor_sync(0xffffffffu, acc4.z, 16);
    acc4.w += __shfl_xor_sync(0xffffffffu, acc4.w, 16);
    if (lane < 16){
        float4 o = {acc4.x*invZ, acc4.y*invZ, acc4.z*invZ, acc4.w*invZ};
        *(float4*)&g_xo[((size_t)b*Nn + nq0 + w)*Cc + h*Dd + ll*4] = o;
    }
}

// ---- route softmax + proj lows, 8 rows per block ----
__global__ void k_route(const float* __restrict__ routeW, const float* __restrict__ projA){
    __shared__ float xs[8*Cc];
    __shared__ float lg[8][4], pl[8][32], sm[8][4];
    const int tid = threadIdx.x;
    const int m0 = blockIdx.x * 8;
    for (int i = tid; i < 8*Cc; i += NT) xs[i] = g_xo[(size_t)m0*Cc + i];
    __syncthreads();
    const int warp = tid >> 5, lane = tid & 31;
    for (int o = warp; o < 36; o += 8){
        const float* a = (o < 4) ? &routeW[o*Cc] : &projA[(o - 4)*Cc];
        float acc[8];
        #pragma unroll
        for (int r = 0; r < 8; r++) acc[r] = 0.f;
        for (int i = lane; i < Cc; i += 32){
            float av = a[i];
            #pragma unroll
            for (int r = 0; r < 8; r++) acc[r] += xs[r*Cc + i] * av;
        }
        #pragma unroll
        for (int r = 0; r < 8; r++){
            float p = acc[r];
            #pragma unroll
            for (int off = 16; off; off >>= 1) p += __shfl_xor_sync(0xffffffffu, p, off);
            if (lane == 0){
                if (o < 4) lg[r][o] = p;
                else       pl[r][o - 4] = p;
            }
        }
    }
    __syncthreads();
    if (tid < 8){
        int r = tid;
        float mx = fmaxf(fmaxf(lg[r][0], lg[r][1]), fmaxf(lg[r][2], lg[r][3]));
        float e0 = __expf(lg[r][0]-mx), e1 = __expf(lg[r][1]-mx);
        float e2 = __expf(lg[r][2]-mx), e3 = __expf(lg[r][3]-mx);
        float si = 1.f / (e0 + e1 + e2 + e3);
        sm[r][0] = e0*si; sm[r][1] = e1*si; sm[r][2] = e2*si; sm[r][3] = e3*si;
    }
    __syncthreads();
    {
        int r = tid >> 5, t = tid & 31;
        g_wplow[(m0 + r)*32 + t] = sm[r][t >> 3] * pl[r][t] * 0.125f;
    }
}

__global__ __launch_bounds__(NT, 2)
void k_sgemm_proj(const float* __restrict__ W, const float* __restrict__ bp,
                  const float* __restrict__ projB, float* __restrict__ out){
    SG128_MAIN(g_xo, W, Cc)
    #pragma unroll
    for (int ii = 0; ii < 8; ii++){
        const int m = row0 + ty*4 + (ii & 3) + (ii >> 2)*64;
        float wl[32];
        #pragma unroll
        for (int t = 0; t < 32; t++) wl[t] = g_wplow[m*32 + t];
        #pragma unroll
        for (int jh = 0; jh < 2; jh++){
            float vv[4];
            #pragma unroll
            for (int q = 0; q < 4; q++){
                const int c = col0 + jh*64 + tx*4 + q;
                float lora = 0.f;
                #pragma unroll
                for (int e = 0; e < 4; e++){
                    const float* bv = &projB[(e*Cc + c)*8];
                    #pragma unroll
                    for (int r = 0; r < 8; r++) lora += wl[e*8 + r] * bv[r];
                }
                vv[q] = acc[ii][jh*4 + q] + bp[c] + lora;
            }
            const int c0 = col0 + jh*64 + tx*4;
            float4 o = {vv[0], vv[1], vv[2], vv[3]};
            *(float4*)&out[(size_t)m*Cc + c0] = o;
        }
    }
}

extern "C" void kernel_launch(void* const* d_in, const int* in_sizes, int n_in,
                              void* d_out, int out_size){
    const float* x      = (const float*)d_in[0];
    const float* idt    = (const float*)d_in[1];
    const float* memk   = (const float*)d_in[2];
    const float* memv   = (const float*)d_in[3];
    const float* Wqkv   = (const float*)d_in[4];
    const float* bqkv   = (const float*)d_in[5];
    const float* qkvA   = (const float*)d_in[6];
    const float* qkvB   = (const float*)d_in[7];
    const float* Wproj  = (const float*)d_in[8];
    const float* bproj  = (const float*)d_in[9];
    const float* routeW = (const float*)d_in[10];
    const float* projA  = (const float*)d_in[11];
    const float* projB  = (const float*)d_in[12];
    const float* Widk   = (const float*)d_in[13];
    const float* bidk   = (const float*)d_in[14];
    const float* idkA   = (const float*)d_in[15];
    const float* idkB   = (const float*)d_in[16];
    const float* Widv   = (const float*)d_in[17];
    const float* bidv   = (const float*)d_in[18];
    const float* idvA   = (const float*)d_in[19];
    const float* idvB   = (const float*)d_in[20];

    float* out  = (float*)d_out;
    float* kmid = out + Bb*Nn*Cc;
    float* vmid = kmid + Bb*Hh*NM*Dd;

    static int init = 0;
    if (!init){
        cudaFuncSetAttribute(k_attn_m, cudaFuncAttributeMaxDynamicSharedMemorySize, SMEM_M_TOT);
        cudaFuncSetAttribute(k_attn_s, cudaFuncAttributeMaxDynamicSharedMemorySize, SMEM_S_TOT);
        init = 1;
    }

    k_qkv_low<<<Bb*Nn/8, NT>>>(x, qkvA);
    k_sgemm_qkv<<<dim3(18, 40), NT>>>(x, Wqkv, bqkv, qkvB);
    k_id_small<<<Bb*NM, NT>>>(idt, idkA, idvA, Widk, bidk, idkB);
    k_sgemm_idv<<<dim3(12, 16), NT>>>(idt, Widv, bidv, idvB);
    k_apply_id<<<(Bb*Hh*NM*Dd)/NT, NT>>>(kmid, vmid);
    k_attn_m<<<Bb*Hh*NM/TQS, NTS, SMEM_M_TOT>>>(kmid, vmid);
    k_attn_s<<<Bb*Hh*NSd/TQS, NTS, SMEM_S_TOT>>>(memk, memv, vmid);
    k_route<<<Bb*Nn/8, NT>>>(routeW, projA);
    k_sgemm_proj<<<dim3(6, 40), NT>>>(Wproj, bproj, projB, out);
}

// round 11
// speedup vs baseline: 2.6895x; 1.0351x over previous
#include <cuda_runtime.h>
#include <cstring>

#define Bb 4
#define Nn 1280
#define NM 256
#define NSd 1024
#define Cc 768
#define Hh 12
#define Dd 64
#define MEMN 1280
#define LFULL 2560
#define KSEL_S 640
#define KSEL_M 128
#define NT 256
#define NTS 512
#define TQS 16
#define KTP 257
#define KT2 129
#define CKS 128
#define NCH 20

typedef unsigned long long u64t;

__device__ float g_q[Bb*Hh*Nn*Dd];
__device__ float g_k[Bb*Hh*Nn*Dd];
__device__ float g_v[Bb*Hh*Nn*Dd];
__device__ float g_qkvlow[Bb*Nn*24];
__device__ float g_idvlow[Bb*NM*8];
__device__ float g_act[Bb*NM*Hh];
__device__ float g_idv[Bb*NM*Cc];
__device__ float g_xo[Bb*Nn*Cc];
__device__ float g_wplow[Bb*Nn*32];

__device__ __forceinline__ u64t ffma2(u64t a, u64t b, u64t c){
    u64t d;
    asm("fma.rn.f32x2 %0, %1, %2, %3;" : "=l"(d) : "l"(a), "l"(b), "l"(c));
    return d;
}
__device__ __forceinline__ u64t pack2(float x, float y){
    u64t d;
    asm("mov.b64 %0, {%1, %2};" : "=l"(d) : "r"(__float_as_uint(x)), "r"(__float_as_uint(y)));
    return d;
}
__device__ __forceinline__ u64t f2u(float2 v){ u64t u; memcpy(&u, &v, 8); return u; }
__device__ __forceinline__ float2 u2f(u64t u){ float2 v; memcpy(&v, &u, 8); return v; }

__device__ __forceinline__ unsigned fkey(float f){
    unsigned b = __float_as_uint(f);
    return (b & 0x80000000u) ? ~b : (b | 0x80000000u);
}
__device__ __forceinline__ float inv_fkey(unsigned k){
    return (k & 0x80000000u) ? __uint_as_float(k ^ 0x80000000u)
                             : __uint_as_float(~k);
}

// Warp-synchronous exact top-K + softmax (keys pre-converted; early-exit radix).
template<int L, int KS, int GPC>
__device__ float warp_topk(float* sp, unsigned short* idxl, int* cs,
                           unsigned maxkey, int lane){
    const unsigned FULL = 0xffffffffu;
    unsigned* spk = (unsigned*)sp;
    const int G = L/32;
    const float vmax = inv_fkey(maxkey);
    unsigned prefix = 0; int need = KS;
    const int SH[7] = {27,22,17,12,7,2,0};
    const int NB[7] = {5,5,5,5,5,5,2};
    #pragma unroll
    for (int p = 0; p < 7; p++){
        const int shift = SH[p], nb = NB[p];
        const unsigned Bm = (1u << nb) - 1u;
        const unsigned maskhi = (p == 0) ? 0u : ~((1u << (shift + nb)) - 1u);
        unsigned cnt = 0;
        for (int g = 0; g < G; g++){
            unsigned key = spk[g*32 + lane];
            bool act = ((key & maskhi) == prefix);
            unsigned wv = (key >> shift) & Bm;
            unsigned mact = __ballot_sync(FULL, act);
            unsigned m0 = __ballot_sync(FULL, wv & 1);
            unsigned m1 = __ballot_sync(FULL, wv & 2);
            unsigned sel = mact & ((lane & 1) ? m0 : ~m0)
                                & ((lane & 2) ? m1 : ~m1);
            if (nb == 5){
                unsigned m2 = __ballot_sync(FULL, wv & 4);
                unsigned m3 = __ballot_sync(FULL, wv & 8);
                unsigned m4 = __ballot_sync(FULL, wv & 16);
                sel &= (lane & 4) ? m2 : ~m2;
                sel &= (lane & 8) ? m3 : ~m3;
                sel &= (lane & 16) ? m4 : ~m4;
            }
            cnt += __popc(sel);
        }
        if ((unsigned)lane > Bm) cnt = 0;
        unsigned run = cnt;
        #pragma unroll
        for (int off = 1; off < 32; off <<= 1){
            unsigned v = __shfl_down_sync(FULL, run, off);
            if (lane + off < 32) run += v;
        }
        unsigned gt = run - cnt;
        bool isthr = ((int)run >= need) && ((int)gt < need);
        unsigned mthr = __ballot_sync(FULL, isthr);
        int tl = __ffs(mthr) - 1;
        unsigned gtt = __shfl_sync(FULL, gt, tl);
        need -= (int)gtt;
        prefix |= ((unsigned)tl) << shift;
        unsigned cb = __shfl_sync(FULL, cnt, tl);
        if ((int)cb == need) break;
    }
    const unsigned thr = prefix;
    int tieacc = 0, nsel = 0; float lsum = 0.f;
    for (int g = 0; g < G; g++){
        if ((g % GPC) == 0 && lane == 0) cs[g / GPC] = nsel;
        int j = g*32 + lane;
        unsigned key = spk[j];
        bool eq = (key == thr);
        unsigned eqm = __ballot_sync(FULL, eq);
        bool selb = (key > thr) || (eq && (tieacc + __popc(eqm & ((1u<<lane)-1u))) < need);
        tieacc += __popc(eqm);
        float v = inv_fkey(key);
        float e = selb ? __expf(v - vmax) : 0.f;
        sp[j] = e; lsum += e;
        unsigned sm = __ballot_sync(FULL, selb);
        if (selb) idxl[nsel + __popc(sm & ((1u<<lane)-1u))] = (unsigned short)j;
        nsel += __popc(sm);
    }
    if (lane == 0) cs[G / GPC] = KS;
    #pragma unroll
    for (int off = 16; off; off >>= 1) lsum += __shfl_xor_sync(FULL, lsum, off);
    return lsum;
}

// ---- qkv lora low, 8 rows per block ----
__global__ void k_qkv_low(const float* __restrict__ x, const float* __restrict__ qkvA){
    __shared__ float xs[8*Cc];
    const int tid = threadIdx.x;
    const int m0 = blockIdx.x * 8;
    for (int i = tid; i < 8*Cc; i += NT) xs[i] = x[(size_t)m0*Cc + i];
    __syncthreads();
    const int warp = tid >> 5, lane = tid & 31;
    for (int o = warp; o < 24; o += 8){
        const float* a = &qkvA[o*Cc];
        float acc[8];
        #pragma unroll
        for (int r = 0; r < 8; r++) acc[r] = 0.f;
        for (int i = lane; i < Cc; i += 32){
            float av = a[i];
            #pragma unroll
            for (int r = 0; r < 8; r++) acc[r] += xs[r*Cc + i] * av;
        }
        #pragma unroll
        for (int r = 0; r < 8; r++){
            float p = acc[r];
            #pragma unroll
            for (int off = 16; off; off >>= 1) p += __shfl_xor_sync(0xffffffffu, p, off);
            if (lane == 0) g_qkvlow[(m0 + r)*24 + o] = p;
        }
    }
}

// ---- 128x128x8 double-buffered SGEMM pieces (f32x2 packed FMA) ----
#define SG128_COMP(STG)                                                           \
    _Pragma("unroll")                                                             \
    for (int kk = 0; kk < 8; kk++){                                               \
        float4 ra0 = *(const float4*)&As[STG][kk*128 + ty*4];                     \
        float4 ra1 = *(const float4*)&As[STG][kk*128 + 64 + ty*4];                \
        float4 rb0 = *(const float4*)&Ws[STG][kk*128 + tx*4];                     \
        float4 rb1 = *(const float4*)&Ws[STG][kk*128 + 64 + tx*4];                \
        u64t av2[4];                                                              \
        av2[0] = f2u(make_float2(ra0.x, ra0.y));                                  \
        av2[1] = f2u(make_float2(ra0.z, ra0.w));                                  \
        av2[2] = f2u(make_float2(ra1.x, ra1.y));                                  \
        av2[3] = f2u(make_float2(ra1.z, ra1.w));                                  \
        float bw_[8] = {rb0.x,rb0.y,rb0.z,rb0.w,rb1.x,rb1.y,rb1.z,rb1.w};         \
        _Pragma("unroll") for (int j_ = 0; j_ < 8; j_++){                         \
            u64t bd = pack2(bw_[j_], bw_[j_]);                                    \
            _Pragma("unroll") for (int i_ = 0; i_ < 4; i_++)                      \
                acc2[i_][j_] = ffma2(av2[i_], bd, acc2[i_][j_]);                  \
        }                                                                         \
    }

#define SG128_STORE(STG)                                                          \
    As[STG][(lc+0)*128 + lr] = pa.x; As[STG][(lc+1)*128 + lr] = pa.y;             \
    As[STG][(lc+2)*128 + lr] = pa.z; As[STG][(lc+3)*128 + lr] = pa.w;             \
    Ws[STG][(lc+0)*128 + lr] = pw.x; Ws[STG][(lc+1)*128 + lr] = pw.y;             \
    Ws[STG][(lc+2)*128 + lr] = pw.z; Ws[STG][(lc+3)*128 + lr] = pw.w;

#define SG128_PREAMBLE                                                            \
    __shared__ __align__(16) float As[2][8*128];                                  \
    __shared__ __align__(16) float Ws[2][8*128];                                  \
    u64t acc2[4][8];                                                              \
    _Pragma("unroll") for (int i_ = 0; i_ < 4; i_++)                              \
    _Pragma("unroll") for (int j_ = 0; j_ < 8; j_++) acc2[i_][j_] = 0ull;         \
    const int tid = threadIdx.x;                                                  \
    const int ty = tid >> 4, tx = tid & 15;                                       \
    const int lr = tid >> 1, lc = (tid & 1)*4;                                    \
    const int row0 = blockIdx.y*128, col0 = blockIdx.x*128;

#define SG128_LOOP(KEXT)                                                          \
    float4 pa = LOADA(0);                                                         \
    float4 pw = LOADW(0);                                                         \
    int stg = 0;                                                                  \
    SG128_STORE(0)                                                                \
    __syncthreads();                                                              \
    for (int kt = 8; kt < (KEXT); kt += 8){                                       \
        float4 na = LOADA(kt);                                                    \
        float4 nw = LOADW(kt);                                                    \
        SG128_COMP(stg)                                                           \
        pa = na; pw = nw;                                                         \
        { const int so = stg ^ 1; SG128_STORE(so) }                               \
        __syncthreads();                                                          \
        stg ^= 1;                                                                 \
    }                                                                             \
    SG128_COMP(stg)                                                               \
    float acc[8][8];                                                              \
    _Pragma("unroll") for (int p_ = 0; p_ < 4; p_++)                              \
    _Pragma("unroll") for (int j_ = 0; j_ < 8; j_++){                             \
        float2 t_ = u2f(acc2[p_][j_]);                                            \
        acc[2*p_][j_] = t_.x; acc[2*p_+1][j_] = t_.y;                             \
    }

// ---- QKV GEMM: lora folded as 8 extra K-steps (K = 776) ----
__global__ __launch_bounds__(NT, 2)
void k_sgemm_qkv(const float* __restrict__ x, const float* __restrict__ W,
                 const float* __restrict__ bq, const float* __restrict__ qkvB){
    SG128_PREAMBLE
    const int g = col0 / Cc;
    auto LOADA = [&](int kt)->float4{
        if (kt < Cc) return *(const float4*)&x[(size_t)(row0 + lr)*Cc + kt + lc];
        float4 v = *(const float4*)&g_qkvlow[(row0 + lr)*24 + g*8 + (kt - Cc) + lc];
        v.x *= 0.125f; v.y *= 0.125f; v.z *= 0.125f; v.w *= 0.125f;
        return v;
    };
    auto LOADW = [&](int kt)->float4{
        if (kt < Cc) return *(const float4*)&W[(size_t)(col0 + lr)*Cc + kt + lc];
        return *(const float4*)&qkvB[(size_t)(col0 + lr)*8 + (kt - Cc) + lc];
    };
    SG128_LOOP(Cc + 8)
    #pragma unroll
    for (int ii = 0; ii < 8; ii++){
        const int m = row0 + ty*4 + (ii & 3) + (ii >> 2)*64;
        const int b = m / Nn, n = m % Nn;
        #pragma unroll
        for (int jh = 0; jh < 2; jh++){
            float vv[4];
            #pragma unroll
            for (int q = 0; q < 4; q++){
                const int j = col0 + jh*64 + tx*4 + q;
                vv[q] = acc[ii][jh*4 + q] + bq[j];
            }
            const int c0 = col0 + jh*64 + tx*4 - g*Cc;
            const int h = c0 >> 6, d = c0 & 63;
            const size_t dst = ((size_t)(b*Hh + h)*Nn + n)*Dd + d;
            if (g == 0){
                float4 o = {vv[0]*0.125f, vv[1]*0.125f, vv[2]*0.125f, vv[3]*0.125f};
                *(float4*)&g_q[dst] = o;
            } else if (g == 1){
                float4 o = {vv[0], vv[1], vv[2], vv[3]};
                *(float4*)&g_k[dst] = o;
            } else {
                float4 o = {vv[0], vv[1], vv[2], vv[3]};
                *(float4*)&g_v[dst] = o;
            }
        }
    }
}

__global__ void k_id_small(const float* __restrict__ idt, const float* __restrict__ idkA,
                           const float* __restrict__ idvA, const float* __restrict__ Widk,
                           const float* __restrict__ bidk, const float* __restrict__ idkB){
    const int row = blockIdx.x;
    const int tid = threadIdx.x;
    __shared__ float xs[Cc];
    __shared__ float lk[8], dk[12];
    for (int i = tid; i < Cc; i += NT) xs[i] = idt[row*Cc + i];
    __syncthreads();
    const int warp = tid >> 5, lane = tid & 31;
    for (int o = warp; o < 28; o += 8){
        const float* a;
        if (o < 8)       a = &idkA[o*Cc];
        else if (o < 16) a = &idvA[(o - 8)*Cc];
        else             a = &Widk[(o - 16)*Cc];
        float p = 0.f;
        for (int i = lane; i < Cc; i += 32) p += xs[i] * a[i];
        #pragma unroll
        for (int off = 16; off; off >>= 1) p += __shfl_xor_sync(0xffffffffu, p, off);
        if (lane == 0){
            if (o < 8)       lk[o] = p;
            else if (o < 16) g_idvlow[row*8 + (o - 8)] = p;
            else             dk[o - 16] = p;
        }
    }
    __syncthreads();
    if (tid < 12){
        float lo = 0.f;
        #pragma unroll
        for (int r = 0; r < 8; r++) lo += lk[r] * idkB[tid*8 + r];
        float f = dk[tid] + bidk[tid] + 0.125f * lo;
        g_act[row*Hh + tid] = 1.f + tanhf(f);
    }
}

// ---- idv GEMM: 64x64 tiles ----
__global__ void k_sgemm_idv(const float* __restrict__ idt, const float* __restrict__ W,
                            const float* __restrict__ bidv, const float* __restrict__ idvB){
    __shared__ __align__(16) float As[16*64];
    __shared__ __align__(16) float Ws[16*64];
    float acc[4][4];
    #pragma unroll
    for (int i = 0; i < 4; i++)
    #pragma unroll
    for (int j = 0; j < 4; j++) acc[i][j] = 0.f;
    const int tid = threadIdx.x;
    const int ty = tid >> 4, tx = tid & 15;
    const int lr = tid >> 2, lk = (tid & 3) * 4;
    const int row0 = blockIdx.y * 64, col0 = blockIdx.x * 64;
    for (int kt = 0; kt < Cc; kt += 16){
        float4 a4 = *(const float4*)&idt[(row0 + lr)*Cc + kt + lk];
        float4 w4 = *(const float4*)&W[(col0 + lr)*Cc + kt + lk];
        __syncthreads();
        As[(lk+0)*64 + lr] = a4.x; As[(lk+1)*64 + lr] = a4.y;
        As[(lk+2)*64 + lr] = a4.z; As[(lk+3)*64 + lr] = a4.w;
        Ws[(lk+0)*64 + lr] = w4.x; Ws[(lk+1)*64 + lr] = w4.y;
        Ws[(lk+2)*64 + lr] = w4.z; Ws[(lk+3)*64 + lr] = w4.w;
        __syncthreads();
        #pragma unroll
        for (int kk = 0; kk < 16; kk++){
            float4 ra = *(const float4*)&As[kk*64 + ty*4];
            float4 rb = *(const float4*)&Ws[kk*64 + tx*4];
            acc[0][0] += ra.x*rb.x; acc[0][1] += ra.x*rb.y;
            acc[0][2] += ra.x*rb.z; acc[0][3] += ra.x*rb.w;
            acc[1][0] += ra.y*rb.x; acc[1][1] += ra.y*rb.y;
            acc[1][2] += ra.y*rb.z; acc[1][3] += ra.y*rb.w;
            acc[2][0] += ra.z*rb.x; acc[2][1] += ra.z*rb.y;
            acc[2][2] += ra.z*rb.z; acc[2][3] += ra.z*rb.w;
            acc[3][0] += ra.w*rb.x; acc[3][1] += ra.w*rb.y;
            acc[3][2] += ra.w*rb.z; acc[3][3] += ra.w*rb.w;
        }
    }
    #pragma unroll
    for (int ii = 0; ii < 4; ii++){
        const int m = row0 + ty*4 + ii;
        float lw[8];
        #pragma unroll
        for (int r = 0; r < 8; r++) lw[r] = g_idvlow[m*8 + r];
        #pragma unroll
        for (int jj = 0; jj < 4; jj++){
            const int c = col0 + tx*4 + jj;
            const float* bv = &idvB[c*8];
            float lora = 0.f;
            #pragma unroll
            for (int r = 0; r < 8; r++) lora += lw[r] * bv[r];
            g_idv[m*Cc + c] = acc[ii][jj] + bidv[c] + 0.125f * lora;
        }
    }
}

__global__ void k_apply_id(float* __restrict__ kmid, float* __restrict__ vmid){
    const int idx = blockIdx.x * NT + threadIdx.x;
    const int d = idx & 63;
    int t = idx >> 6;
    const int m = t % NM; t /= NM;
    const int h = t % Hh; const int b = t / Hh;
    const int src = ((b*Hh + h)*Nn + m)*Dd + d;
    kmid[idx] = g_k[src] * g_act[(b*NM + m)*Hh + h];
    vmid[idx] = g_v[src] + g_idv[(b*NM + m)*Cc + h*Dd + d];
}

// ---- mem attention: 16 rows/block, 512 threads, packed-f32x2 scores ----
#define SMM_S    0
#define SMM_KT   16384
#define SMM_QS   82176
#define SMM_IDX  86272
#define SMM_CS   90368
#define SMEM_M_TOT 90496

__global__ __launch_bounds__(NTS, 2)
void k_attn_m(const float* __restrict__ kmid, const float* __restrict__ vmid){
    extern __shared__ __align__(16) char smb[];
    float* s  = (float*)(smb + SMM_S);
    float* kt = (float*)(smb + SMM_KT);
    float* qs = (float*)(smb + SMM_QS);
    unsigned short* idxall = (unsigned short*)(smb + SMM_IDX);
    int* csall = (int*)(smb + SMM_CS);
    const int tid = threadIdx.x, lane = tid & 31, w = tid >> 5;
    const int qt = blockIdx.x & 15;
    const int bh = blockIdx.x >> 4;
    const int b = bh / Hh, h = bh % Hh;
    const int m0 = qt * TQS;
    #pragma unroll
    for (int i = tid; i < TQS*Dd; i += NTS){
        int r = i >> 6, d = i & 63;
        qs[(r >> 1)*128 + (d << 1) + (r & 1)] = g_q[((size_t)bh*Nn + m0 + r)*Dd + d];
    }
    #pragma unroll
    for (int ph = 0; ph < 8; ph++){
        int idx = tid + ph*NTS;
        int r = idx >> 4, c4 = idx & 15;
        float4 kv = *(const float4*)&kmid[((size_t)bh*NM + r)*Dd + c4*4];
        kt[(c4*4+0)*KTP + r] = kv.x;
        kt[(c4*4+1)*KTP + r] = kv.y;
        kt[(c4*4+2)*KTP + r] = kv.z;
        kt[(c4*4+3)*KTP + r] = kv.w;
    }
    __syncthreads();
    {
        const int key = tid & 255, pg = (tid >> 8) * 4;
        u64t a2[4];
        #pragma unroll
        for (int p = 0; p < 4; p++) a2[p] = 0ull;
        #pragma unroll 8
        for (int d = 0; d < 64; d++){
            float kk = kt[d*KTP + key];
            u64t kd = pack2(kk, kk);
            #pragma unroll
            for (int p = 0; p < 4; p++){
                float2 qv = *(const float2*)&qs[(pg + p)*128 + (d << 1)];
                a2[p] = ffma2(kd, f2u(qv), a2[p]);
            }
        }
        #pragma unroll
        for (int p = 0; p < 4; p++){
            float2 t = u2f(a2[p]);
            ((unsigned*)s)[(pg*2 + 2*p + 0)*NM + key] = fkey(t.x);
            ((unsigned*)s)[(pg*2 + 2*p + 1)*NM + key] = fkey(t.y);
        }
    }
    __syncthreads();
    float* sp = s + w*NM;
    unsigned* spk = (unsigned*)sp;
    unsigned kmax = 0;
    #pragma unroll
    for (int g = 0; g < NM/32; g++) kmax = max(kmax, spk[g*32 + lane]);
    #pragma unroll
    for (int off = 16; off; off >>= 1) kmax = max(kmax, __shfl_xor_sync(0xffffffffu, kmax, off));
    float Z = warp_topk<NM, KSEL_M, 8>(sp, idxall + w*KSEL_M, csall + w*2, kmax, lane);
    float invZ = 1.f / Z;
    __syncthreads();
    float* vsh = kt;
    #pragma unroll
    for (int ph = 0; ph < 8; ph++){
        int idx = tid + ph*NTS;
        int r = idx >> 4, c4 = idx & 15;
        *(float4*)&vsh[r*Dd + c4*4] = *(const float4*)&vmid[((size_t)bh*NM + r)*Dd + c4*4];
    }
    __syncthreads();
    u64t acc2v = 0ull;
    const unsigned short* il = idxall + w*KSEL_M;
    #pragma unroll 4
    for (int n = 0; n < KSEL_M; n++){
        int j = il[n];
        float wgt = sp[j];
        u64t wd = pack2(wgt, wgt);
        float2 v2 = ((const float2*)&vsh[j*Dd])[lane];
        acc2v = ffma2(wd, f2u(v2), acc2v);
    }
    float2 accv = u2f(acc2v);
    float2 o = {accv.x*invZ, accv.y*invZ};
    ((float2*)&g_xo[((size_t)b*Nn + m0 + w)*Cc + h*Dd])[lane] = o;
}

// ---- streaming attention: 16 rows/block, packed-f32x2 scores, reg-prefetch ----
#define SMS_S    0
#define SMS_KT   163840
#define SMS_QS   196864
#define SMS_CS   200960
#define SMS_IDX  202496
#define SMEM_S_TOT 222976

__global__ __launch_bounds__(NTS, 1)
void k_attn_s(const float* __restrict__ memk, const float* __restrict__ memv,
              const float* __restrict__ vmid){
    extern __shared__ __align__(16) char smb[];
    float* s  = (float*)(smb + SMS_S);
    float* kt = (float*)(smb + SMS_KT);
    float* qs = (float*)(smb + SMS_QS);
    int* csall = (int*)(smb + SMS_CS);
    unsigned short* idxall = (unsigned short*)(smb + SMS_IDX);
    const int tid = threadIdx.x, lane = tid & 31, w = tid >> 5;
    const int qt = blockIdx.x & 63;
    const int bh = blockIdx.x >> 6;
    const int b = bh / Hh, h = bh % Hh;
    const int nq0 = NM + qt*TQS;
    #pragma unroll
    for (int i = tid; i < TQS*Dd; i += NTS){
        int r = i >> 6, d = i & 63;
        qs[(r >> 1)*128 + (d << 1) + (r & 1)] = g_q[((size_t)bh*Nn + nq0 + r)*Dd + d];
    }
    const int pr = tid >> 2;
    const int pco = (tid & 3) * 4;
    float4 pre[4];
    {
        const float* kr = &memk[((size_t)bh*MEMN + pr)*Dd];
        #pragma unroll
        for (int i = 0; i < 4; i++) pre[i] = ((const float4*)kr)[pco + i];
    }
    const int key = tid & 127, pb = (tid >> 7) * 2;
    for (int ck = 0; ck < NCH; ck++){
        __syncthreads();
        #pragma unroll
        for (int i = 0; i < 4; i++){
            int c = (pco + i)*4;
            kt[(c+0)*KT2 + pr] = pre[i].x; kt[(c+1)*KT2 + pr] = pre[i].y;
            kt[(c+2)*KT2 + pr] = pre[i].z; kt[(c+3)*KT2 + pr] = pre[i].w;
        }
        __syncthreads();
        if (ck + 1 < NCH){
            int j = (ck+1)*CKS + pr;
            const float* kr = (j < MEMN) ? &memk[((size_t)bh*MEMN + j)*Dd]
                                         : &g_k[((size_t)bh*Nn + (j - MEMN))*Dd];
            #pragma unroll
            for (int i = 0; i < 4; i++) pre[i] = ((const float4*)kr)[pco + i];
        }
        u64t a2A = 0ull, a2B = 0ull;
        #pragma unroll 16
        for (int d = 0; d < 64; d++){
            float kk = kt[d*KT2 + key];
            u64t kd = pack2(kk, kk);
            float2 qA = *(const float2*)&qs[pb*128 + (d << 1)];
            float2 qB = *(const float2*)&qs[(pb + 1)*128 + (d << 1)];
            a2A = ffma2(kd, f2u(qA), a2A);
            a2B = ffma2(kd, f2u(qB), a2B);
        }
        float2 r01 = u2f(a2A), r23 = u2f(a2B);
        unsigned* su = (unsigned*)s;
        su[(pb*2+0)*LFULL + ck*CKS + key] = fkey(r01.x);
        su[(pb*2+1)*LFULL + ck*CKS + key] = fkey(r01.y);
        su[(pb*2+2)*LFULL + ck*CKS + key] = fkey(r23.x);
        su[(pb*2+3)*LFULL + ck*CKS + key] = fkey(r23.y);
    }
    __syncthreads();
    float* sp = s + w*LFULL;
    unsigned* spk = (unsigned*)sp;
    int* cs = csall + w*24;
    unsigned short* il = idxall + w*KSEL_S;
    unsigned kmax = 0;
    for (int g = 0; g < LFULL/32; g++) kmax = max(kmax, spk[g*32 + lane]);
    #pragma unroll
    for (int off = 16; off; off >>= 1) kmax = max(kmax, __shfl_xor_sync(0xffffffffu, kmax, off));
    float Z = warp_topk<LFULL, KSEL_S, 4>(sp, il, cs, kmax, lane);
    float invZ = 1.f / Z;
    float* vsh = kt;
    {
        const float* vr = &memv[((size_t)bh*MEMN + pr)*Dd];
        #pragma unroll
        for (int i = 0; i < 4; i++) pre[i] = ((const float4*)vr)[pco + i];
    }
    const int hl = lane >> 4, ll = lane & 15;
    u64t accA = 0ull, accB = 0ull;
    for (int ck = 0; ck < NCH; ck++){
        __syncthreads();
        #pragma unroll
        for (int i = 0; i < 4; i++)
            *(float4*)&vsh[pr*Dd + (pco + i)*4] = pre[i];
        __syncthreads();
        if (ck + 1 < NCH){
            int j = (ck+1)*CKS + pr;
            const float* vr;
            if (j < MEMN)            vr = &memv[((size_t)bh*MEMN + j)*Dd];
            else if (j < MEMN + NM)  vr = &vmid[((size_t)bh*NM + (j - MEMN))*Dd];
            else                     vr = &g_v[((size_t)bh*Nn + (j - MEMN))*Dd];
            #pragma unroll
            for (int i = 0; i < 4; i++) pre[i] = ((const float4*)vr)[pco + i];
        }
        const int nb = cs[ck], ne = cs[ck+1], jb = ck*CKS;
        for (int n = nb; n < ne; n += 2){
            int j0 = il[n];
            int j1 = (n + 1 < ne) ? il[n+1] : j0;
            int jj = hl ? j1 : j0;
            float wgt = sp[jj];
            if (hl && (n + 1 >= ne)) wgt = 0.f;
            u64t wd = pack2(wgt, wgt);
            const float* vb = &vsh[(jj - jb)*Dd + ll*4];
            float2 vA = *(const float2*)vb;
            float2 vB = *(const float2*)(vb + 2);
            accA = ffma2(wd, f2u(vA), accA);
            accB = ffma2(wd, f2u(vB), accB);
        }
    }
    float2 aA = u2f(accA), aB = u2f(accB);
    float4 acc4 = {aA.x, aA.y, aB.x, aB.y};
    acc4.x += __shfl_xor_sync(0xffffffffu, acc4.x, 16);
    acc4.y += __shfl_xor_sync(0xffffffffu, acc4.y, 16);
    acc4.z += __shfl_xor_sync(0xffffffffu, acc4.z, 16);
    acc4.w += __shfl_xor_sync(0xffffffffu, acc4.w, 16);
    if (lane < 16){
        float4 o = {acc4.x*invZ, acc4.y*invZ, acc4.z*invZ, acc4.w*invZ};
        *(float4*)&g_xo[((size_t)b*Nn + nq0 + w)*Cc + h*Dd + ll*4] = o;
    }
}

// ---- route softmax + proj lows, 8 rows per block ----
__global__ void k_route(const float* __restrict__ routeW, const float* __restrict__ projA){
    __shared__ float xs[8*Cc];
    __shared__ float lg[8][4], pl[8][32], sm[8][4];
    const int tid = threadIdx.x;
    const int m0 = blockIdx.x * 8;
    for (int i = tid; i < 8*Cc; i += NT) xs[i] = g_xo[(size_t)m0*Cc + i];
    __syncthreads();
    const int warp = tid >> 5, lane = tid & 31;
    for (int o = warp; o < 36; o += 8){
        const float* a = (o < 4) ? &routeW[o*Cc] : &projA[(o - 4)*Cc];
        float acc[8];
        #pragma unroll
        for (int r = 0; r < 8; r++) acc[r] = 0.f;
        for (int i = lane; i < Cc; i += 32){
            float av = a[i];
            #pragma unroll
            for (int r = 0; r < 8; r++) acc[r] += xs[r*Cc + i] * av;
        }
        #pragma unroll
        for (int r = 0; r < 8; r++){
            float p = acc[r];
            #pragma unroll
            for (int off = 16; off; off >>= 1) p += __shfl_xor_sync(0xffffffffu, p, off);
            if (lane == 0){
                if (o < 4) lg[r][o] = p;
                else       pl[r][o - 4] = p;
            }
        }
    }
    __syncthreads();
    if (tid < 8){
        int r = tid;
        float mx = fmaxf(fmaxf(lg[r][0], lg[r][1]), fmaxf(lg[r][2], lg[r][3]));
        float e0 = __expf(lg[r][0]-mx), e1 = __expf(lg[r][1]-mx);
        float e2 = __expf(lg[r][2]-mx), e3 = __expf(lg[r][3]-mx);
        float si = 1.f / (e0 + e1 + e2 + e3);
        sm[r][0] = e0*si; sm[r][1] = e1*si; sm[r][2] = e2*si; sm[r][3] = e3*si;
    }
    __syncthreads();
    {
        int r = tid >> 5, t = tid & 31;
        g_wplow[(m0 + r)*32 + t] = sm[r][t >> 3] * pl[r][t] * 0.125f;
    }
}

// ---- output projection GEMM: MoE lora folded as 32 extra K-steps (K = 800) ----
__global__ __launch_bounds__(NT, 2)
void k_sgemm_proj(const float* __restrict__ W, const float* __restrict__ bp,
                  const float* __restrict__ projB, float* __restrict__ out){
    SG128_PREAMBLE
    auto LOADA = [&](int kt)->float4{
        if (kt < Cc) return *(const float4*)&g_xo[(size_t)(row0 + lr)*Cc + kt + lc];
        return *(const float4*)&g_wplow[(row0 + lr)*32 + (kt - Cc) + lc];
    };
    auto LOADW = [&](int kt)->float4{
        if (kt < Cc) return *(const float4*)&W[(size_t)(col0 + lr)*Cc + kt + lc];
        int k2 = kt - Cc + lc;
        int e = k2 >> 3, r = k2 & 7;
        return *(const float4*)&projB[((size_t)e*Cc + (col0 + lr))*8 + r];
    };
    SG128_LOOP(Cc + 32)
    #pragma unroll
    for (int ii = 0; ii < 8; ii++){
        const int m = row0 + ty*4 + (ii & 3) + (ii >> 2)*64;
        #pragma unroll
        for (int jh = 0; jh < 2; jh++){
            float vv[4];
            #pragma unroll
            for (int q = 0; q < 4; q++){
                const int c = col0 + jh*64 + tx*4 + q;
                vv[q] = acc[ii][jh*4 + q] + bp[c];
            }
            const int c0 = col0 + jh*64 + tx*4;
            float4 o = {vv[0], vv[1], vv[2], vv[3]};
            *(float4*)&out[(size_t)m*Cc + c0] = o;
        }
    }
}

extern "C" void kernel_launch(void* const* d_in, const int* in_sizes, int n_in,
                              void* d_out, int out_size){
    const float* x      = (const float*)d_in[0];
    const float* idt    = (const float*)d_in[1];
    const float* memk   = (const float*)d_in[2];
    const float* memv   = (const float*)d_in[3];
    const float* Wqkv   = (const float*)d_in[4];
    const float* bqkv   = (const float*)d_in[5];
    const float* qkvA   = (const float*)d_in[6];
    const float* qkvB   = (const float*)d_in[7];
    const float* Wproj  = (const float*)d_in[8];
    const float* bproj  = (const float*)d_in[9];
    const float* routeW = (const float*)d_in[10];
    const float* projA  = (const float*)d_in[11];
    const float* projB  = (const float*)d_in[12];
    const float* Widk   = (const float*)d_in[13];
    const float* bidk   = (const float*)d_in[14];
    const float* idkA   = (const float*)d_in[15];
    const float* idkB   = (const float*)d_in[16];
    const float* Widv   = (const float*)d_in[17];
    const float* bidv   = (const float*)d_in[18];
    const float* idvA   = (const float*)d_in[19];
    const float* idvB   = (const float*)d_in[20];

    float* out  = (float*)d_out;
    float* kmid = out + Bb*Nn*Cc;
    float* vmid = kmid + Bb*Hh*NM*Dd;

    static int init = 0;
    static cudaStream_t s2;
    static cudaEvent_t evF, evA, evB, evC;
    if (!init){
        cudaFuncSetAttribute(k_attn_m, cudaFuncAttributeMaxDynamicSharedMemorySize, SMEM_M_TOT);
        cudaFuncSetAttribute(k_attn_s, cudaFuncAttributeMaxDynamicSharedMemorySize, SMEM_S_TOT);
        cudaStreamCreateWithFlags(&s2, cudaStreamNonBlocking);
        cudaEventCreateWithFlags(&evF, cudaEventDisableTiming);
        cudaEventCreateWithFlags(&evA, cudaEventDisableTiming);
        cudaEventCreateWithFlags(&evB, cudaEventDisableTiming);
        cudaEventCreateWithFlags(&evC, cudaEventDisableTiming);
        init = 1;
    }

    // fork: s2 handles the id-chain concurrently with the qkv-chain
    cudaEventRecord(evF, 0);
    cudaStreamWaitEvent(s2, evF, 0);

    k_id_small<<<Bb*NM, NT, 0, s2>>>(idt, idkA, idvA, Widk, bidk, idkB);
    k_sgemm_idv<<<dim3(12, 16), NT, 0, s2>>>(idt, Widv, bidv, idvB);
    cudaEventRecord(evA, s2);

    k_qkv_low<<<Bb*Nn/8, NT>>>(x, qkvA);
    k_sgemm_qkv<<<dim3(18, 40), NT>>>(x, Wqkv, bqkv, qkvB);

    // join id-chain into stream 0 before apply_id
    cudaStreamWaitEvent(0, evA, 0);
    k_apply_id<<<(Bb*Hh*NM*Dd)/NT, NT>>>(kmid, vmid);
    cudaEventRecord(evB, 0);

    // attn_m on s2 concurrently with attn_s on stream 0
    cudaStreamWaitEvent(s2, evB, 0);
    k_attn_m<<<Bb*Hh*NM/TQS, NTS, SMEM_M_TOT, s2>>>(kmid, vmid);
    cudaEventRecord(evC, s2);

    k_attn_s<<<Bb*Hh*NSd/TQS, NTS, SMEM_S_TOT>>>(memk, memv, vmid);

    // join attn_m before route/proj
    cudaStreamWaitEvent(0, evC, 0);
    k_route<<<Bb*Nn/8, NT>>>(routeW, projA);
    k_sgemm_proj<<<dim3(6, 40), NT>>>(Wproj, bproj, projB, out);
}